// round 9
// baseline (speedup 1.0000x reference)
#include <cuda_runtime.h>
#include <cuda_fp16.h>
#include <math.h>
#include <stdint.h>

// ---------------- problem constants ----------------
#define BATCH 16
#define HDIM  56
#define WDIM  56
#define CH    512
#define CFF   2048
#define NHEAD 16
#define DH    32
#define MWIN  7
#define NTOKW 49
#define SHIFT 3
#define NTOK  (BATCH*HDIM*WDIM)                  // 50176
#define NWIN  (BATCH*(HDIM/MWIN)*(WDIM/MWIN))    // 1024

// ---------------- device scratch (allocation-free) ----------------
__device__ half  g_xw  [(size_t)NTOK*CH];
__device__ half  g_qkv [(size_t)NTOK*3*CH];
__device__ half  g_att [(size_t)NTOK*CH];
__device__ half  g_proj[(size_t)NTOK*CH];
__device__ float g_x2  [(size_t)NTOK*CH];
__device__ half  g_h2  [(size_t)NTOK*CH];
__device__ half  g_ffn [(size_t)NTOK*CFF];
// weights transposed to [N,K] fp16
__device__ half g_wqkv [(size_t)CH*3*CH];
__device__ half g_wproj[(size_t)CH*CH];
__device__ half g_w1   [(size_t)CH*CFF];
__device__ half g_w2   [(size_t)CFF*CH];

// ---------------- PTX helpers ----------------
__device__ __forceinline__ uint32_t smem_u32(const void* p){
    uint32_t a;
    asm("{ .reg .u64 t; cvta.to.shared.u64 t, %1; cvt.u32.u64 %0, t; }" : "=r"(a) : "l"(p));
    return a;
}
#define CP_ASYNC16(dst, src) \
    asm volatile("cp.async.cg.shared.global [%0], [%1], 16;" :: "r"(dst), "l"(src))
#define CP_COMMIT() asm volatile("cp.async.commit_group;" ::: "memory")
#define CP_WAIT(N)  asm volatile("cp.async.wait_group %0;" :: "n"(N) : "memory")

#define LDSM_X4(r, a) \
    asm volatile("ldmatrix.sync.aligned.m8n8.x4.shared.b16 {%0,%1,%2,%3}, [%4];" \
        : "=r"((r)[0]), "=r"((r)[1]), "=r"((r)[2]), "=r"((r)[3]) : "r"(a))

#define MMA_F16(d, a, b0, b1) \
    asm volatile("mma.sync.aligned.m16n8k16.row.col.f32.f16.f16.f32 " \
        "{%0,%1,%2,%3}, {%4,%5,%6,%7}, {%8,%9}, {%0,%1,%2,%3};" \
        : "+f"((d)[0]), "+f"((d)[1]), "+f"((d)[2]), "+f"((d)[3]) \
        : "r"((a)[0]), "r"((a)[1]), "r"((a)[2]), "r"((a)[3]), "r"(b0), "r"(b1))

// ---------------- fp16 HMMA GEMM: 128x256 CTA tile, 4-stage cp.async ----------------
// C[M,N] = A @ B^T + bias ; A: [M,K] fp16, B: [N,K] fp16, fp32 accumulate.
// 512 threads = 16 warps (2 x 8), warp tile 64x32. BK=32.
// smem rows padded to 80B -> conflict-free ldmatrix (bank-quad (5r+c)%8 is a
// permutation over 8 rows). Stage = A 128x80 + B 256x80 = 30KB; 4 stages.
// EPI=0: fp32 out. EPI=1: GELU -> fp16. EPI=2: +res -> fp32. EPI=3: fp16.
#define ATILE  10240
#define BTILE  20480
#define STAGEB 30720
#define GSMEM  (4*STAGEB)

template<int EPI>
__global__ __launch_bounds__(512, 1) void hmma_gemm(
    const half* __restrict__ Ag, const half* __restrict__ Bg,
    const float* __restrict__ bias, const float* __restrict__ res,
    float* __restrict__ Cf, half* __restrict__ Ch,
    int K, int Nc)
{
    extern __shared__ char smem[];
    const int tid = threadIdx.x;
    const int lane = tid & 31, wid = tid >> 5;
    const int wm = wid & 1, wn = wid >> 1;          // 2 x 8 warps, tile 64 x 32

    const half* Ab = Ag + (size_t)blockIdx.y * 128 * K;
    const half* Bb = Bg + (size_t)blockIdx.x * 256 * K;

    const uint32_t sb = smem_u32(smem);
    const int NK = K >> 5;

    float acc[4][4][4];
    #pragma unroll
    for (int a = 0; a < 4; a++)
        #pragma unroll
        for (int b = 0; b < 4; b++)
            #pragma unroll
            for (int c = 0; c < 4; c++) acc[a][b][c] = 0.f;

    const int lr = tid >> 2;           // 0..127
    const int lc = tid & 3;            // 16B chunk 0..3
    auto load_stage = [&](int kb, int s) {
        uint32_t st = sb + (uint32_t)s * STAGEB;
        // A: 128 rows, 1 chunk per thread
        CP_ASYNC16(st + (uint32_t)(lr * 80 + lc * 16),
                   Ab + (size_t)lr * K + kb * 32 + lc * 8);
        // B: 256 rows, 2 chunks per thread
        #pragma unroll
        for (int i = 0; i < 2; i++) {
            int r = i * 128 + lr;
            CP_ASYNC16(st + (uint32_t)(ATILE + r * 80 + lc * 16),
                       Bb + (size_t)r * K + kb * 32 + lc * 8);
        }
        CP_COMMIT();
    };

    auto compute_stage = [&](int s) {
        uint32_t st = sb + (uint32_t)s * STAGEB;
        #pragma unroll
        for (int kk = 0; kk < 2; kk++) {
            const int ch = kk * 2 + (lane >> 4);
            uint32_t bh[2][4];
            #pragma unroll
            for (int np = 0; np < 2; np++) {
                int row = wn * 32 + np * 16 + (lane & 15);
                uint32_t off = (uint32_t)(ATILE + row * 80 + ch * 16);
                LDSM_X4(bh[np], st + off);
            }
            #pragma unroll
            for (int mt = 0; mt < 4; mt++) {
                int row = wm * 64 + mt * 16 + (lane & 15);
                uint32_t off = (uint32_t)(row * 80 + ch * 16);
                uint32_t ah[4];
                LDSM_X4(ah, st + off);
                #pragma unroll
                for (int nt = 0; nt < 4; nt++) {
                    int np = nt >> 1, se = nt & 1;
                    MMA_F16(acc[mt][nt], ah, bh[np][se], bh[np][se + 2]);
                }
            }
        }
    };

    // prologue: fill 3 stages
    load_stage(0, 0);
    if (NK > 1) load_stage(1, 1);
    if (NK > 2) load_stage(2, 2);

    for (int kb = 0; kb < NK; kb++) {
        if (kb + 3 <= NK) { CP_WAIT(2); }
        else if (kb + 2 == NK) { CP_WAIT(1); }
        else { CP_WAIT(0); }
        __syncthreads();
        if (kb + 3 < NK) load_stage(kb + 3, (kb + 3) & 3);
        compute_stage(kb & 3);
    }

    // --- epilogue: registers -> gmem ---
    int row0 = blockIdx.y * 128 + wm * 64;
    int col0 = blockIdx.x * 256 + wn * 32;
    #pragma unroll
    for (int mt = 0; mt < 4; mt++) {
        #pragma unroll
        for (int nt = 0; nt < 4; nt++) {
            int c = col0 + nt * 8 + (lane & 3) * 2;
            float b0 = bias[c], b1 = bias[c + 1];
            #pragma unroll
            for (int h = 0; h < 2; h++) {
                int r = row0 + mt * 16 + (lane >> 2) + h * 8;
                float v0 = acc[mt][nt][h * 2]     + b0;
                float v1 = acc[mt][nt][h * 2 + 1] + b1;
                size_t o = (size_t)r * Nc + c;
                if (EPI == 1) {
                    v0 = 0.5f * v0 * (1.0f + erff(v0 * 0.70710678118654752f));
                    v1 = 0.5f * v1 * (1.0f + erff(v1 * 0.70710678118654752f));
                    *(half2*)(Ch + o) = __floats2half2_rn(v0, v1);
                } else if (EPI == 3) {
                    *(half2*)(Ch + o) = __floats2half2_rn(v0, v1);
                } else {
                    if (EPI == 2) {
                        float2 rv = *(const float2*)(res + o);
                        v0 += rv.x; v1 += rv.y;
                    }
                    *(float2*)(Cf + o) = make_float2(v0, v1);
                }
            }
        }
    }
}

// ---------------- weight prep: [K,N] fp32 -> [N,K] fp16 (tiled transpose) ----------------
__global__ __launch_bounds__(256) void prep_w(
    const float* __restrict__ W, half* __restrict__ Wh, int K, int N)
{
    __shared__ float tile[32][33];
    int nb = blockIdx.x * 32, kb = blockIdx.y * 32;
    int tx = threadIdx.x & 31, ty = threadIdx.x >> 5;  // 32 x 8
    #pragma unroll
    for (int j = 0; j < 32; j += 8)
        tile[ty + j][tx] = W[(size_t)(kb + ty + j) * N + nb + tx];
    __syncthreads();
    #pragma unroll
    for (int j = 0; j < 32; j += 8)
        Wh[(size_t)(nb + ty + j) * K + kb + tx] = __float2half_rn(tile[tx][ty + j]);
}

// ---------------- block reduction (256 threads) ----------------
__device__ __forceinline__ void block_reduce_2(float& s, float& sq) {
    __shared__ float sh[16];
    int lane = threadIdx.x & 31, wid = threadIdx.x >> 5;
    #pragma unroll
    for (int o = 16; o > 0; o >>= 1) {
        s  += __shfl_down_sync(0xffffffffu, s,  o);
        sq += __shfl_down_sync(0xffffffffu, sq, o);
    }
    if (lane == 0) { sh[wid] = s; sh[wid + 8] = sq; }
    __syncthreads();
    if (threadIdx.x == 0) {
        float S = 0.f, SQ = 0.f;
        #pragma unroll
        for (int i = 0; i < 8; i++) { S += sh[i]; SQ += sh[i + 8]; }
        sh[0] = S; sh[8] = SQ;
    }
    __syncthreads();
    s = sh[0]; sq = sh[8];
}

// ---------------- LN1 + shift + window partition -> fp16 ----------------
__global__ __launch_bounds__(256) void ln1_window_kernel(
    const float* __restrict__ x, const float* __restrict__ g, const float* __restrict__ b,
    half* __restrict__ out)
{
    int t = blockIdx.x;
    int w = t / NTOKW, tok = t - w * NTOKW;
    int bb = w >> 6, wrem = w & 63;
    int wi = wrem >> 3, wj = wrem & 7;
    int ti = tok / MWIN, tj = tok - ti * MWIN;
    int r = (wi * MWIN + ti + SHIFT) % HDIM;
    int c = (wj * MWIN + tj + SHIFT) % WDIM;
    const float* src = x + ((size_t)bb * (HDIM * WDIM) + r * WDIM + c) * CH;
    int tid = threadIdx.x;
    float v0 = src[tid], v1 = src[tid + 256];
    float s = v0 + v1, sq = v0 * v0 + v1 * v1;
    block_reduce_2(s, sq);
    float mu  = s * (1.0f / CH);
    float var = sq * (1.0f / CH) - mu * mu;
    float inv = rsqrtf(var + 1e-5f);
    size_t base = (size_t)t * CH;
    out[base + tid]       = __float2half_rn((v0 - mu) * inv * g[tid]       + b[tid]);
    out[base + tid + 256] = __float2half_rn((v1 - mu) * inv * g[tid + 256] + b[tid + 256]);
}

// ---------------- windowed attention: register-tiled ----------------
__global__ __launch_bounds__(128) void attn_kernel(
    const half* __restrict__ qkv, const float* __restrict__ bias_table,
    half* __restrict__ out)
{
    int win  = blockIdx.x >> 4;
    int head = blockIdx.x & 15;
    __shared__ float q[52 * 33], kk[52 * 33], v[52 * 33];
    __shared__ float sc[52 * 57];
    int tid = threadIdx.x;
    const float scale = 0.17677669529663687f;
    size_t base = (size_t)win * NTOKW * (3 * CH) + head * DH;

    for (int i = tid; i < NTOKW * 16; i += 128) {
        int n = i >> 4, d2 = (i & 15) * 2;
        size_t rb = base + (size_t)n * (3 * CH) + d2;
        float2 fq = __half22float2(*(const half2*)(qkv + rb));
        float2 fk = __half22float2(*(const half2*)(qkv + rb + CH));
        float2 fv = __half22float2(*(const half2*)(qkv + rb + 2 * CH));
        q [n * 33 + d2] = fq.x;  q [n * 33 + d2 + 1] = fq.y;
        kk[n * 33 + d2] = fk.x;  kk[n * 33 + d2 + 1] = fk.y;
        v [n * 33 + d2] = fv.x;  v [n * 33 + d2 + 1] = fv.y;
    }
    __syncthreads();

    if (tid < 91) {
        int tr = tid / 7, tc = tid - tr * 7;
        int n0 = tr * 4, m0 = tc * 7;
        float acc[4][7];
        #pragma unroll
        for (int i = 0; i < 4; i++)
            #pragma unroll
            for (int j = 0; j < 7; j++) acc[i][j] = 0.f;
        #pragma unroll 8
        for (int d = 0; d < DH; d++) {
            float qr[4], kr[7];
            #pragma unroll
            for (int i = 0; i < 4; i++) qr[i] = q[(n0 + i) * 33 + d];
            #pragma unroll
            for (int j = 0; j < 7; j++) kr[j] = kk[(m0 + j) * 33 + d];
            #pragma unroll
            for (int i = 0; i < 4; i++)
                #pragma unroll
                for (int j = 0; j < 7; j++)
                    acc[i][j] = fmaf(qr[i], kr[j], acc[i][j]);
        }
        #pragma unroll
        for (int i = 0; i < 4; i++) {
            int n = n0 + i;
            int nn = n < NTOKW ? n : NTOKW - 1;
            int nr = nn / MWIN, ncm = nn - nr * MWIN;
            #pragma unroll
            for (int j = 0; j < 7; j++) {
                int m = m0 + j;
                int mr = m / MWIN, mc = m - mr * MWIN;
                int dr = nr - mr + (MWIN - 1), dc = ncm - mc + (MWIN - 1);
                sc[n * 57 + m] = acc[i][j] * scale
                               + bias_table[(dr * (2 * MWIN - 1) + dc) * NHEAD + head];
            }
        }
    }
    __syncthreads();

    if (tid < NTOKW) {
        float* row = sc + tid * 57;
        float mx = -1e30f;
        #pragma unroll 7
        for (int m = 0; m < NTOKW; m++) mx = fmaxf(mx, row[m]);
        float sum = 0.f;
        #pragma unroll 7
        for (int m = 0; m < NTOKW; m++) { float e = __expf(row[m] - mx); row[m] = e; sum += e; }
        float inv = 1.0f / sum;
        #pragma unroll 7
        for (int m = 0; m < NTOKW; m++) row[m] *= inv;
    }
    __syncthreads();

    if (tid < 104) {
        int tr = tid >> 3, dc = tid & 7;
        int n0 = tr * 4, d0 = dc * 4;
        float acc[4][4];
        #pragma unroll
        for (int i = 0; i < 4; i++)
            #pragma unroll
            for (int k = 0; k < 4; k++) acc[i][k] = 0.f;
        #pragma unroll 7
        for (int m = 0; m < NTOKW; m++) {
            float vv[4], pp[4];
            #pragma unroll
            for (int k = 0; k < 4; k++) vv[k] = v[m * 33 + d0 + k];
            #pragma unroll
            for (int i = 0; i < 4; i++) pp[i] = sc[(n0 + i) * 57 + m];
            #pragma unroll
            for (int i = 0; i < 4; i++)
                #pragma unroll
                for (int k = 0; k < 4; k++)
                    acc[i][k] = fmaf(pp[i], vv[k], acc[i][k]);
        }
        #pragma unroll
        for (int i = 0; i < 4; i++) {
            int n = n0 + i;
            if (n < NTOKW) {
                size_t o = ((size_t)win * NTOKW + n) * CH + head * DH + d0;
                *(half2*)(out + o)     = __floats2half2_rn(acc[i][0], acc[i][1]);
                *(half2*)(out + o + 2) = __floats2half2_rn(acc[i][2], acc[i][3]);
            }
        }
    }
}

// ---------------- window reverse + roll + residual + LN2 (proj fp16) ----------------
__global__ __launch_bounds__(256) void res_ln2_kernel(
    const float* __restrict__ x, const half* __restrict__ proj,
    const float* __restrict__ g, const float* __restrict__ b,
    float* __restrict__ x2, half* __restrict__ h2)
{
    int t = blockIdx.x;
    int bb = t / (HDIM * WDIM);
    int rc = t - bb * (HDIM * WDIM);
    int r = rc / WDIM, c = rc - r * WDIM;
    int rs = (r - SHIFT + HDIM) % HDIM;
    int cs = (c - SHIFT + WDIM) % WDIM;
    int w   = bb * 64 + (rs / MWIN) * 8 + (cs / MWIN);
    int tok = (rs % MWIN) * MWIN + (cs % MWIN);
    const half* ps = proj + ((size_t)w * NTOKW + tok) * CH;
    const float* xs = x + (size_t)t * CH;
    int tid = threadIdx.x;
    float v0 = xs[tid] + __half2float(ps[tid]);
    float v1 = xs[tid + 256] + __half2float(ps[tid + 256]);
    float* x2p = x2 + (size_t)t * CH;
    x2p[tid] = v0; x2p[tid + 256] = v1;
    float s = v0 + v1, sq = v0 * v0 + v1 * v1;
    block_reduce_2(s, sq);
    float mu  = s * (1.0f / CH);
    float var = sq * (1.0f / CH) - mu * mu;
    float inv = rsqrtf(var + 1e-5f);
    size_t base = (size_t)t * CH;
    h2[base + tid]       = __float2half_rn((v0 - mu) * inv * g[tid]       + b[tid]);
    h2[base + tid + 256] = __float2half_rn((v1 - mu) * inv * g[tid + 256] + b[tid + 256]);
}

// ---------------- launcher ----------------
extern "C" void kernel_launch(void* const* d_in, const int* in_sizes, int n_in,
                              void* d_out, int out_size)
{
    const float* x          = (const float*)d_in[0];
    const float* w_qkv      = (const float*)d_in[3];
    const float* b_qkv      = (const float*)d_in[4];
    const float* w_proj     = (const float*)d_in[5];
    const float* b_proj     = (const float*)d_in[6];
    const float* bias_table = (const float*)d_in[7];
    const float* g1         = (const float*)d_in[8];
    const float* be1        = (const float*)d_in[9];
    const float* g2         = (const float*)d_in[10];
    const float* be2        = (const float*)d_in[11];
    const float* w1         = (const float*)d_in[12];
    const float* b1         = (const float*)d_in[13];
    const float* w2         = (const float*)d_in[14];
    const float* b2         = (const float*)d_in[15];
    float* out = (float*)d_out;

    half *p_xw, *p_qkv, *p_att, *p_proj, *p_h2, *p_ffn;
    float *p_x2;
    half *p_wqkv, *p_wproj, *p_w1, *p_w2;
    cudaGetSymbolAddress((void**)&p_xw,   g_xw);
    cudaGetSymbolAddress((void**)&p_qkv,  g_qkv);
    cudaGetSymbolAddress((void**)&p_att,  g_att);
    cudaGetSymbolAddress((void**)&p_proj, g_proj);
    cudaGetSymbolAddress((void**)&p_x2,   g_x2);
    cudaGetSymbolAddress((void**)&p_h2,   g_h2);
    cudaGetSymbolAddress((void**)&p_ffn,  g_ffn);
    cudaGetSymbolAddress((void**)&p_wqkv,  g_wqkv);
    cudaGetSymbolAddress((void**)&p_wproj, g_wproj);
    cudaGetSymbolAddress((void**)&p_w1,    g_w1);
    cudaGetSymbolAddress((void**)&p_w2,    g_w2);

    cudaFuncSetAttribute(hmma_gemm<0>, cudaFuncAttributeMaxDynamicSharedMemorySize, GSMEM);
    cudaFuncSetAttribute(hmma_gemm<1>, cudaFuncAttributeMaxDynamicSharedMemorySize, GSMEM);
    cudaFuncSetAttribute(hmma_gemm<2>, cudaFuncAttributeMaxDynamicSharedMemorySize, GSMEM);
    cudaFuncSetAttribute(hmma_gemm<3>, cudaFuncAttributeMaxDynamicSharedMemorySize, GSMEM);

    // weight prep (tiled transpose to fp16)
    prep_w<<<dim3((3*CH)/32, CH/32), 256>>>(w_qkv, p_wqkv, CH, 3*CH);
    prep_w<<<dim3(CH/32,     CH/32), 256>>>(w_proj, p_wproj, CH, CH);
    prep_w<<<dim3(CFF/32,    CH/32), 256>>>(w1, p_w1, CH, CFF);
    prep_w<<<dim3(CH/32,    CFF/32), 256>>>(w2, p_w2, CFF, CH);

    // 1. LN1 + shift + window partition -> fp16
    ln1_window_kernel<<<NTOK, 256>>>(x, g1, be1, p_xw);

    // 2. QKV GEMM -> fp16 (bias only)
    hmma_gemm<3><<<dim3((3*CH)/256, NTOK/128), 512, GSMEM>>>(
        p_xw, p_wqkv, b_qkv, nullptr, nullptr, p_qkv, CH, 3*CH);

    // 3. windowed attention -> fp16
    attn_kernel<<<NWIN * NHEAD, 128>>>(p_qkv, bias_table, p_att);

    // 4. proj GEMM -> fp16
    hmma_gemm<3><<<dim3(CH/256, NTOK/128), 512, GSMEM>>>(
        p_att, p_wproj, b_proj, nullptr, nullptr, p_proj, CH, CH);

    // 5. window reverse + roll + residual + LN2
    res_ln2_kernel<<<NTOK, 256>>>(x, p_proj, g2, be2, p_x2, p_h2);

    // 6. FFN1 + GELU -> fp16
    hmma_gemm<1><<<dim3(CFF/256, NTOK/128), 512, GSMEM>>>(
        p_h2, p_w1, b1, nullptr, nullptr, p_ffn, CH, CFF);

    // 7. FFN2 + residual -> out
    hmma_gemm<2><<<dim3(CH/256, NTOK/128), 512, GSMEM>>>(
        p_ffn, p_w2, b2, p_x2, out, nullptr, CFF, CH);
}

// round 10
// speedup vs baseline: 1.0580x; 1.0580x over previous
#include <cuda_runtime.h>
#include <cuda_fp16.h>
#include <math.h>
#include <stdint.h>

// ---------------- problem constants ----------------
#define BATCH 16
#define HDIM  56
#define WDIM  56
#define CH    512
#define CFF   2048
#define NHEAD 16
#define DH    32
#define MWIN  7
#define NTOKW 49
#define SHIFT 3
#define NTOK  (BATCH*HDIM*WDIM)                  // 50176
#define NWIN  (BATCH*(HDIM/MWIN)*(WDIM/MWIN))    // 1024

// ---------------- device scratch (allocation-free) ----------------
__device__ half  g_xw  [(size_t)NTOK*CH];
__device__ half  g_qkv [(size_t)NTOK*3*CH];
__device__ half  g_att [(size_t)NTOK*CH];
__device__ half  g_proj[(size_t)NTOK*CH];
__device__ float g_x2  [(size_t)NTOK*CH];
__device__ half  g_h2  [(size_t)NTOK*CH];
__device__ half  g_ffn [(size_t)NTOK*CFF];
// weights transposed to [N,K] fp16
__device__ half g_wqkv [(size_t)CH*3*CH];
__device__ half g_wproj[(size_t)CH*CH];
__device__ half g_w1   [(size_t)CH*CFF];
__device__ half g_w2   [(size_t)CFF*CH];

// ---------------- PTX helpers ----------------
__device__ __forceinline__ uint32_t smem_u32(const void* p){
    uint32_t a;
    asm("{ .reg .u64 t; cvta.to.shared.u64 t, %1; cvt.u32.u64 %0, t; }" : "=r"(a) : "l"(p));
    return a;
}
#define CP_ASYNC16(dst, src) \
    asm volatile("cp.async.cg.shared.global [%0], [%1], 16;" :: "r"(dst), "l"(src))
#define CP_COMMIT() asm volatile("cp.async.commit_group;" ::: "memory")
#define CP_WAIT(N)  asm volatile("cp.async.wait_group %0;" :: "n"(N) : "memory")

#define LDSM_X4(r, a) \
    asm volatile("ldmatrix.sync.aligned.m8n8.x4.shared.b16 {%0,%1,%2,%3}, [%4];" \
        : "=r"((r)[0]), "=r"((r)[1]), "=r"((r)[2]), "=r"((r)[3]) : "r"(a))

#define MMA_F16(d, a, b0, b1) \
    asm volatile("mma.sync.aligned.m16n8k16.row.col.f32.f16.f16.f32 " \
        "{%0,%1,%2,%3}, {%4,%5,%6,%7}, {%8,%9}, {%0,%1,%2,%3};" \
        : "+f"((d)[0]), "+f"((d)[1]), "+f"((d)[2]), "+f"((d)[3]) \
        : "r"((a)[0]), "r"((a)[1]), "r"((a)[2]), "r"((a)[3]), "r"(b0), "r"(b1))

// ---------------- fp16 HMMA GEMM, 4-stage cp.async pipeline ----------------
// C[M,N] = A @ B^T + bias ; A: [M,K] fp16, B: [N,K] fp16, fp32 accumulate.
// CTA tile 128x128, BK=32, 256 threads, rows padded to 80B (conflict-free
// ldmatrix: bank-quad (5r+c)%8 is a permutation over 8 rows).
// Stage = 20KB; 4 stages = 80KB -> 2 CTAs/SM (barrier overlap between CTAs).
// EPI=0: fp32 out. EPI=1: GELU -> fp16. EPI=2: +res -> fp32. EPI=3: fp16.
#define TILEB  10240
#define STAGEB 20480
#define GSMEM  (4*STAGEB)

template<int EPI>
__global__ __launch_bounds__(256, 2) void hmma_gemm(
    const half* __restrict__ Ag, const half* __restrict__ Bg,
    const float* __restrict__ bias, const float* __restrict__ res,
    float* __restrict__ Cf, half* __restrict__ Ch,
    int K, int Nc)
{
    extern __shared__ char smem[];
    const int tid = threadIdx.x;
    const int lane = tid & 31, wid = tid >> 5;
    const int wm = wid & 1, wn = wid >> 1;          // warp tile: 64 x 32

    const half* Ab = Ag + (size_t)blockIdx.y * 128 * K;
    const half* Bb = Bg + (size_t)blockIdx.x * 128 * K;

    const uint32_t sb = smem_u32(smem);
    const int NK = K >> 5;

    float acc[4][4][4];
    #pragma unroll
    for (int a = 0; a < 4; a++)
        #pragma unroll
        for (int b = 0; b < 4; b++)
            #pragma unroll
            for (int c = 0; c < 4; c++) acc[a][b][c] = 0.f;

    const int lr0 = tid >> 2;          // 0..63
    const int lc  = tid & 3;           // 16B chunk 0..3
    auto load_stage = [&](int kb, int s) {
        uint32_t st = sb + (uint32_t)s * STAGEB;
        #pragma unroll
        for (int i = 0; i < 4; i++) {
            const int t = i >> 1;
            int r = (i & 1) * 64 + lr0;
            const half* src = (t ? Bb : Ab) + (size_t)r * K + kb * 32 + lc * 8;
            uint32_t dst = st + (uint32_t)(t * TILEB + r * 80 + lc * 16);
            CP_ASYNC16(dst, src);
        }
        CP_COMMIT();
    };

    auto compute_stage = [&](int s) {
        uint32_t st = sb + (uint32_t)s * STAGEB;
        #pragma unroll
        for (int kk = 0; kk < 2; kk++) {
            const int ch = kk * 2 + (lane >> 4);
            uint32_t bh[2][4];
            #pragma unroll
            for (int np = 0; np < 2; np++) {
                int row = wn * 32 + np * 16 + (lane & 15);
                uint32_t off = (uint32_t)(row * 80 + ch * 16);
                LDSM_X4(bh[np], st + 1u * TILEB + off);
            }
            #pragma unroll
            for (int mt = 0; mt < 4; mt++) {
                int row = wm * 64 + mt * 16 + (lane & 15);
                uint32_t off = (uint32_t)(row * 80 + ch * 16);
                uint32_t ah[4];
                LDSM_X4(ah, st + off);
                #pragma unroll
                for (int nt = 0; nt < 4; nt++) {
                    int np = nt >> 1, se = nt & 1;
                    MMA_F16(acc[mt][nt], ah, bh[np][se], bh[np][se + 2]);
                }
            }
        }
    };

    // prologue: fill 3 stages
    load_stage(0, 0);
    if (NK > 1) load_stage(1, 1);
    if (NK > 2) load_stage(2, 2);

    for (int kb = 0; kb < NK; kb++) {
        if (kb + 3 <= NK) { CP_WAIT(2); }
        else if (kb + 2 == NK) { CP_WAIT(1); }
        else { CP_WAIT(0); }
        __syncthreads();
        if (kb + 3 < NK) load_stage(kb + 3, (kb + 3) & 3);
        compute_stage(kb & 3);
    }

    // --- epilogue: registers -> gmem ---
    int row0 = blockIdx.y * 128 + wm * 64;
    int col0 = blockIdx.x * 128 + wn * 32;
    #pragma unroll
    for (int mt = 0; mt < 4; mt++) {
        #pragma unroll
        for (int nt = 0; nt < 4; nt++) {
            int c = col0 + nt * 8 + (lane & 3) * 2;
            float b0 = bias[c], b1 = bias[c + 1];
            #pragma unroll
            for (int h = 0; h < 2; h++) {
                int r = row0 + mt * 16 + (lane >> 2) + h * 8;
                float v0 = acc[mt][nt][h * 2]     + b0;
                float v1 = acc[mt][nt][h * 2 + 1] + b1;
                size_t o = (size_t)r * Nc + c;
                if (EPI == 1) {
                    v0 = 0.5f * v0 * (1.0f + erff(v0 * 0.70710678118654752f));
                    v1 = 0.5f * v1 * (1.0f + erff(v1 * 0.70710678118654752f));
                    *(half2*)(Ch + o) = __floats2half2_rn(v0, v1);
                } else if (EPI == 3) {
                    *(half2*)(Ch + o) = __floats2half2_rn(v0, v1);
                } else {
                    if (EPI == 2) {
                        float2 rv = *(const float2*)(res + o);
                        v0 += rv.x; v1 += rv.y;
                    }
                    *(float2*)(Cf + o) = make_float2(v0, v1);
                }
            }
        }
    }
}

// ---------------- weight prep: [K,N] fp32 -> [N,K] fp16 (tiled transpose) ----------------
__global__ __launch_bounds__(256) void prep_w(
    const float* __restrict__ W, half* __restrict__ Wh, int K, int N)
{
    __shared__ float tile[32][33];
    int nb = blockIdx.x * 32, kb = blockIdx.y * 32;
    int tx = threadIdx.x & 31, ty = threadIdx.x >> 5;  // 32 x 8
    #pragma unroll
    for (int j = 0; j < 32; j += 8)
        tile[ty + j][tx] = W[(size_t)(kb + ty + j) * N + nb + tx];
    __syncthreads();
    #pragma unroll
    for (int j = 0; j < 32; j += 8)
        Wh[(size_t)(nb + ty + j) * K + kb + tx] = __float2half_rn(tile[tx][ty + j]);
}

// ---------------- block reduction (256 threads) ----------------
__device__ __forceinline__ void block_reduce_2(float& s, float& sq) {
    __shared__ float sh[16];
    int lane = threadIdx.x & 31, wid = threadIdx.x >> 5;
    #pragma unroll
    for (int o = 16; o > 0; o >>= 1) {
        s  += __shfl_down_sync(0xffffffffu, s,  o);
        sq += __shfl_down_sync(0xffffffffu, sq, o);
    }
    if (lane == 0) { sh[wid] = s; sh[wid + 8] = sq; }
    __syncthreads();
    if (threadIdx.x == 0) {
        float S = 0.f, SQ = 0.f;
        #pragma unroll
        for (int i = 0; i < 8; i++) { S += sh[i]; SQ += sh[i + 8]; }
        sh[0] = S; sh[8] = SQ;
    }
    __syncthreads();
    s = sh[0]; sq = sh[8];
}

// ---------------- LN1 + shift + window partition -> fp16 ----------------
__global__ __launch_bounds__(256) void ln1_window_kernel(
    const float* __restrict__ x, const float* __restrict__ g, const float* __restrict__ b,
    half* __restrict__ out)
{
    int t = blockIdx.x;
    int w = t / NTOKW, tok = t - w * NTOKW;
    int bb = w >> 6, wrem = w & 63;
    int wi = wrem >> 3, wj = wrem & 7;
    int ti = tok / MWIN, tj = tok - ti * MWIN;
    int r = (wi * MWIN + ti + SHIFT) % HDIM;
    int c = (wj * MWIN + tj + SHIFT) % WDIM;
    const float* src = x + ((size_t)bb * (HDIM * WDIM) + r * WDIM + c) * CH;
    int tid = threadIdx.x;
    float v0 = src[tid], v1 = src[tid + 256];
    float s = v0 + v1, sq = v0 * v0 + v1 * v1;
    block_reduce_2(s, sq);
    float mu  = s * (1.0f / CH);
    float var = sq * (1.0f / CH) - mu * mu;
    float inv = rsqrtf(var + 1e-5f);
    size_t base = (size_t)t * CH;
    out[base + tid]       = __float2half_rn((v0 - mu) * inv * g[tid]       + b[tid]);
    out[base + tid + 256] = __float2half_rn((v1 - mu) * inv * g[tid + 256] + b[tid + 256]);
}

// ---------------- windowed attention: register-tiled ----------------
__global__ __launch_bounds__(128) void attn_kernel(
    const half* __restrict__ qkv, const float* __restrict__ bias_table,
    half* __restrict__ out)
{
    int win  = blockIdx.x >> 4;
    int head = blockIdx.x & 15;
    __shared__ float q[52 * 33], kk[52 * 33], v[52 * 33];
    __shared__ float sc[52 * 57];
    int tid = threadIdx.x;
    const float scale = 0.17677669529663687f;
    size_t base = (size_t)win * NTOKW * (3 * CH) + head * DH;

    for (int i = tid; i < NTOKW * 16; i += 128) {
        int n = i >> 4, d2 = (i & 15) * 2;
        size_t rb = base + (size_t)n * (3 * CH) + d2;
        float2 fq = __half22float2(*(const half2*)(qkv + rb));
        float2 fk = __half22float2(*(const half2*)(qkv + rb + CH));
        float2 fv = __half22float2(*(const half2*)(qkv + rb + 2 * CH));
        q [n * 33 + d2] = fq.x;  q [n * 33 + d2 + 1] = fq.y;
        kk[n * 33 + d2] = fk.x;  kk[n * 33 + d2 + 1] = fk.y;
        v [n * 33 + d2] = fv.x;  v [n * 33 + d2 + 1] = fv.y;
    }
    __syncthreads();

    if (tid < 91) {
        int tr = tid / 7, tc = tid - tr * 7;
        int n0 = tr * 4, m0 = tc * 7;
        float acc[4][7];
        #pragma unroll
        for (int i = 0; i < 4; i++)
            #pragma unroll
            for (int j = 0; j < 7; j++) acc[i][j] = 0.f;
        #pragma unroll 8
        for (int d = 0; d < DH; d++) {
            float qr[4], kr[7];
            #pragma unroll
            for (int i = 0; i < 4; i++) qr[i] = q[(n0 + i) * 33 + d];
            #pragma unroll
            for (int j = 0; j < 7; j++) kr[j] = kk[(m0 + j) * 33 + d];
            #pragma unroll
            for (int i = 0; i < 4; i++)
                #pragma unroll
                for (int j = 0; j < 7; j++)
                    acc[i][j] = fmaf(qr[i], kr[j], acc[i][j]);
        }
        #pragma unroll
        for (int i = 0; i < 4; i++) {
            int n = n0 + i;
            int nn = n < NTOKW ? n : NTOKW - 1;
            int nr = nn / MWIN, ncm = nn - nr * MWIN;
            #pragma unroll
            for (int j = 0; j < 7; j++) {
                int m = m0 + j;
                int mr = m / MWIN, mc = m - mr * MWIN;
                int dr = nr - mr + (MWIN - 1), dc = ncm - mc + (MWIN - 1);
                sc[n * 57 + m] = acc[i][j] * scale
                               + bias_table[(dr * (2 * MWIN - 1) + dc) * NHEAD + head];
            }
        }
    }
    __syncthreads();

    if (tid < NTOKW) {
        float* row = sc + tid * 57;
        float mx = -1e30f;
        #pragma unroll 7
        for (int m = 0; m < NTOKW; m++) mx = fmaxf(mx, row[m]);
        float sum = 0.f;
        #pragma unroll 7
        for (int m = 0; m < NTOKW; m++) { float e = __expf(row[m] - mx); row[m] = e; sum += e; }
        float inv = 1.0f / sum;
        #pragma unroll 7
        for (int m = 0; m < NTOKW; m++) row[m] *= inv;
    }
    __syncthreads();

    if (tid < 104) {
        int tr = tid >> 3, dc = tid & 7;
        int n0 = tr * 4, d0 = dc * 4;
        float acc[4][4];
        #pragma unroll
        for (int i = 0; i < 4; i++)
            #pragma unroll
            for (int k = 0; k < 4; k++) acc[i][k] = 0.f;
        #pragma unroll 7
        for (int m = 0; m < NTOKW; m++) {
            float vv[4], pp[4];
            #pragma unroll
            for (int k = 0; k < 4; k++) vv[k] = v[m * 33 + d0 + k];
            #pragma unroll
            for (int i = 0; i < 4; i++) pp[i] = sc[(n0 + i) * 57 + m];
            #pragma unroll
            for (int i = 0; i < 4; i++)
                #pragma unroll
                for (int k = 0; k < 4; k++)
                    acc[i][k] = fmaf(pp[i], vv[k], acc[i][k]);
        }
        #pragma unroll
        for (int i = 0; i < 4; i++) {
            int n = n0 + i;
            if (n < NTOKW) {
                size_t o = ((size_t)win * NTOKW + n) * CH + head * DH + d0;
                *(half2*)(out + o)     = __floats2half2_rn(acc[i][0], acc[i][1]);
                *(half2*)(out + o + 2) = __floats2half2_rn(acc[i][2], acc[i][3]);
            }
        }
    }
}

// ---------------- window reverse + roll + residual + LN2 (proj fp16) ----------------
__global__ __launch_bounds__(256) void res_ln2_kernel(
    const float* __restrict__ x, const half* __restrict__ proj,
    const float* __restrict__ g, const float* __restrict__ b,
    float* __restrict__ x2, half* __restrict__ h2)
{
    int t = blockIdx.x;
    int bb = t / (HDIM * WDIM);
    int rc = t - bb * (HDIM * WDIM);
    int r = rc / WDIM, c = rc - r * WDIM;
    int rs = (r - SHIFT + HDIM) % HDIM;
    int cs = (c - SHIFT + WDIM) % WDIM;
    int w   = bb * 64 + (rs / MWIN) * 8 + (cs / MWIN);
    int tok = (rs % MWIN) * MWIN + (cs % MWIN);
    const half* ps = proj + ((size_t)w * NTOKW + tok) * CH;
    const float* xs = x + (size_t)t * CH;
    int tid = threadIdx.x;
    float v0 = xs[tid] + __half2float(ps[tid]);
    float v1 = xs[tid + 256] + __half2float(ps[tid + 256]);
    float* x2p = x2 + (size_t)t * CH;
    x2p[tid] = v0; x2p[tid + 256] = v1;
    float s = v0 + v1, sq = v0 * v0 + v1 * v1;
    block_reduce_2(s, sq);
    float mu  = s * (1.0f / CH);
    float var = sq * (1.0f / CH) - mu * mu;
    float inv = rsqrtf(var + 1e-5f);
    size_t base = (size_t)t * CH;
    h2[base + tid]       = __float2half_rn((v0 - mu) * inv * g[tid]       + b[tid]);
    h2[base + tid + 256] = __float2half_rn((v1 - mu) * inv * g[tid + 256] + b[tid + 256]);
}

// ---------------- launcher ----------------
extern "C" void kernel_launch(void* const* d_in, const int* in_sizes, int n_in,
                              void* d_out, int out_size)
{
    const float* x          = (const float*)d_in[0];
    const float* w_qkv      = (const float*)d_in[3];
    const float* b_qkv      = (const float*)d_in[4];
    const float* w_proj     = (const float*)d_in[5];
    const float* b_proj     = (const float*)d_in[6];
    const float* bias_table = (const float*)d_in[7];
    const float* g1         = (const float*)d_in[8];
    const float* be1        = (const float*)d_in[9];
    const float* g2         = (const float*)d_in[10];
    const float* be2        = (const float*)d_in[11];
    const float* w1         = (const float*)d_in[12];
    const float* b1         = (const float*)d_in[13];
    const float* w2         = (const float*)d_in[14];
    const float* b2         = (const float*)d_in[15];
    float* out = (float*)d_out;

    half *p_xw, *p_qkv, *p_att, *p_proj, *p_h2, *p_ffn;
    float *p_x2;
    half *p_wqkv, *p_wproj, *p_w1, *p_w2;
    cudaGetSymbolAddress((void**)&p_xw,   g_xw);
    cudaGetSymbolAddress((void**)&p_qkv,  g_qkv);
    cudaGetSymbolAddress((void**)&p_att,  g_att);
    cudaGetSymbolAddress((void**)&p_proj, g_proj);
    cudaGetSymbolAddress((void**)&p_x2,   g_x2);
    cudaGetSymbolAddress((void**)&p_h2,   g_h2);
    cudaGetSymbolAddress((void**)&p_ffn,  g_ffn);
    cudaGetSymbolAddress((void**)&p_wqkv,  g_wqkv);
    cudaGetSymbolAddress((void**)&p_wproj, g_wproj);
    cudaGetSymbolAddress((void**)&p_w1,    g_w1);
    cudaGetSymbolAddress((void**)&p_w2,    g_w2);

    cudaFuncSetAttribute(hmma_gemm<0>, cudaFuncAttributeMaxDynamicSharedMemorySize, GSMEM);
    cudaFuncSetAttribute(hmma_gemm<1>, cudaFuncAttributeMaxDynamicSharedMemorySize, GSMEM);
    cudaFuncSetAttribute(hmma_gemm<2>, cudaFuncAttributeMaxDynamicSharedMemorySize, GSMEM);
    cudaFuncSetAttribute(hmma_gemm<3>, cudaFuncAttributeMaxDynamicSharedMemorySize, GSMEM);

    // weight prep (tiled transpose to fp16)
    prep_w<<<dim3((3*CH)/32, CH/32), 256>>>(w_qkv, p_wqkv, CH, 3*CH);
    prep_w<<<dim3(CH/32,     CH/32), 256>>>(w_proj, p_wproj, CH, CH);
    prep_w<<<dim3(CFF/32,    CH/32), 256>>>(w1, p_w1, CH, CFF);
    prep_w<<<dim3(CH/32,    CFF/32), 256>>>(w2, p_w2, CFF, CH);

    // 1. LN1 + shift + window partition -> fp16
    ln1_window_kernel<<<NTOK, 256>>>(x, g1, be1, p_xw);

    // 2. QKV GEMM -> fp16 (bias only)
    hmma_gemm<3><<<dim3((3*CH)/128, NTOK/128), 256, GSMEM>>>(
        p_xw, p_wqkv, b_qkv, nullptr, nullptr, p_qkv, CH, 3*CH);

    // 3. windowed attention -> fp16
    attn_kernel<<<NWIN * NHEAD, 128>>>(p_qkv, bias_table, p_att);

    // 4. proj GEMM -> fp16
    hmma_gemm<3><<<dim3(CH/128, NTOK/128), 256, GSMEM>>>(
        p_att, p_wproj, b_proj, nullptr, nullptr, p_proj, CH, CH);

    // 5. window reverse + roll + residual + LN2
    res_ln2_kernel<<<NTOK, 256>>>(x, p_proj, g2, be2, p_x2, p_h2);

    // 6. FFN1 + GELU -> fp16
    hmma_gemm<1><<<dim3(CFF/128, NTOK/128), 256, GSMEM>>>(
        p_h2, p_w1, b1, nullptr, nullptr, p_ffn, CH, CFF);

    // 7. FFN2 + residual -> out
    hmma_gemm<2><<<dim3(CH/128, NTOK/128), 256, GSMEM>>>(
        p_ffn, p_w2, b2, p_x2, out, nullptr, CFF, CH);
}

// round 11
// speedup vs baseline: 1.0927x; 1.0328x over previous
#include <cuda_runtime.h>
#include <cuda_fp16.h>
#include <math.h>
#include <stdint.h>

// ---------------- problem constants ----------------
#define BATCH 16
#define HDIM  56
#define WDIM  56
#define CH    512
#define CFF   2048
#define NHEAD 16
#define DH    32
#define MWIN  7
#define NTOKW 49
#define SHIFT 3
#define NTOK  (BATCH*HDIM*WDIM)                  // 50176
#define NWIN  (BATCH*(HDIM/MWIN)*(WDIM/MWIN))    // 1024

// ---------------- device scratch (allocation-free) ----------------
__device__ half  g_xw  [(size_t)NTOK*CH];
__device__ half  g_qkv [(size_t)NTOK*3*CH];
__device__ half  g_att [(size_t)NTOK*CH];
__device__ half  g_proj[(size_t)NTOK*CH];
__device__ float g_x2  [(size_t)NTOK*CH];
__device__ half  g_h2  [(size_t)NTOK*CH];
__device__ half  g_ffn [(size_t)NTOK*CFF];
// weights transposed to [N,K] fp16
__device__ half g_wqkv [(size_t)CH*3*CH];
__device__ half g_wproj[(size_t)CH*CH];
__device__ half g_w1   [(size_t)CH*CFF];
__device__ half g_w2   [(size_t)CFF*CH];

// ---------------- PTX helpers ----------------
__device__ __forceinline__ uint32_t smem_u32(const void* p){
    uint32_t a;
    asm("{ .reg .u64 t; cvta.to.shared.u64 t, %1; cvt.u32.u64 %0, t; }" : "=r"(a) : "l"(p));
    return a;
}
#define CP_ASYNC16(dst, src) \
    asm volatile("cp.async.cg.shared.global [%0], [%1], 16;" :: "r"(dst), "l"(src))
#define CP_COMMIT() asm volatile("cp.async.commit_group;" ::: "memory")
#define CP_WAIT(N)  asm volatile("cp.async.wait_group %0;" :: "n"(N) : "memory")

#define LDSM_X4(r, a) \
    asm volatile("ldmatrix.sync.aligned.m8n8.x4.shared.b16 {%0,%1,%2,%3}, [%4];" \
        : "=r"((r)[0]), "=r"((r)[1]), "=r"((r)[2]), "=r"((r)[3]) : "r"(a))

#define MMA_F16(d, a, b0, b1) \
    asm volatile("mma.sync.aligned.m16n8k16.row.col.f32.f16.f16.f32 " \
        "{%0,%1,%2,%3}, {%4,%5,%6,%7}, {%8,%9}, {%0,%1,%2,%3};" \
        : "+f"((d)[0]), "+f"((d)[1]), "+f"((d)[2]), "+f"((d)[3]) \
        : "r"((a)[0]), "r"((a)[1]), "r"((a)[2]), "r"((a)[3]), "r"(b0), "r"(b1))

// fast GELU: tanh form with HW tanh.approx (MUFU) — ~6 instr vs ~20 for erff
__device__ __forceinline__ float gelu_fast(float x){
    float u = 0.7978845608028654f * fmaf(0.044715f * x, x * x, x);
    float t;
    asm("tanh.approx.f32 %0, %1;" : "=f"(t) : "f"(u));
    return 0.5f * x * (1.0f + t);
}

// ---------------- fp16 HMMA GEMM, 4-stage cp.async pipeline ----------------
// C[M,N] = A @ B^T + bias ; A: [M,K] fp16, B: [N,K] fp16, fp32 accumulate.
// CTA tile 128x128, BK=32, 256 threads, rows padded to 80B (conflict-free
// ldmatrix: bank-quad (5r+c)%8 is a permutation over 8 rows).
// Stage = 20KB; 4 stages = 80KB -> 2 CTAs/SM (barrier overlap between CTAs).
// EPI=0: fp32 out. EPI=1: GELU -> fp16. EPI=2: +res -> fp32. EPI=3: fp16.
#define TILEB  10240
#define STAGEB 20480
#define GSMEM  (4*STAGEB)

template<int EPI>
__global__ __launch_bounds__(256, 2) void hmma_gemm(
    const half* __restrict__ Ag, const half* __restrict__ Bg,
    const float* __restrict__ bias, const float* __restrict__ res,
    float* __restrict__ Cf, half* __restrict__ Ch,
    int K, int Nc)
{
    extern __shared__ char smem[];
    const int tid = threadIdx.x;
    const int lane = tid & 31, wid = tid >> 5;
    const int wm = wid & 1, wn = wid >> 1;          // warp tile: 64 x 32

    const half* Ab = Ag + (size_t)blockIdx.y * 128 * K;
    const half* Bb = Bg + (size_t)blockIdx.x * 128 * K;

    const uint32_t sb = smem_u32(smem);
    const int NK = K >> 5;

    float acc[4][4][4];
    #pragma unroll
    for (int a = 0; a < 4; a++)
        #pragma unroll
        for (int b = 0; b < 4; b++)
            #pragma unroll
            for (int c = 0; c < 4; c++) acc[a][b][c] = 0.f;

    const int lr0 = tid >> 2;          // 0..63
    const int lc  = tid & 3;           // 16B chunk 0..3
    auto load_stage = [&](int kb, int s) {
        uint32_t st = sb + (uint32_t)s * STAGEB;
        #pragma unroll
        for (int i = 0; i < 4; i++) {
            const int t = i >> 1;
            int r = (i & 1) * 64 + lr0;
            const half* src = (t ? Bb : Ab) + (size_t)r * K + kb * 32 + lc * 8;
            uint32_t dst = st + (uint32_t)(t * TILEB + r * 80 + lc * 16);
            CP_ASYNC16(dst, src);
        }
        CP_COMMIT();
    };

    auto compute_stage = [&](int s) {
        uint32_t st = sb + (uint32_t)s * STAGEB;
        #pragma unroll
        for (int kk = 0; kk < 2; kk++) {
            const int ch = kk * 2 + (lane >> 4);
            uint32_t bh[2][4];
            #pragma unroll
            for (int np = 0; np < 2; np++) {
                int row = wn * 32 + np * 16 + (lane & 15);
                uint32_t off = (uint32_t)(row * 80 + ch * 16);
                LDSM_X4(bh[np], st + 1u * TILEB + off);
            }
            #pragma unroll
            for (int mt = 0; mt < 4; mt++) {
                int row = wm * 64 + mt * 16 + (lane & 15);
                uint32_t off = (uint32_t)(row * 80 + ch * 16);
                uint32_t ah[4];
                LDSM_X4(ah, st + off);
                #pragma unroll
                for (int nt = 0; nt < 4; nt++) {
                    int np = nt >> 1, se = nt & 1;
                    MMA_F16(acc[mt][nt], ah, bh[np][se], bh[np][se + 2]);
                }
            }
        }
    };

    // prologue: fill 3 stages
    load_stage(0, 0);
    if (NK > 1) load_stage(1, 1);
    if (NK > 2) load_stage(2, 2);

    for (int kb = 0; kb < NK; kb++) {
        if (kb + 3 <= NK) { CP_WAIT(2); }
        else if (kb + 2 == NK) { CP_WAIT(1); }
        else { CP_WAIT(0); }
        __syncthreads();
        if (kb + 3 < NK) load_stage(kb + 3, (kb + 3) & 3);
        compute_stage(kb & 3);
    }

    // --- epilogue: registers -> gmem ---
    int row0 = blockIdx.y * 128 + wm * 64;
    int col0 = blockIdx.x * 128 + wn * 32;
    #pragma unroll
    for (int mt = 0; mt < 4; mt++) {
        #pragma unroll
        for (int nt = 0; nt < 4; nt++) {
            int c = col0 + nt * 8 + (lane & 3) * 2;
            float b0 = bias[c], b1 = bias[c + 1];
            #pragma unroll
            for (int h = 0; h < 2; h++) {
                int r = row0 + mt * 16 + (lane >> 2) + h * 8;
                float v0 = acc[mt][nt][h * 2]     + b0;
                float v1 = acc[mt][nt][h * 2 + 1] + b1;
                size_t o = (size_t)r * Nc + c;
                if (EPI == 1) {
                    v0 = gelu_fast(v0);
                    v1 = gelu_fast(v1);
                    *(half2*)(Ch + o) = __floats2half2_rn(v0, v1);
                } else if (EPI == 3) {
                    *(half2*)(Ch + o) = __floats2half2_rn(v0, v1);
                } else {
                    if (EPI == 2) {
                        float2 rv = *(const float2*)(res + o);
                        v0 += rv.x; v1 += rv.y;
                    }
                    *(float2*)(Cf + o) = make_float2(v0, v1);
                }
            }
        }
    }
}

// ---------------- weight prep: [K,N] fp32 -> [N,K] fp16 (tiled transpose) ----------------
__global__ __launch_bounds__(256) void prep_w(
    const float* __restrict__ W, half* __restrict__ Wh, int K, int N)
{
    __shared__ float tile[32][33];
    int nb = blockIdx.x * 32, kb = blockIdx.y * 32;
    int tx = threadIdx.x & 31, ty = threadIdx.x >> 5;  // 32 x 8
    #pragma unroll
    for (int j = 0; j < 32; j += 8)
        tile[ty + j][tx] = W[(size_t)(kb + ty + j) * N + nb + tx];
    __syncthreads();
    #pragma unroll
    for (int j = 0; j < 32; j += 8)
        Wh[(size_t)(nb + ty + j) * K + kb + tx] = __float2half_rn(tile[tx][ty + j]);
}

// ---------------- block reduction (256 threads) ----------------
__device__ __forceinline__ void block_reduce_2(float& s, float& sq) {
    __shared__ float sh[16];
    int lane = threadIdx.x & 31, wid = threadIdx.x >> 5;
    #pragma unroll
    for (int o = 16; o > 0; o >>= 1) {
        s  += __shfl_down_sync(0xffffffffu, s,  o);
        sq += __shfl_down_sync(0xffffffffu, sq, o);
    }
    if (lane == 0) { sh[wid] = s; sh[wid + 8] = sq; }
    __syncthreads();
    if (threadIdx.x == 0) {
        float S = 0.f, SQ = 0.f;
        #pragma unroll
        for (int i = 0; i < 8; i++) { S += sh[i]; SQ += sh[i + 8]; }
        sh[0] = S; sh[8] = SQ;
    }
    __syncthreads();
    s = sh[0]; sq = sh[8];
}

// ---------------- LN1 + shift + window partition -> fp16 ----------------
__global__ __launch_bounds__(256) void ln1_window_kernel(
    const float* __restrict__ x, const float* __restrict__ g, const float* __restrict__ b,
    half* __restrict__ out)
{
    int t = blockIdx.x;
    int w = t / NTOKW, tok = t - w * NTOKW;
    int bb = w >> 6, wrem = w & 63;
    int wi = wrem >> 3, wj = wrem & 7;
    int ti = tok / MWIN, tj = tok - ti * MWIN;
    int r = (wi * MWIN + ti + SHIFT) % HDIM;
    int c = (wj * MWIN + tj + SHIFT) % WDIM;
    const float* src = x + ((size_t)bb * (HDIM * WDIM) + r * WDIM + c) * CH;
    int tid = threadIdx.x;
    float v0 = src[tid], v1 = src[tid + 256];
    float s = v0 + v1, sq = v0 * v0 + v1 * v1;
    block_reduce_2(s, sq);
    float mu  = s * (1.0f / CH);
    float var = sq * (1.0f / CH) - mu * mu;
    float inv = rsqrtf(var + 1e-5f);
    size_t base = (size_t)t * CH;
    out[base + tid]       = __float2half_rn((v0 - mu) * inv * g[tid]       + b[tid]);
    out[base + tid + 256] = __float2half_rn((v1 - mu) * inv * g[tid + 256] + b[tid + 256]);
}

// ---------------- windowed attention: register-tiled ----------------
__global__ __launch_bounds__(128) void attn_kernel(
    const half* __restrict__ qkv, const float* __restrict__ bias_table,
    half* __restrict__ out)
{
    int win  = blockIdx.x >> 4;
    int head = blockIdx.x & 15;
    __shared__ float q[52 * 33], kk[52 * 33], v[52 * 33];
    __shared__ float sc[52 * 57];
    int tid = threadIdx.x;
    const float scale = 0.17677669529663687f;
    size_t base = (size_t)win * NTOKW * (3 * CH) + head * DH;

    for (int i = tid; i < NTOKW * 16; i += 128) {
        int n = i >> 4, d2 = (i & 15) * 2;
        size_t rb = base + (size_t)n * (3 * CH) + d2;
        float2 fq = __half22float2(*(const half2*)(qkv + rb));
        float2 fk = __half22float2(*(const half2*)(qkv + rb + CH));
        float2 fv = __half22float2(*(const half2*)(qkv + rb + 2 * CH));
        q [n * 33 + d2] = fq.x;  q [n * 33 + d2 + 1] = fq.y;
        kk[n * 33 + d2] = fk.x;  kk[n * 33 + d2 + 1] = fk.y;
        v [n * 33 + d2] = fv.x;  v [n * 33 + d2 + 1] = fv.y;
    }
    __syncthreads();

    if (tid < 91) {
        int tr = tid / 7, tc = tid - tr * 7;
        int n0 = tr * 4, m0 = tc * 7;
        float acc[4][7];
        #pragma unroll
        for (int i = 0; i < 4; i++)
            #pragma unroll
            for (int j = 0; j < 7; j++) acc[i][j] = 0.f;
        #pragma unroll 8
        for (int d = 0; d < DH; d++) {
            float qr[4], kr[7];
            #pragma unroll
            for (int i = 0; i < 4; i++) qr[i] = q[(n0 + i) * 33 + d];
            #pragma unroll
            for (int j = 0; j < 7; j++) kr[j] = kk[(m0 + j) * 33 + d];
            #pragma unroll
            for (int i = 0; i < 4; i++)
                #pragma unroll
                for (int j = 0; j < 7; j++)
                    acc[i][j] = fmaf(qr[i], kr[j], acc[i][j]);
        }
        #pragma unroll
        for (int i = 0; i < 4; i++) {
            int n = n0 + i;
            int nn = n < NTOKW ? n : NTOKW - 1;
            int nr = nn / MWIN, ncm = nn - nr * MWIN;
            #pragma unroll
            for (int j = 0; j < 7; j++) {
                int m = m0 + j;
                int mr = m / MWIN, mc = m - mr * MWIN;
                int dr = nr - mr + (MWIN - 1), dc = ncm - mc + (MWIN - 1);
                sc[n * 57 + m] = acc[i][j] * scale
                               + bias_table[(dr * (2 * MWIN - 1) + dc) * NHEAD + head];
            }
        }
    }
    __syncthreads();

    if (tid < NTOKW) {
        float* row = sc + tid * 57;
        float mx = -1e30f;
        #pragma unroll 7
        for (int m = 0; m < NTOKW; m++) mx = fmaxf(mx, row[m]);
        float sum = 0.f;
        #pragma unroll 7
        for (int m = 0; m < NTOKW; m++) { float e = __expf(row[m] - mx); row[m] = e; sum += e; }
        float inv = 1.0f / sum;
        #pragma unroll 7
        for (int m = 0; m < NTOKW; m++) row[m] *= inv;
    }
    __syncthreads();

    if (tid < 104) {
        int tr = tid >> 3, dc = tid & 7;
        int n0 = tr * 4, d0 = dc * 4;
        float acc[4][4];
        #pragma unroll
        for (int i = 0; i < 4; i++)
            #pragma unroll
            for (int k = 0; k < 4; k++) acc[i][k] = 0.f;
        #pragma unroll 7
        for (int m = 0; m < NTOKW; m++) {
            float vv[4], pp[4];
            #pragma unroll
            for (int k = 0; k < 4; k++) vv[k] = v[m * 33 + d0 + k];
            #pragma unroll
            for (int i = 0; i < 4; i++) pp[i] = sc[(n0 + i) * 57 + m];
            #pragma unroll
            for (int i = 0; i < 4; i++)
                #pragma unroll
                for (int k = 0; k < 4; k++)
                    acc[i][k] = fmaf(pp[i], vv[k], acc[i][k]);
        }
        #pragma unroll
        for (int i = 0; i < 4; i++) {
            int n = n0 + i;
            if (n < NTOKW) {
                size_t o = ((size_t)win * NTOKW + n) * CH + head * DH + d0;
                *(half2*)(out + o)     = __floats2half2_rn(acc[i][0], acc[i][1]);
                *(half2*)(out + o + 2) = __floats2half2_rn(acc[i][2], acc[i][3]);
            }
        }
    }
}

// ---------------- window reverse + roll + residual + LN2 (proj fp16) ----------------
__global__ __launch_bounds__(256) void res_ln2_kernel(
    const float* __restrict__ x, const half* __restrict__ proj,
    const float* __restrict__ g, const float* __restrict__ b,
    float* __restrict__ x2, half* __restrict__ h2)
{
    int t = blockIdx.x;
    int bb = t / (HDIM * WDIM);
    int rc = t - bb * (HDIM * WDIM);
    int r = rc / WDIM, c = rc - r * WDIM;
    int rs = (r - SHIFT + HDIM) % HDIM;
    int cs = (c - SHIFT + WDIM) % WDIM;
    int w   = bb * 64 + (rs / MWIN) * 8 + (cs / MWIN);
    int tok = (rs % MWIN) * MWIN + (cs % MWIN);
    const half* ps = proj + ((size_t)w * NTOKW + tok) * CH;
    const float* xs = x + (size_t)t * CH;
    int tid = threadIdx.x;
    float v0 = xs[tid] + __half2float(ps[tid]);
    float v1 = xs[tid + 256] + __half2float(ps[tid + 256]);
    float* x2p = x2 + (size_t)t * CH;
    x2p[tid] = v0; x2p[tid + 256] = v1;
    float s = v0 + v1, sq = v0 * v0 + v1 * v1;
    block_reduce_2(s, sq);
    float mu  = s * (1.0f / CH);
    float var = sq * (1.0f / CH) - mu * mu;
    float inv = rsqrtf(var + 1e-5f);
    size_t base = (size_t)t * CH;
    h2[base + tid]       = __float2half_rn((v0 - mu) * inv * g[tid]       + b[tid]);
    h2[base + tid + 256] = __float2half_rn((v1 - mu) * inv * g[tid + 256] + b[tid + 256]);
}

// ---------------- launcher ----------------
extern "C" void kernel_launch(void* const* d_in, const int* in_sizes, int n_in,
                              void* d_out, int out_size)
{
    const float* x          = (const float*)d_in[0];
    const float* w_qkv      = (const float*)d_in[3];
    const float* b_qkv      = (const float*)d_in[4];
    const float* w_proj     = (const float*)d_in[5];
    const float* b_proj     = (const float*)d_in[6];
    const float* bias_table = (const float*)d_in[7];
    const float* g1         = (const float*)d_in[8];
    const float* be1        = (const float*)d_in[9];
    const float* g2         = (const float*)d_in[10];
    const float* be2        = (const float*)d_in[11];
    const float* w1         = (const float*)d_in[12];
    const float* b1         = (const float*)d_in[13];
    const float* w2         = (const float*)d_in[14];
    const float* b2         = (const float*)d_in[15];
    float* out = (float*)d_out;

    half *p_xw, *p_qkv, *p_att, *p_proj, *p_h2, *p_ffn;
    float *p_x2;
    half *p_wqkv, *p_wproj, *p_w1, *p_w2;
    cudaGetSymbolAddress((void**)&p_xw,   g_xw);
    cudaGetSymbolAddress((void**)&p_qkv,  g_qkv);
    cudaGetSymbolAddress((void**)&p_att,  g_att);
    cudaGetSymbolAddress((void**)&p_proj, g_proj);
    cudaGetSymbolAddress((void**)&p_x2,   g_x2);
    cudaGetSymbolAddress((void**)&p_h2,   g_h2);
    cudaGetSymbolAddress((void**)&p_ffn,  g_ffn);
    cudaGetSymbolAddress((void**)&p_wqkv,  g_wqkv);
    cudaGetSymbolAddress((void**)&p_wproj, g_wproj);
    cudaGetSymbolAddress((void**)&p_w1,    g_w1);
    cudaGetSymbolAddress((void**)&p_w2,    g_w2);

    cudaFuncSetAttribute(hmma_gemm<0>, cudaFuncAttributeMaxDynamicSharedMemorySize, GSMEM);
    cudaFuncSetAttribute(hmma_gemm<1>, cudaFuncAttributeMaxDynamicSharedMemorySize, GSMEM);
    cudaFuncSetAttribute(hmma_gemm<2>, cudaFuncAttributeMaxDynamicSharedMemorySize, GSMEM);
    cudaFuncSetAttribute(hmma_gemm<3>, cudaFuncAttributeMaxDynamicSharedMemorySize, GSMEM);

    // weight prep (tiled transpose to fp16)
    prep_w<<<dim3((3*CH)/32, CH/32), 256>>>(w_qkv, p_wqkv, CH, 3*CH);
    prep_w<<<dim3(CH/32,     CH/32), 256>>>(w_proj, p_wproj, CH, CH);
    prep_w<<<dim3(CFF/32,    CH/32), 256>>>(w1, p_w1, CH, CFF);
    prep_w<<<dim3(CH/32,    CFF/32), 256>>>(w2, p_w2, CFF, CH);

    // 1. LN1 + shift + window partition -> fp16
    ln1_window_kernel<<<NTOK, 256>>>(x, g1, be1, p_xw);

    // 2. QKV GEMM -> fp16 (bias only)
    hmma_gemm<3><<<dim3((3*CH)/128, NTOK/128), 256, GSMEM>>>(
        p_xw, p_wqkv, b_qkv, nullptr, nullptr, p_qkv, CH, 3*CH);

    // 3. windowed attention -> fp16
    attn_kernel<<<NWIN * NHEAD, 128>>>(p_qkv, bias_table, p_att);

    // 4. proj GEMM -> fp16
    hmma_gemm<3><<<dim3(CH/128, NTOK/128), 256, GSMEM>>>(
        p_att, p_wproj, b_proj, nullptr, nullptr, p_proj, CH, CH);

    // 5. window reverse + roll + residual + LN2
    res_ln2_kernel<<<NTOK, 256>>>(x, p_proj, g2, be2, p_x2, p_h2);

    // 6. FFN1 + fast GELU -> fp16
    hmma_gemm<1><<<dim3(CFF/128, NTOK/128), 256, GSMEM>>>(
        p_h2, p_w1, b1, nullptr, nullptr, p_ffn, CH, CFF);

    // 7. FFN2 + residual -> out
    hmma_gemm<2><<<dim3(CH/128, NTOK/128), 256, GSMEM>>>(
        p_ffn, p_w2, b2, p_x2, out, nullptr, CFF, CH);
}

// round 12
// speedup vs baseline: 1.1283x; 1.0326x over previous
#include <cuda_runtime.h>
#include <cuda_fp16.h>
#include <math.h>
#include <stdint.h>

// ---------------- problem constants ----------------
#define BATCH 16
#define HDIM  56
#define WDIM  56
#define CH    512
#define CFF   2048
#define NHEAD 16
#define DH    32
#define MWIN  7
#define NTOKW 49
#define SHIFT 3
#define NTOK  (BATCH*HDIM*WDIM)                  // 50176
#define NWIN  (BATCH*(HDIM/MWIN)*(WDIM/MWIN))    // 1024

// ---------------- device scratch (allocation-free) ----------------
__device__ half  g_xw  [(size_t)NTOK*CH];
__device__ half  g_qkv [(size_t)NTOK*3*CH];
__device__ half  g_att [(size_t)NTOK*CH];
__device__ half  g_proj[(size_t)NTOK*CH];
__device__ half  g_x2h [(size_t)NTOK*CH];
__device__ half  g_h2  [(size_t)NTOK*CH];
__device__ half  g_ffn [(size_t)NTOK*CFF];
// weights transposed to [N,K] fp16
__device__ half g_wqkv [(size_t)CH*3*CH];
__device__ half g_wproj[(size_t)CH*CH];
__device__ half g_w1   [(size_t)CH*CFF];
__device__ half g_w2   [(size_t)CFF*CH];

// ---------------- PTX helpers ----------------
__device__ __forceinline__ uint32_t smem_u32(const void* p){
    uint32_t a;
    asm("{ .reg .u64 t; cvta.to.shared.u64 t, %1; cvt.u32.u64 %0, t; }" : "=r"(a) : "l"(p));
    return a;
}
#define CP_ASYNC16(dst, src) \
    asm volatile("cp.async.cg.shared.global [%0], [%1], 16;" :: "r"(dst), "l"(src))
#define CP_COMMIT() asm volatile("cp.async.commit_group;" ::: "memory")
#define CP_WAIT(N)  asm volatile("cp.async.wait_group %0;" :: "n"(N) : "memory")

#define LDSM_X4(r, a) \
    asm volatile("ldmatrix.sync.aligned.m8n8.x4.shared.b16 {%0,%1,%2,%3}, [%4];" \
        : "=r"((r)[0]), "=r"((r)[1]), "=r"((r)[2]), "=r"((r)[3]) : "r"(a))

#define MMA_F16(d, a, b0, b1) \
    asm volatile("mma.sync.aligned.m16n8k16.row.col.f32.f16.f16.f32 " \
        "{%0,%1,%2,%3}, {%4,%5,%6,%7}, {%8,%9}, {%0,%1,%2,%3};" \
        : "+f"((d)[0]), "+f"((d)[1]), "+f"((d)[2]), "+f"((d)[3]) \
        : "r"((a)[0]), "r"((a)[1]), "r"((a)[2]), "r"((a)[3]), "r"(b0), "r"(b1))

// fast GELU: tanh form with HW tanh.approx (MUFU)
__device__ __forceinline__ float gelu_fast(float x){
    float u = 0.7978845608028654f * fmaf(0.044715f * x, x * x, x);
    float t;
    asm("tanh.approx.f32 %0, %1;" : "=f"(t) : "f"(u));
    return 0.5f * x * (1.0f + t);
}

// ---------------- fp16 HMMA GEMM, 4-stage cp.async pipeline ----------------
// C[M,N] = A @ B^T + bias ; A: [M,K] fp16, B: [N,K] fp16, fp32 accumulate.
// CTA tile 128x128, BK=32, 256 threads, rows padded to 80B (conflict-free
// ldmatrix: bank-quad (5r+c)%8 is a permutation over 8 rows).
// Stage = 20KB; 4 stages = 80KB -> 2 CTAs/SM (barrier overlap between CTAs).
// EPI=1: GELU -> fp16. EPI=2: +res(fp16) -> fp32. EPI=3: fp16.
#define TILEB  10240
#define STAGEB 20480
#define GSMEM  (4*STAGEB)

template<int EPI>
__global__ __launch_bounds__(256, 2) void hmma_gemm(
    const half* __restrict__ Ag, const half* __restrict__ Bg,
    const float* __restrict__ bias, const half* __restrict__ res,
    float* __restrict__ Cf, half* __restrict__ Ch,
    int K, int Nc)
{
    extern __shared__ char smem[];
    const int tid = threadIdx.x;
    const int lane = tid & 31, wid = tid >> 5;
    const int wm = wid & 1, wn = wid >> 1;          // warp tile: 64 x 32

    const half* Ab = Ag + (size_t)blockIdx.y * 128 * K;
    const half* Bb = Bg + (size_t)blockIdx.x * 128 * K;

    const uint32_t sb = smem_u32(smem);
    const int NK = K >> 5;

    float acc[4][4][4];
    #pragma unroll
    for (int a = 0; a < 4; a++)
        #pragma unroll
        for (int b = 0; b < 4; b++)
            #pragma unroll
            for (int c = 0; c < 4; c++) acc[a][b][c] = 0.f;

    const int lr0 = tid >> 2;          // 0..63
    const int lc  = tid & 3;           // 16B chunk 0..3
    auto load_stage = [&](int kb, int s) {
        uint32_t st = sb + (uint32_t)s * STAGEB;
        #pragma unroll
        for (int i = 0; i < 4; i++) {
            const int t = i >> 1;
            int r = (i & 1) * 64 + lr0;
            const half* src = (t ? Bb : Ab) + (size_t)r * K + kb * 32 + lc * 8;
            uint32_t dst = st + (uint32_t)(t * TILEB + r * 80 + lc * 16);
            CP_ASYNC16(dst, src);
        }
        CP_COMMIT();
    };

    auto compute_stage = [&](int s) {
        uint32_t st = sb + (uint32_t)s * STAGEB;
        #pragma unroll
        for (int kk = 0; kk < 2; kk++) {
            const int ch = kk * 2 + (lane >> 4);
            uint32_t bh[2][4];
            #pragma unroll
            for (int np = 0; np < 2; np++) {
                int row = wn * 32 + np * 16 + (lane & 15);
                uint32_t off = (uint32_t)(row * 80 + ch * 16);
                LDSM_X4(bh[np], st + 1u * TILEB + off);
            }
            #pragma unroll
            for (int mt = 0; mt < 4; mt++) {
                int row = wm * 64 + mt * 16 + (lane & 15);
                uint32_t off = (uint32_t)(row * 80 + ch * 16);
                uint32_t ah[4];
                LDSM_X4(ah, st + off);
                #pragma unroll
                for (int nt = 0; nt < 4; nt++) {
                    int np = nt >> 1, se = nt & 1;
                    MMA_F16(acc[mt][nt], ah, bh[np][se], bh[np][se + 2]);
                }
            }
        }
    };

    // prologue: fill 3 stages
    load_stage(0, 0);
    if (NK > 1) load_stage(1, 1);
    if (NK > 2) load_stage(2, 2);

    for (int kb = 0; kb < NK; kb++) {
        if (kb + 3 <= NK) { CP_WAIT(2); }
        else if (kb + 2 == NK) { CP_WAIT(1); }
        else { CP_WAIT(0); }
        __syncthreads();
        if (kb + 3 < NK) load_stage(kb + 3, (kb + 3) & 3);
        compute_stage(kb & 3);
    }

    // --- epilogue: registers -> gmem ---
    int row0 = blockIdx.y * 128 + wm * 64;
    int col0 = blockIdx.x * 128 + wn * 32;
    #pragma unroll
    for (int mt = 0; mt < 4; mt++) {
        #pragma unroll
        for (int nt = 0; nt < 4; nt++) {
            int c = col0 + nt * 8 + (lane & 3) * 2;
            float b0 = bias[c], b1 = bias[c + 1];
            #pragma unroll
            for (int h = 0; h < 2; h++) {
                int r = row0 + mt * 16 + (lane >> 2) + h * 8;
                float v0 = acc[mt][nt][h * 2]     + b0;
                float v1 = acc[mt][nt][h * 2 + 1] + b1;
                size_t o = (size_t)r * Nc + c;
                if (EPI == 1) {
                    v0 = gelu_fast(v0);
                    v1 = gelu_fast(v1);
                    *(half2*)(Ch + o) = __floats2half2_rn(v0, v1);
                } else if (EPI == 3) {
                    *(half2*)(Ch + o) = __floats2half2_rn(v0, v1);
                } else {
                    if (EPI == 2) {
                        float2 rv = __half22float2(*(const half2*)(res + o));
                        v0 += rv.x; v1 += rv.y;
                    }
                    *(float2*)(Cf + o) = make_float2(v0, v1);
                }
            }
        }
    }
}

// ---------------- weight prep: [K,N] fp32 -> [N,K] fp16 (tiled transpose) ----------------
__global__ __launch_bounds__(256) void prep_w(
    const float* __restrict__ W, half* __restrict__ Wh, int K, int N)
{
    __shared__ float tile[32][33];
    int nb = blockIdx.x * 32, kb = blockIdx.y * 32;
    int tx = threadIdx.x & 31, ty = threadIdx.x >> 5;  // 32 x 8
    #pragma unroll
    for (int j = 0; j < 32; j += 8)
        tile[ty + j][tx] = W[(size_t)(kb + ty + j) * N + nb + tx];
    __syncthreads();
    #pragma unroll
    for (int j = 0; j < 32; j += 8)
        Wh[(size_t)(nb + ty + j) * K + kb + tx] = __float2half_rn(tile[tx][ty + j]);
}

// ---------------- block reduction (256 threads) ----------------
__device__ __forceinline__ void block_reduce_2(float& s, float& sq) {
    __shared__ float sh[16];
    int lane = threadIdx.x & 31, wid = threadIdx.x >> 5;
    #pragma unroll
    for (int o = 16; o > 0; o >>= 1) {
        s  += __shfl_down_sync(0xffffffffu, s,  o);
        sq += __shfl_down_sync(0xffffffffu, sq, o);
    }
    if (lane == 0) { sh[wid] = s; sh[wid + 8] = sq; }
    __syncthreads();
    if (threadIdx.x == 0) {
        float S = 0.f, SQ = 0.f;
        #pragma unroll
        for (int i = 0; i < 8; i++) { S += sh[i]; SQ += sh[i + 8]; }
        sh[0] = S; sh[8] = SQ;
    }
    __syncthreads();
    s = sh[0]; sq = sh[8];
}

// ---------------- LN1 + shift + window partition -> fp16 ----------------
__global__ __launch_bounds__(256) void ln1_window_kernel(
    const float* __restrict__ x, const float* __restrict__ g, const float* __restrict__ b,
    half* __restrict__ out)
{
    int t = blockIdx.x;
    int w = t / NTOKW, tok = t - w * NTOKW;
    int bb = w >> 6, wrem = w & 63;
    int wi = wrem >> 3, wj = wrem & 7;
    int ti = tok / MWIN, tj = tok - ti * MWIN;
    int r = (wi * MWIN + ti + SHIFT) % HDIM;
    int c = (wj * MWIN + tj + SHIFT) % WDIM;
    const float* src = x + ((size_t)bb * (HDIM * WDIM) + r * WDIM + c) * CH;
    int tid = threadIdx.x;
    float v0 = src[tid], v1 = src[tid + 256];
    float s = v0 + v1, sq = v0 * v0 + v1 * v1;
    block_reduce_2(s, sq);
    float mu  = s * (1.0f / CH);
    float var = sq * (1.0f / CH) - mu * mu;
    float inv = rsqrtf(var + 1e-5f);
    size_t base = (size_t)t * CH;
    out[base + tid]       = __float2half_rn((v0 - mu) * inv * g[tid]       + b[tid]);
    out[base + tid + 256] = __float2half_rn((v1 - mu) * inv * g[tid + 256] + b[tid + 256]);
}

// ---------------- windowed attention: register-tiled, fp16 half2 smem ----------------
// One block (128 thr) per (window, head). q/k/v in half2 smem (22.5KB static
// -> 10 blocks/SM vs 7 before). Inner loops unpack one half2 per d-pair:
// halves LDS count per FMA.
__global__ __launch_bounds__(128) void attn_kernel(
    const half* __restrict__ qkv, const float* __restrict__ bias_table,
    half* __restrict__ out)
{
    int win  = blockIdx.x >> 4;
    int head = blockIdx.x & 15;
    __shared__ half2 qh[52][17], kh[52][17], vh[52][17];
    __shared__ float sc[52][57];
    int tid = threadIdx.x;
    const float scale = 0.17677669529663687f;
    size_t base = (size_t)win * NTOKW * (3 * CH) + head * DH;

    // load Q,K,V as half2 (direct copy, no conversion)
    for (int i = tid; i < NTOKW * 16; i += 128) {
        int n = i >> 4, c = i & 15;
        size_t rb = base + (size_t)n * (3 * CH) + c * 2;
        qh[n][c] = *(const half2*)(qkv + rb);
        kh[n][c] = *(const half2*)(qkv + rb + CH);
        vh[n][c] = *(const half2*)(qkv + rb + 2 * CH);
    }
    __syncthreads();

    // QK^T + bias: 13x7 grid of 4x7 tiles (91 threads)
    if (tid < 91) {
        int tr = tid / 7, tc = tid - tr * 7;
        int n0 = tr * 4, m0 = tc * 7;
        float acc[4][7];
        #pragma unroll
        for (int i = 0; i < 4; i++)
            #pragma unroll
            for (int j = 0; j < 7; j++) acc[i][j] = 0.f;
        #pragma unroll 4
        for (int dp = 0; dp < 16; dp++) {
            float2 qr[4], kr[7];
            #pragma unroll
            for (int i = 0; i < 4; i++) qr[i] = __half22float2(qh[n0 + i][dp]);
            #pragma unroll
            for (int j = 0; j < 7; j++) kr[j] = __half22float2(kh[m0 + j][dp]);
            #pragma unroll
            for (int i = 0; i < 4; i++)
                #pragma unroll
                for (int j = 0; j < 7; j++) {
                    acc[i][j] = fmaf(qr[i].x, kr[j].x, acc[i][j]);
                    acc[i][j] = fmaf(qr[i].y, kr[j].y, acc[i][j]);
                }
        }
        #pragma unroll
        for (int i = 0; i < 4; i++) {
            int n = n0 + i;
            int nn = n < NTOKW ? n : NTOKW - 1;
            int nr = nn / MWIN, ncm = nn - nr * MWIN;
            #pragma unroll
            for (int j = 0; j < 7; j++) {
                int m = m0 + j;
                int mr = m / MWIN, mc = m - mr * MWIN;
                int dr = nr - mr + (MWIN - 1), dc = ncm - mc + (MWIN - 1);
                sc[n][m] = acc[i][j] * scale
                         + bias_table[(dr * (2 * MWIN - 1) + dc) * NHEAD + head];
            }
        }
    }
    __syncthreads();

    // softmax per row
    if (tid < NTOKW) {
        float* row = sc[tid];
        float mx = -1e30f;
        #pragma unroll 7
        for (int m = 0; m < NTOKW; m++) mx = fmaxf(mx, row[m]);
        float sum = 0.f;
        #pragma unroll 7
        for (int m = 0; m < NTOKW; m++) { float e = __expf(row[m] - mx); row[m] = e; sum += e; }
        float inv = 1.0f / sum;
        #pragma unroll 7
        for (int m = 0; m < NTOKW; m++) row[m] *= inv;
    }
    __syncthreads();

    // AV: 13x8 grid of 4x4 tiles (104 threads)
    if (tid < 104) {
        int tr = tid >> 3, dc = tid & 7;
        int n0 = tr * 4, d0 = dc * 2;      // d0 in half2 units (covers 4 floats)
        float acc[4][4];
        #pragma unroll
        for (int i = 0; i < 4; i++)
            #pragma unroll
            for (int k = 0; k < 4; k++) acc[i][k] = 0.f;
        #pragma unroll 7
        for (int m = 0; m < NTOKW; m++) {
            float2 v0 = __half22float2(vh[m][d0]);
            float2 v1 = __half22float2(vh[m][d0 + 1]);
            float pp[4];
            #pragma unroll
            for (int i = 0; i < 4; i++) pp[i] = sc[n0 + i][m];
            #pragma unroll
            for (int i = 0; i < 4; i++) {
                acc[i][0] = fmaf(pp[i], v0.x, acc[i][0]);
                acc[i][1] = fmaf(pp[i], v0.y, acc[i][1]);
                acc[i][2] = fmaf(pp[i], v1.x, acc[i][2]);
                acc[i][3] = fmaf(pp[i], v1.y, acc[i][3]);
            }
        }
        #pragma unroll
        for (int i = 0; i < 4; i++) {
            int n = n0 + i;
            if (n < NTOKW) {
                size_t o = ((size_t)win * NTOKW + n) * CH + head * DH + d0 * 2;
                *(half2*)(out + o)     = __floats2half2_rn(acc[i][0], acc[i][1]);
                *(half2*)(out + o + 2) = __floats2half2_rn(acc[i][2], acc[i][3]);
            }
        }
    }
}

// ---------------- window reverse + roll + residual + LN2 (all fp16 I/O) ----------------
__global__ __launch_bounds__(256) void res_ln2_kernel(
    const float* __restrict__ x, const half* __restrict__ proj,
    const float* __restrict__ g, const float* __restrict__ b,
    half* __restrict__ x2, half* __restrict__ h2)
{
    int t = blockIdx.x;
    int bb = t / (HDIM * WDIM);
    int rc = t - bb * (HDIM * WDIM);
    int r = rc / WDIM, c = rc - r * WDIM;
    int rs = (r - SHIFT + HDIM) % HDIM;
    int cs = (c - SHIFT + WDIM) % WDIM;
    int w   = bb * 64 + (rs / MWIN) * 8 + (cs / MWIN);
    int tok = (rs % MWIN) * MWIN + (cs % MWIN);
    const half* ps = proj + ((size_t)w * NTOKW + tok) * CH;
    const float* xs = x + (size_t)t * CH;
    int tid = threadIdx.x;
    float v0 = xs[tid] + __half2float(ps[tid]);
    float v1 = xs[tid + 256] + __half2float(ps[tid + 256]);
    half* x2p = x2 + (size_t)t * CH;
    x2p[tid] = __float2half_rn(v0);
    x2p[tid + 256] = __float2half_rn(v1);
    float s = v0 + v1, sq = v0 * v0 + v1 * v1;
    block_reduce_2(s, sq);
    float mu  = s * (1.0f / CH);
    float var = sq * (1.0f / CH) - mu * mu;
    float inv = rsqrtf(var + 1e-5f);
    size_t base = (size_t)t * CH;
    h2[base + tid]       = __float2half_rn((v0 - mu) * inv * g[tid]       + b[tid]);
    h2[base + tid + 256] = __float2half_rn((v1 - mu) * inv * g[tid + 256] + b[tid + 256]);
}

// ---------------- launcher ----------------
extern "C" void kernel_launch(void* const* d_in, const int* in_sizes, int n_in,
                              void* d_out, int out_size)
{
    const float* x          = (const float*)d_in[0];
    const float* w_qkv      = (const float*)d_in[3];
    const float* b_qkv      = (const float*)d_in[4];
    const float* w_proj     = (const float*)d_in[5];
    const float* b_proj     = (const float*)d_in[6];
    const float* bias_table = (const float*)d_in[7];
    const float* g1         = (const float*)d_in[8];
    const float* be1        = (const float*)d_in[9];
    const float* g2         = (const float*)d_in[10];
    const float* be2        = (const float*)d_in[11];
    const float* w1         = (const float*)d_in[12];
    const float* b1         = (const float*)d_in[13];
    const float* w2         = (const float*)d_in[14];
    const float* b2         = (const float*)d_in[15];
    float* out = (float*)d_out;

    half *p_xw, *p_qkv, *p_att, *p_proj, *p_x2h, *p_h2, *p_ffn;
    half *p_wqkv, *p_wproj, *p_w1, *p_w2;
    cudaGetSymbolAddress((void**)&p_xw,   g_xw);
    cudaGetSymbolAddress((void**)&p_qkv,  g_qkv);
    cudaGetSymbolAddress((void**)&p_att,  g_att);
    cudaGetSymbolAddress((void**)&p_proj, g_proj);
    cudaGetSymbolAddress((void**)&p_x2h,  g_x2h);
    cudaGetSymbolAddress((void**)&p_h2,   g_h2);
    cudaGetSymbolAddress((void**)&p_ffn,  g_ffn);
    cudaGetSymbolAddress((void**)&p_wqkv,  g_wqkv);
    cudaGetSymbolAddress((void**)&p_wproj, g_wproj);
    cudaGetSymbolAddress((void**)&p_w1,    g_w1);
    cudaGetSymbolAddress((void**)&p_w2,    g_w2);

    cudaFuncSetAttribute(hmma_gemm<1>, cudaFuncAttributeMaxDynamicSharedMemorySize, GSMEM);
    cudaFuncSetAttribute(hmma_gemm<2>, cudaFuncAttributeMaxDynamicSharedMemorySize, GSMEM);
    cudaFuncSetAttribute(hmma_gemm<3>, cudaFuncAttributeMaxDynamicSharedMemorySize, GSMEM);

    // weight prep (tiled transpose to fp16)
    prep_w<<<dim3((3*CH)/32, CH/32), 256>>>(w_qkv, p_wqkv, CH, 3*CH);
    prep_w<<<dim3(CH/32,     CH/32), 256>>>(w_proj, p_wproj, CH, CH);
    prep_w<<<dim3(CFF/32,    CH/32), 256>>>(w1, p_w1, CH, CFF);
    prep_w<<<dim3(CH/32,    CFF/32), 256>>>(w2, p_w2, CFF, CH);

    // 1. LN1 + shift + window partition -> fp16
    ln1_window_kernel<<<NTOK, 256>>>(x, g1, be1, p_xw);

    // 2. QKV GEMM -> fp16 (bias only)
    hmma_gemm<3><<<dim3((3*CH)/128, NTOK/128), 256, GSMEM>>>(
        p_xw, p_wqkv, b_qkv, nullptr, nullptr, p_qkv, CH, 3*CH);

    // 3. windowed attention -> fp16
    attn_kernel<<<NWIN * NHEAD, 128>>>(p_qkv, bias_table, p_att);

    // 4. proj GEMM -> fp16
    hmma_gemm<3><<<dim3(CH/128, NTOK/128), 256, GSMEM>>>(
        p_att, p_wproj, b_proj, nullptr, nullptr, p_proj, CH, CH);

    // 5. window reverse + roll + residual + LN2 (x2 stored fp16)
    res_ln2_kernel<<<NTOK, 256>>>(x, p_proj, g2, be2, p_x2h, p_h2);

    // 6. FFN1 + fast GELU -> fp16
    hmma_gemm<1><<<dim3(CFF/128, NTOK/128), 256, GSMEM>>>(
        p_h2, p_w1, b1, nullptr, nullptr, p_ffn, CH, CFF);

    // 7. FFN2 + residual(fp16) -> fp32 out
    hmma_gemm<2><<<dim3(CH/128, NTOK/128), 256, GSMEM>>>(
        p_ffn, p_w2, b2, p_x2h, out, nullptr, CFF, CH);
}

// round 13
// speedup vs baseline: 1.1535x; 1.0223x over previous
#include <cuda_runtime.h>
#include <cuda_fp16.h>
#include <math.h>
#include <stdint.h>

// ---------------- problem constants ----------------
#define BATCH 16
#define HDIM  56
#define WDIM  56
#define CH    512
#define CFF   2048
#define NHEAD 16
#define DH    32
#define MWIN  7
#define NTOKW 49
#define SHIFT 3
#define NTOK  (BATCH*HDIM*WDIM)                  // 50176
#define NWIN  (BATCH*(HDIM/MWIN)*(WDIM/MWIN))    // 1024

// ---------------- device scratch (allocation-free) ----------------
__device__ half  g_xw  [(size_t)NTOK*CH];
__device__ half  g_qkv [(size_t)NTOK*3*CH];
__device__ half  g_att [(size_t)NTOK*CH];
__device__ half  g_proj[(size_t)NTOK*CH];
__device__ half  g_x2h [(size_t)NTOK*CH];
__device__ half  g_h2  [(size_t)NTOK*CH];
__device__ half  g_ffn [(size_t)NTOK*CFF];
// weights transposed to [N,K] fp16
__device__ half g_wqkv [(size_t)CH*3*CH];
__device__ half g_wproj[(size_t)CH*CH];
__device__ half g_w1   [(size_t)CH*CFF];
__device__ half g_w2   [(size_t)CFF*CH];

// ---------------- PTX helpers ----------------
__device__ __forceinline__ uint32_t smem_u32(const void* p){
    uint32_t a;
    asm("{ .reg .u64 t; cvta.to.shared.u64 t, %1; cvt.u32.u64 %0, t; }" : "=r"(a) : "l"(p));
    return a;
}
#define CP_ASYNC16(dst, src) \
    asm volatile("cp.async.cg.shared.global [%0], [%1], 16;" :: "r"(dst), "l"(src))
#define CP_COMMIT() asm volatile("cp.async.commit_group;" ::: "memory")
#define CP_WAIT(N)  asm volatile("cp.async.wait_group %0;" :: "n"(N) : "memory")

#define LDSM_X4(r, a) \
    asm volatile("ldmatrix.sync.aligned.m8n8.x4.shared.b16 {%0,%1,%2,%3}, [%4];" \
        : "=r"((r)[0]), "=r"((r)[1]), "=r"((r)[2]), "=r"((r)[3]) : "r"(a))

#define MMA_F16(d, a, b0, b1) \
    asm volatile("mma.sync.aligned.m16n8k16.row.col.f32.f16.f16.f32 " \
        "{%0,%1,%2,%3}, {%4,%5,%6,%7}, {%8,%9}, {%0,%1,%2,%3};" \
        : "+f"((d)[0]), "+f"((d)[1]), "+f"((d)[2]), "+f"((d)[3]) \
        : "r"((a)[0]), "r"((a)[1]), "r"((a)[2]), "r"((a)[3]), "r"(b0), "r"(b1))

// fast GELU: tanh form with HW tanh.approx (MUFU)
__device__ __forceinline__ float gelu_fast(float x){
    float u = 0.7978845608028654f * fmaf(0.044715f * x, x * x, x);
    float t;
    asm("tanh.approx.f32 %0, %1;" : "=f"(t) : "f"(u));
    return 0.5f * x * (1.0f + t);
}

// ---------------- fp16 HMMA GEMM, 4-stage cp.async pipeline ----------------
// C[M,N] = A @ B^T + bias ; A: [M,K] fp16, B: [N,K] fp16, fp32 accumulate.
// CTA tile 128x128, BK=32, 256 threads, rows padded to 80B (conflict-free
// ldmatrix: bank-quad (5r+c)%8 is a permutation over 8 rows).
// Stage = 20KB; 4 stages = 80KB -> 2 CTAs/SM (barrier overlap between CTAs).
// EPI=1: GELU -> fp16. EPI=2: +res(fp16) -> fp32. EPI=3: fp16.
#define TILEB  10240
#define STAGEB 20480
#define GSMEM  (4*STAGEB)

template<int EPI>
__global__ __launch_bounds__(256, 2) void hmma_gemm(
    const half* __restrict__ Ag, const half* __restrict__ Bg,
    const float* __restrict__ bias, const half* __restrict__ res,
    float* __restrict__ Cf, half* __restrict__ Ch,
    int K, int Nc)
{
    extern __shared__ char smem[];
    const int tid = threadIdx.x;
    const int lane = tid & 31, wid = tid >> 5;
    const int wm = wid & 1, wn = wid >> 1;          // warp tile: 64 x 32

    const half* Ab = Ag + (size_t)blockIdx.y * 128 * K;
    const half* Bb = Bg + (size_t)blockIdx.x * 128 * K;

    const uint32_t sb = smem_u32(smem);
    const int NK = K >> 5;

    float acc[4][4][4];
    #pragma unroll
    for (int a = 0; a < 4; a++)
        #pragma unroll
        for (int b = 0; b < 4; b++)
            #pragma unroll
            for (int c = 0; c < 4; c++) acc[a][b][c] = 0.f;

    const int lr0 = tid >> 2;          // 0..63
    const int lc  = tid & 3;           // 16B chunk 0..3
    auto load_stage = [&](int kb, int s) {
        uint32_t st = sb + (uint32_t)s * STAGEB;
        #pragma unroll
        for (int i = 0; i < 4; i++) {
            const int t = i >> 1;
            int r = (i & 1) * 64 + lr0;
            const half* src = (t ? Bb : Ab) + (size_t)r * K + kb * 32 + lc * 8;
            uint32_t dst = st + (uint32_t)(t * TILEB + r * 80 + lc * 16);
            CP_ASYNC16(dst, src);
        }
        CP_COMMIT();
    };

    auto compute_stage = [&](int s) {
        uint32_t st = sb + (uint32_t)s * STAGEB;
        #pragma unroll
        for (int kk = 0; kk < 2; kk++) {
            const int ch = kk * 2 + (lane >> 4);
            uint32_t bh[2][4];
            #pragma unroll
            for (int np = 0; np < 2; np++) {
                int row = wn * 32 + np * 16 + (lane & 15);
                uint32_t off = (uint32_t)(row * 80 + ch * 16);
                LDSM_X4(bh[np], st + 1u * TILEB + off);
            }
            #pragma unroll
            for (int mt = 0; mt < 4; mt++) {
                int row = wm * 64 + mt * 16 + (lane & 15);
                uint32_t off = (uint32_t)(row * 80 + ch * 16);
                uint32_t ah[4];
                LDSM_X4(ah, st + off);
                #pragma unroll
                for (int nt = 0; nt < 4; nt++) {
                    int np = nt >> 1, se = nt & 1;
                    MMA_F16(acc[mt][nt], ah, bh[np][se], bh[np][se + 2]);
                }
            }
        }
    };

    // prologue: fill 3 stages
    load_stage(0, 0);
    if (NK > 1) load_stage(1, 1);
    if (NK > 2) load_stage(2, 2);

    for (int kb = 0; kb < NK; kb++) {
        if (kb + 3 <= NK) { CP_WAIT(2); }
        else if (kb + 2 == NK) { CP_WAIT(1); }
        else { CP_WAIT(0); }
        __syncthreads();
        if (kb + 3 < NK) load_stage(kb + 3, (kb + 3) & 3);
        compute_stage(kb & 3);
    }

    // --- epilogue: registers -> gmem ---
    int row0 = blockIdx.y * 128 + wm * 64;
    int col0 = blockIdx.x * 128 + wn * 32;
    #pragma unroll
    for (int mt = 0; mt < 4; mt++) {
        #pragma unroll
        for (int nt = 0; nt < 4; nt++) {
            int c = col0 + nt * 8 + (lane & 3) * 2;
            float b0 = bias[c], b1 = bias[c + 1];
            #pragma unroll
            for (int h = 0; h < 2; h++) {
                int r = row0 + mt * 16 + (lane >> 2) + h * 8;
                float v0 = acc[mt][nt][h * 2]     + b0;
                float v1 = acc[mt][nt][h * 2 + 1] + b1;
                size_t o = (size_t)r * Nc + c;
                if (EPI == 1) {
                    v0 = gelu_fast(v0);
                    v1 = gelu_fast(v1);
                    *(half2*)(Ch + o) = __floats2half2_rn(v0, v1);
                } else if (EPI == 3) {
                    *(half2*)(Ch + o) = __floats2half2_rn(v0, v1);
                } else {
                    if (EPI == 2) {
                        float2 rv = __half22float2(*(const half2*)(res + o));
                        v0 += rv.x; v1 += rv.y;
                    }
                    *(float2*)(Cf + o) = make_float2(v0, v1);
                }
            }
        }
    }
}

// ---------------- weight prep: [K,N] fp32 -> [N,K] fp16 (tiled transpose) ----------------
__global__ __launch_bounds__(256) void prep_w(
    const float* __restrict__ W, half* __restrict__ Wh, int K, int N)
{
    __shared__ float tile[32][33];
    int nb = blockIdx.x * 32, kb = blockIdx.y * 32;
    int tx = threadIdx.x & 31, ty = threadIdx.x >> 5;  // 32 x 8
    #pragma unroll
    for (int j = 0; j < 32; j += 8)
        tile[ty + j][tx] = W[(size_t)(kb + ty + j) * N + nb + tx];
    __syncthreads();
    #pragma unroll
    for (int j = 0; j < 32; j += 8)
        Wh[(size_t)(nb + ty + j) * K + kb + tx] = __float2half_rn(tile[tx][ty + j]);
}

// ---------------- block reduction (256 threads) ----------------
__device__ __forceinline__ void block_reduce_2(float& s, float& sq) {
    __shared__ float sh[16];
    int lane = threadIdx.x & 31, wid = threadIdx.x >> 5;
    #pragma unroll
    for (int o = 16; o > 0; o >>= 1) {
        s  += __shfl_down_sync(0xffffffffu, s,  o);
        sq += __shfl_down_sync(0xffffffffu, sq, o);
    }
    if (lane == 0) { sh[wid] = s; sh[wid + 8] = sq; }
    __syncthreads();
    if (threadIdx.x == 0) {
        float S = 0.f, SQ = 0.f;
        #pragma unroll
        for (int i = 0; i < 8; i++) { S += sh[i]; SQ += sh[i + 8]; }
        sh[0] = S; sh[8] = SQ;
    }
    __syncthreads();
    s = sh[0]; sq = sh[8];
}

// ---------------- LN1 + shift + window partition -> fp16 (float2 vectorized) ----------------
__global__ __launch_bounds__(256) void ln1_window_kernel(
    const float* __restrict__ x, const float* __restrict__ g, const float* __restrict__ b,
    half* __restrict__ out)
{
    int t = blockIdx.x;
    int w = t / NTOKW, tok = t - w * NTOKW;
    int bb = w >> 6, wrem = w & 63;
    int wi = wrem >> 3, wj = wrem & 7;
    int ti = tok / MWIN, tj = tok - ti * MWIN;
    int r = (wi * MWIN + ti + SHIFT) % HDIM;
    int c = (wj * MWIN + tj + SHIFT) % WDIM;
    const float2* src = (const float2*)(x + ((size_t)bb * (HDIM * WDIM) + r * WDIM + c) * CH);
    int tid = threadIdx.x;
    float2 v = src[tid];
    float s = v.x + v.y, sq = v.x * v.x + v.y * v.y;
    block_reduce_2(s, sq);
    float mu  = s * (1.0f / CH);
    float var = sq * (1.0f / CH) - mu * mu;
    float inv = rsqrtf(var + 1e-5f);
    float2 gg = ((const float2*)g)[tid];
    float2 bb2 = ((const float2*)b)[tid];
    half2* dst = (half2*)(out + (size_t)t * CH);
    dst[tid] = __floats2half2_rn((v.x - mu) * inv * gg.x + bb2.x,
                                 (v.y - mu) * inv * gg.y + bb2.y);
}

// ---------------- windowed attention: register-tiled, fp16 half2 smem ----------------
// One block (128 thr) per (window, head). q/k/v in half2 smem; bias-table
// slice for this head preloaded to smem (169 floats) — converts 28 scattered
// global reads/thread into LDS.
__global__ __launch_bounds__(128) void attn_kernel(
    const half* __restrict__ qkv, const float* __restrict__ bias_table,
    half* __restrict__ out)
{
    int win  = blockIdx.x >> 4;
    int head = blockIdx.x & 15;
    __shared__ half2 qh[52][17], kh[52][17], vh[52][17];
    __shared__ float sc[52][57];
    __shared__ float sbias[(2*MWIN-1)*(2*MWIN-1)];   // 169
    int tid = threadIdx.x;
    const float scale = 0.17677669529663687f;
    size_t base = (size_t)win * NTOKW * (3 * CH) + head * DH;

    // preload bias slice for this head
    for (int i = tid; i < (2*MWIN-1)*(2*MWIN-1); i += 128)
        sbias[i] = bias_table[i * NHEAD + head];

    // load Q,K,V as half2 (direct copy, no conversion)
    for (int i = tid; i < NTOKW * 16; i += 128) {
        int n = i >> 4, c = i & 15;
        size_t rb = base + (size_t)n * (3 * CH) + c * 2;
        qh[n][c] = *(const half2*)(qkv + rb);
        kh[n][c] = *(const half2*)(qkv + rb + CH);
        vh[n][c] = *(const half2*)(qkv + rb + 2 * CH);
    }
    __syncthreads();

    // QK^T + bias: 13x7 grid of 4x7 tiles (91 threads)
    if (tid < 91) {
        int tr = tid / 7, tc = tid - tr * 7;
        int n0 = tr * 4, m0 = tc * 7;
        float acc[4][7];
        #pragma unroll
        for (int i = 0; i < 4; i++)
            #pragma unroll
            for (int j = 0; j < 7; j++) acc[i][j] = 0.f;
        #pragma unroll 4
        for (int dp = 0; dp < 16; dp++) {
            float2 qr[4], kr[7];
            #pragma unroll
            for (int i = 0; i < 4; i++) qr[i] = __half22float2(qh[n0 + i][dp]);
            #pragma unroll
            for (int j = 0; j < 7; j++) kr[j] = __half22float2(kh[m0 + j][dp]);
            #pragma unroll
            for (int i = 0; i < 4; i++)
                #pragma unroll
                for (int j = 0; j < 7; j++) {
                    acc[i][j] = fmaf(qr[i].x, kr[j].x, acc[i][j]);
                    acc[i][j] = fmaf(qr[i].y, kr[j].y, acc[i][j]);
                }
        }
        #pragma unroll
        for (int i = 0; i < 4; i++) {
            int n = n0 + i;
            int nn = n < NTOKW ? n : NTOKW - 1;
            int nr = nn / MWIN, ncm = nn - nr * MWIN;
            #pragma unroll
            for (int j = 0; j < 7; j++) {
                int m = m0 + j;
                int mr = m / MWIN, mc = m - mr * MWIN;
                int dr = nr - mr + (MWIN - 1), dc = ncm - mc + (MWIN - 1);
                sc[n][m] = acc[i][j] * scale + sbias[dr * (2 * MWIN - 1) + dc];
            }
        }
    }
    __syncthreads();

    // softmax per row
    if (tid < NTOKW) {
        float* row = sc[tid];
        float mx = -1e30f;
        #pragma unroll 7
        for (int m = 0; m < NTOKW; m++) mx = fmaxf(mx, row[m]);
        float sum = 0.f;
        #pragma unroll 7
        for (int m = 0; m < NTOKW; m++) { float e = __expf(row[m] - mx); row[m] = e; sum += e; }
        float inv = 1.0f / sum;
        #pragma unroll 7
        for (int m = 0; m < NTOKW; m++) row[m] *= inv;
    }
    __syncthreads();

    // AV: 13x8 grid of 4x4 tiles (104 threads)
    if (tid < 104) {
        int tr = tid >> 3, dc = tid & 7;
        int n0 = tr * 4, d0 = dc * 2;      // d0 in half2 units (covers 4 floats)
        float acc[4][4];
        #pragma unroll
        for (int i = 0; i < 4; i++)
            #pragma unroll
            for (int k = 0; k < 4; k++) acc[i][k] = 0.f;
        #pragma unroll 7
        for (int m = 0; m < NTOKW; m++) {
            float2 v0 = __half22float2(vh[m][d0]);
            float2 v1 = __half22float2(vh[m][d0 + 1]);
            float pp[4];
            #pragma unroll
            for (int i = 0; i < 4; i++) pp[i] = sc[n0 + i][m];
            #pragma unroll
            for (int i = 0; i < 4; i++) {
                acc[i][0] = fmaf(pp[i], v0.x, acc[i][0]);
                acc[i][1] = fmaf(pp[i], v0.y, acc[i][1]);
                acc[i][2] = fmaf(pp[i], v1.x, acc[i][2]);
                acc[i][3] = fmaf(pp[i], v1.y, acc[i][3]);
            }
        }
        #pragma unroll
        for (int i = 0; i < 4; i++) {
            int n = n0 + i;
            if (n < NTOKW) {
                size_t o = ((size_t)win * NTOKW + n) * CH + head * DH + d0 * 2;
                *(half2*)(out + o)     = __floats2half2_rn(acc[i][0], acc[i][1]);
                *(half2*)(out + o + 2) = __floats2half2_rn(acc[i][2], acc[i][3]);
            }
        }
    }
}

// ---------------- window reverse + roll + residual + LN2 (vectorized, fp16 I/O) ----------------
__global__ __launch_bounds__(256) void res_ln2_kernel(
    const float* __restrict__ x, const half* __restrict__ proj,
    const float* __restrict__ g, const float* __restrict__ b,
    half* __restrict__ x2, half* __restrict__ h2)
{
    int t = blockIdx.x;
    int bb = t / (HDIM * WDIM);
    int rc = t - bb * (HDIM * WDIM);
    int r = rc / WDIM, c = rc - r * WDIM;
    int rs = (r - SHIFT + HDIM) % HDIM;
    int cs = (c - SHIFT + WDIM) % WDIM;
    int w   = bb * 64 + (rs / MWIN) * 8 + (cs / MWIN);
    int tok = (rs % MWIN) * MWIN + (cs % MWIN);
    const half2* ps = (const half2*)(proj + ((size_t)w * NTOKW + tok) * CH);
    const float2* xs = (const float2*)(x + (size_t)t * CH);
    int tid = threadIdx.x;
    float2 xv = xs[tid];
    float2 pv = __half22float2(ps[tid]);
    float v0 = xv.x + pv.x;
    float v1 = xv.y + pv.y;
    half2* x2p = (half2*)(x2 + (size_t)t * CH);
    x2p[tid] = __floats2half2_rn(v0, v1);
    float s = v0 + v1, sq = v0 * v0 + v1 * v1;
    block_reduce_2(s, sq);
    float mu  = s * (1.0f / CH);
    float var = sq * (1.0f / CH) - mu * mu;
    float inv = rsqrtf(var + 1e-5f);
    float2 gg = ((const float2*)g)[tid];
    float2 bb2 = ((const float2*)b)[tid];
    half2* h2p = (half2*)(h2 + (size_t)t * CH);
    h2p[tid] = __floats2half2_rn((v0 - mu) * inv * gg.x + bb2.x,
                                 (v1 - mu) * inv * gg.y + bb2.y);
}

// ---------------- launcher ----------------
extern "C" void kernel_launch(void* const* d_in, const int* in_sizes, int n_in,
                              void* d_out, int out_size)
{
    const float* x          = (const float*)d_in[0];
    const float* w_qkv      = (const float*)d_in[3];
    const float* b_qkv      = (const float*)d_in[4];
    const float* w_proj     = (const float*)d_in[5];
    const float* b_proj     = (const float*)d_in[6];
    const float* bias_table = (const float*)d_in[7];
    const float* g1         = (const float*)d_in[8];
    const float* be1        = (const float*)d_in[9];
    const float* g2         = (const float*)d_in[10];
    const float* be2        = (const float*)d_in[11];
    const float* w1         = (const float*)d_in[12];
    const float* b1         = (const float*)d_in[13];
    const float* w2         = (const float*)d_in[14];
    const float* b2         = (const float*)d_in[15];
    float* out = (float*)d_out;

    half *p_xw, *p_qkv, *p_att, *p_proj, *p_x2h, *p_h2, *p_ffn;
    half *p_wqkv, *p_wproj, *p_w1, *p_w2;
    cudaGetSymbolAddress((void**)&p_xw,   g_xw);
    cudaGetSymbolAddress((void**)&p_qkv,  g_qkv);
    cudaGetSymbolAddress((void**)&p_att,  g_att);
    cudaGetSymbolAddress((void**)&p_proj, g_proj);
    cudaGetSymbolAddress((void**)&p_x2h,  g_x2h);
    cudaGetSymbolAddress((void**)&p_h2,   g_h2);
    cudaGetSymbolAddress((void**)&p_ffn,  g_ffn);
    cudaGetSymbolAddress((void**)&p_wqkv,  g_wqkv);
    cudaGetSymbolAddress((void**)&p_wproj, g_wproj);
    cudaGetSymbolAddress((void**)&p_w1,    g_w1);
    cudaGetSymbolAddress((void**)&p_w2,    g_w2);

    cudaFuncSetAttribute(hmma_gemm<1>, cudaFuncAttributeMaxDynamicSharedMemorySize, GSMEM);
    cudaFuncSetAttribute(hmma_gemm<2>, cudaFuncAttributeMaxDynamicSharedMemorySize, GSMEM);
    cudaFuncSetAttribute(hmma_gemm<3>, cudaFuncAttributeMaxDynamicSharedMemorySize, GSMEM);

    // weight prep (tiled transpose to fp16)
    prep_w<<<dim3((3*CH)/32, CH/32), 256>>>(w_qkv, p_wqkv, CH, 3*CH);
    prep_w<<<dim3(CH/32,     CH/32), 256>>>(w_proj, p_wproj, CH, CH);
    prep_w<<<dim3(CFF/32,    CH/32), 256>>>(w1, p_w1, CH, CFF);
    prep_w<<<dim3(CH/32,    CFF/32), 256>>>(w2, p_w2, CFF, CH);

    // 1. LN1 + shift + window partition -> fp16
    ln1_window_kernel<<<NTOK, 256>>>(x, g1, be1, p_xw);

    // 2. QKV GEMM -> fp16 (bias only)
    hmma_gemm<3><<<dim3((3*CH)/128, NTOK/128), 256, GSMEM>>>(
        p_xw, p_wqkv, b_qkv, nullptr, nullptr, p_qkv, CH, 3*CH);

    // 3. windowed attention -> fp16
    attn_kernel<<<NWIN * NHEAD, 128>>>(p_qkv, bias_table, p_att);

    // 4. proj GEMM -> fp16
    hmma_gemm<3><<<dim3(CH/128, NTOK/128), 256, GSMEM>>>(
        p_att, p_wproj, b_proj, nullptr, nullptr, p_proj, CH, CH);

    // 5. window reverse + roll + residual + LN2 (x2 stored fp16)
    res_ln2_kernel<<<NTOK, 256>>>(x, p_proj, g2, be2, p_x2h, p_h2);

    // 6. FFN1 + fast GELU -> fp16
    hmma_gemm<1><<<dim3(CFF/128, NTOK/128), 256, GSMEM>>>(
        p_h2, p_w1, b1, nullptr, nullptr, p_ffn, CH, CFF);

    // 7. FFN2 + residual(fp16) -> fp32 out
    hmma_gemm<2><<<dim3(CH/128, NTOK/128), 256, GSMEM>>>(
        p_ffn, p_w2, b2, p_x2h, out, nullptr, CFF, CH);
}

// round 14
// speedup vs baseline: 1.2078x; 1.0471x over previous
#include <cuda_runtime.h>
#include <cuda_fp16.h>
#include <math.h>
#include <stdint.h>

// ---------------- problem constants ----------------
#define BATCH 16
#define HDIM  56
#define WDIM  56
#define CH    512
#define CFF   2048
#define NHEAD 16
#define DH    32
#define MWIN  7
#define NTOKW 49
#define SHIFT 3
#define NTOK  (BATCH*HDIM*WDIM)                  // 50176
#define NWIN  (BATCH*(HDIM/MWIN)*(WDIM/MWIN))    // 1024

// ---------------- device scratch (allocation-free) ----------------
__device__ half  g_xw  [(size_t)NTOK*CH];
__device__ half  g_qkv [(size_t)NTOK*3*CH];
__device__ half  g_att [(size_t)NTOK*CH];
__device__ half  g_proj[(size_t)NTOK*CH];
__device__ half  g_x2h [(size_t)NTOK*CH];
__device__ half  g_h2  [(size_t)NTOK*CH];
__device__ half  g_ffn [(size_t)NTOK*CFF];
// weights transposed to [N,K] fp16
__device__ half g_wqkv [(size_t)CH*3*CH];
__device__ half g_wproj[(size_t)CH*CH];
__device__ half g_w1   [(size_t)CH*CFF];
__device__ half g_w2   [(size_t)CFF*CH];

// ---------------- PTX helpers ----------------
__device__ __forceinline__ uint32_t smem_u32(const void* p){
    uint32_t a;
    asm("{ .reg .u64 t; cvta.to.shared.u64 t, %1; cvt.u32.u64 %0, t; }" : "=r"(a) : "l"(p));
    return a;
}
#define CP_ASYNC16(dst, src) \
    asm volatile("cp.async.cg.shared.global [%0], [%1], 16;" :: "r"(dst), "l"(src))
#define CP_COMMIT() asm volatile("cp.async.commit_group;" ::: "memory")
#define CP_WAIT(N)  asm volatile("cp.async.wait_group %0;" :: "n"(N) : "memory")

#define LDSM_X4(r, a) \
    asm volatile("ldmatrix.sync.aligned.m8n8.x4.shared.b16 {%0,%1,%2,%3}, [%4];" \
        : "=r"((r)[0]), "=r"((r)[1]), "=r"((r)[2]), "=r"((r)[3]) : "r"(a))

#define MMA_F16(d, a, b0, b1) \
    asm volatile("mma.sync.aligned.m16n8k16.row.col.f32.f16.f16.f32 " \
        "{%0,%1,%2,%3}, {%4,%5,%6,%7}, {%8,%9}, {%0,%1,%2,%3};" \
        : "+f"((d)[0]), "+f"((d)[1]), "+f"((d)[2]), "+f"((d)[3]) \
        : "r"((a)[0]), "r"((a)[1]), "r"((a)[2]), "r"((a)[3]), "r"(b0), "r"(b1))

// fast GELU: tanh form with HW tanh.approx (MUFU)
__device__ __forceinline__ float gelu_fast(float x){
    float u = 0.7978845608028654f * fmaf(0.044715f * x, x * x, x);
    float t;
    asm("tanh.approx.f32 %0, %1;" : "=f"(t) : "f"(u));
    return 0.5f * x * (1.0f + t);
}

// ---------------- fp16 HMMA GEMM, 5-stage ring, paired-stage sync ----------------
// C[M,N] = A @ B^T + bias ; A: [M,K] fp16, B: [N,K] fp16, fp32 accumulate.
// CTA tile 128x128, BK=32, 256 threads, rows padded to 80B (conflict-free
// ldmatrix: bank-quad (5r+c)%8 is a permutation over 8 rows).
// 5 stages x 20KB = 100KB -> 2 CTAs/SM. Two k-blocks computed per barrier
// (halves sync count vs 1-per-k-block). Requires NK even and >= 4.
// EPI=1: GELU -> fp16. EPI=2: +res(fp16) -> fp32. EPI=3: fp16.
#define TILEB  10240
#define STAGEB 20480
#define GSMEM  (5*STAGEB)

template<int EPI>
__global__ __launch_bounds__(256, 2) void hmma_gemm(
    const half* __restrict__ Ag, const half* __restrict__ Bg,
    const float* __restrict__ bias, const half* __restrict__ res,
    float* __restrict__ Cf, half* __restrict__ Ch,
    int K, int Nc)
{
    extern __shared__ char smem[];
    const int tid = threadIdx.x;
    const int lane = tid & 31, wid = tid >> 5;
    const int wm = wid & 1, wn = wid >> 1;          // warp tile: 64 x 32

    const half* Ab = Ag + (size_t)blockIdx.y * 128 * K;
    const half* Bb = Bg + (size_t)blockIdx.x * 128 * K;

    const uint32_t sb = smem_u32(smem);
    const int NK = K >> 5;

    float acc[4][4][4];
    #pragma unroll
    for (int a = 0; a < 4; a++)
        #pragma unroll
        for (int b = 0; b < 4; b++)
            #pragma unroll
            for (int c = 0; c < 4; c++) acc[a][b][c] = 0.f;

    const int lr0 = tid >> 2;          // 0..63
    const int lc  = tid & 3;           // 16B chunk 0..3
    auto load_stage = [&](int kb, int s) {
        uint32_t st = sb + (uint32_t)s * STAGEB;
        #pragma unroll
        for (int i = 0; i < 4; i++) {
            const int t = i >> 1;
            int r = (i & 1) * 64 + lr0;
            const half* src = (t ? Bb : Ab) + (size_t)r * K + kb * 32 + lc * 8;
            uint32_t dst = st + (uint32_t)(t * TILEB + r * 80 + lc * 16);
            CP_ASYNC16(dst, src);
        }
        CP_COMMIT();
    };

    auto compute_stage = [&](int s) {
        uint32_t st = sb + (uint32_t)s * STAGEB;
        #pragma unroll
        for (int kk = 0; kk < 2; kk++) {
            const int ch = kk * 2 + (lane >> 4);
            uint32_t bh[2][4];
            #pragma unroll
            for (int np = 0; np < 2; np++) {
                int row = wn * 32 + np * 16 + (lane & 15);
                uint32_t off = (uint32_t)(row * 80 + ch * 16);
                LDSM_X4(bh[np], st + 1u * TILEB + off);
            }
            #pragma unroll
            for (int mt = 0; mt < 4; mt++) {
                int row = wm * 64 + mt * 16 + (lane & 15);
                uint32_t off = (uint32_t)(row * 80 + ch * 16);
                uint32_t ah[4];
                LDSM_X4(ah, st + off);
                #pragma unroll
                for (int nt = 0; nt < 4; nt++) {
                    int np = nt >> 1, se = nt & 1;
                    MMA_F16(acc[mt][nt], ah, bh[np][se], bh[np][se + 2]);
                }
            }
        }
    };

    // prologue: fill 3 stages
    load_stage(0, 0);
    load_stage(1, 1);
    load_stage(2, 2);

    // paired-stage mainloop: 2 k-blocks per barrier, 5-slot ring
    for (int kb = 0; kb < NK; kb += 2) {
        if (kb + 2 < NK) { CP_WAIT(1); }   // stages kb, kb+1 landed
        else             { CP_WAIT(0); }
        __syncthreads();
        if (kb + 3 < NK) load_stage(kb + 3, (kb + 3) % 5);
        if (kb + 4 < NK) load_stage(kb + 4, (kb + 4) % 5);
        compute_stage(kb % 5);
        compute_stage((kb + 1) % 5);
    }

    // --- epilogue: registers -> gmem ---
    int row0 = blockIdx.y * 128 + wm * 64;
    int col0 = blockIdx.x * 128 + wn * 32;
    #pragma unroll
    for (int mt = 0; mt < 4; mt++) {
        #pragma unroll
        for (int nt = 0; nt < 4; nt++) {
            int c = col0 + nt * 8 + (lane & 3) * 2;
            float b0 = bias[c], b1 = bias[c + 1];
            #pragma unroll
            for (int h = 0; h < 2; h++) {
                int r = row0 + mt * 16 + (lane >> 2) + h * 8;
                float v0 = acc[mt][nt][h * 2]     + b0;
                float v1 = acc[mt][nt][h * 2 + 1] + b1;
                size_t o = (size_t)r * Nc + c;
                if (EPI == 1) {
                    v0 = gelu_fast(v0);
                    v1 = gelu_fast(v1);
                    *(half2*)(Ch + o) = __floats2half2_rn(v0, v1);
                } else if (EPI == 3) {
                    *(half2*)(Ch + o) = __floats2half2_rn(v0, v1);
                } else {
                    if (EPI == 2) {
                        float2 rv = __half22float2(*(const half2*)(res + o));
                        v0 += rv.x; v1 += rv.y;
                    }
                    *(float2*)(Cf + o) = make_float2(v0, v1);
                }
            }
        }
    }
}

// ---------------- weight prep: [K,N] fp32 -> [N,K] fp16 (tiled transpose) ----------------
__global__ __launch_bounds__(256) void prep_w(
    const float* __restrict__ W, half* __restrict__ Wh, int K, int N)
{
    __shared__ float tile[32][33];
    int nb = blockIdx.x * 32, kb = blockIdx.y * 32;
    int tx = threadIdx.x & 31, ty = threadIdx.x >> 5;  // 32 x 8
    #pragma unroll
    for (int j = 0; j < 32; j += 8)
        tile[ty + j][tx] = W[(size_t)(kb + ty + j) * N + nb + tx];
    __syncthreads();
    #pragma unroll
    for (int j = 0; j < 32; j += 8)
        Wh[(size_t)(nb + ty + j) * K + kb + tx] = __float2half_rn(tile[tx][ty + j]);
}

// ---------------- block reduction (128 threads, 4 warps) ----------------
__device__ __forceinline__ void block_reduce_128(float& s, float& sq) {
    __shared__ float sh[8];
    int lane = threadIdx.x & 31, wid = threadIdx.x >> 5;
    #pragma unroll
    for (int o = 16; o > 0; o >>= 1) {
        s  += __shfl_down_sync(0xffffffffu, s,  o);
        sq += __shfl_down_sync(0xffffffffu, sq, o);
    }
    if (lane == 0) { sh[wid] = s; sh[wid + 4] = sq; }
    __syncthreads();
    if (threadIdx.x == 0) {
        float S = 0.f, SQ = 0.f;
        #pragma unroll
        for (int i = 0; i < 4; i++) { S += sh[i]; SQ += sh[i + 4]; }
        sh[0] = S; sh[4] = SQ;
    }
    __syncthreads();
    s = sh[0]; sq = sh[4];
}

// ---------------- LN1 + shift + window partition -> fp16 (float4, 128 thr) ----------------
__global__ __launch_bounds__(128) void ln1_window_kernel(
    const float* __restrict__ x, const float* __restrict__ g, const float* __restrict__ b,
    half* __restrict__ out)
{
    int t = blockIdx.x;
    int w = t / NTOKW, tok = t - w * NTOKW;
    int bb = w >> 6, wrem = w & 63;
    int wi = wrem >> 3, wj = wrem & 7;
    int ti = tok / MWIN, tj = tok - ti * MWIN;
    int r = (wi * MWIN + ti + SHIFT) % HDIM;
    int c = (wj * MWIN + tj + SHIFT) % WDIM;
    const float4* src = (const float4*)(x + ((size_t)bb * (HDIM * WDIM) + r * WDIM + c) * CH);
    int tid = threadIdx.x;
    float4 v = src[tid];
    float s  = v.x + v.y + v.z + v.w;
    float sq = v.x*v.x + v.y*v.y + v.z*v.z + v.w*v.w;
    block_reduce_128(s, sq);
    float mu  = s * (1.0f / CH);
    float var = sq * (1.0f / CH) - mu * mu;
    float inv = rsqrtf(var + 1e-5f);
    float4 gg = ((const float4*)g)[tid];
    float4 bb4 = ((const float4*)b)[tid];
    half2 h01 = __floats2half2_rn((v.x - mu) * inv * gg.x + bb4.x,
                                  (v.y - mu) * inv * gg.y + bb4.y);
    half2 h23 = __floats2half2_rn((v.z - mu) * inv * gg.z + bb4.z,
                                  (v.w - mu) * inv * gg.w + bb4.w);
    half2* dst = (half2*)(out + (size_t)t * CH);
    dst[tid * 2]     = h01;
    dst[tid * 2 + 1] = h23;
}

// ---------------- windowed attention: register-tiled, fp16 half2 smem ----------------
__global__ __launch_bounds__(128) void attn_kernel(
    const half* __restrict__ qkv, const float* __restrict__ bias_table,
    half* __restrict__ out)
{
    int win  = blockIdx.x >> 4;
    int head = blockIdx.x & 15;
    __shared__ half2 qh[52][17], kh[52][17], vh[52][17];
    __shared__ float sc[52][57];
    __shared__ float sbias[(2*MWIN-1)*(2*MWIN-1)];   // 169
    int tid = threadIdx.x;
    const float scale = 0.17677669529663687f;
    size_t base = (size_t)win * NTOKW * (3 * CH) + head * DH;

    for (int i = tid; i < (2*MWIN-1)*(2*MWIN-1); i += 128)
        sbias[i] = bias_table[i * NHEAD + head];

    for (int i = tid; i < NTOKW * 16; i += 128) {
        int n = i >> 4, c = i & 15;
        size_t rb = base + (size_t)n * (3 * CH) + c * 2;
        qh[n][c] = *(const half2*)(qkv + rb);
        kh[n][c] = *(const half2*)(qkv + rb + CH);
        vh[n][c] = *(const half2*)(qkv + rb + 2 * CH);
    }
    __syncthreads();

    if (tid < 91) {
        int tr = tid / 7, tc = tid - tr * 7;
        int n0 = tr * 4, m0 = tc * 7;
        float acc[4][7];
        #pragma unroll
        for (int i = 0; i < 4; i++)
            #pragma unroll
            for (int j = 0; j < 7; j++) acc[i][j] = 0.f;
        #pragma unroll 4
        for (int dp = 0; dp < 16; dp++) {
            float2 qr[4], kr[7];
            #pragma unroll
            for (int i = 0; i < 4; i++) qr[i] = __half22float2(qh[n0 + i][dp]);
            #pragma unroll
            for (int j = 0; j < 7; j++) kr[j] = __half22float2(kh[m0 + j][dp]);
            #pragma unroll
            for (int i = 0; i < 4; i++)
                #pragma unroll
                for (int j = 0; j < 7; j++) {
                    acc[i][j] = fmaf(qr[i].x, kr[j].x, acc[i][j]);
                    acc[i][j] = fmaf(qr[i].y, kr[j].y, acc[i][j]);
                }
        }
        #pragma unroll
        for (int i = 0; i < 4; i++) {
            int n = n0 + i;
            int nn = n < NTOKW ? n : NTOKW - 1;
            int nr = nn / MWIN, ncm = nn - nr * MWIN;
            #pragma unroll
            for (int j = 0; j < 7; j++) {
                int m = m0 + j;
                int mr = m / MWIN, mc = m - mr * MWIN;
                int dr = nr - mr + (MWIN - 1), dc = ncm - mc + (MWIN - 1);
                sc[n][m] = acc[i][j] * scale + sbias[dr * (2 * MWIN - 1) + dc];
            }
        }
    }
    __syncthreads();

    if (tid < NTOKW) {
        float* row = sc[tid];
        float mx = -1e30f;
        #pragma unroll 7
        for (int m = 0; m < NTOKW; m++) mx = fmaxf(mx, row[m]);
        float sum = 0.f;
        #pragma unroll 7
        for (int m = 0; m < NTOKW; m++) { float e = __expf(row[m] - mx); row[m] = e; sum += e; }
        float inv = 1.0f / sum;
        #pragma unroll 7
        for (int m = 0; m < NTOKW; m++) row[m] *= inv;
    }
    __syncthreads();

    if (tid < 104) {
        int tr = tid >> 3, dc = tid & 7;
        int n0 = tr * 4, d0 = dc * 2;
        float acc[4][4];
        #pragma unroll
        for (int i = 0; i < 4; i++)
            #pragma unroll
            for (int k = 0; k < 4; k++) acc[i][k] = 0.f;
        #pragma unroll 7
        for (int m = 0; m < NTOKW; m++) {
            float2 v0 = __half22float2(vh[m][d0]);
            float2 v1 = __half22float2(vh[m][d0 + 1]);
            float pp[4];
            #pragma unroll
            for (int i = 0; i < 4; i++) pp[i] = sc[n0 + i][m];
            #pragma unroll
            for (int i = 0; i < 4; i++) {
                acc[i][0] = fmaf(pp[i], v0.x, acc[i][0]);
                acc[i][1] = fmaf(pp[i], v0.y, acc[i][1]);
                acc[i][2] = fmaf(pp[i], v1.x, acc[i][2]);
                acc[i][3] = fmaf(pp[i], v1.y, acc[i][3]);
            }
        }
        #pragma unroll
        for (int i = 0; i < 4; i++) {
            int n = n0 + i;
            if (n < NTOKW) {
                size_t o = ((size_t)win * NTOKW + n) * CH + head * DH + d0 * 2;
                *(half2*)(out + o)     = __floats2half2_rn(acc[i][0], acc[i][1]);
                *(half2*)(out + o + 2) = __floats2half2_rn(acc[i][2], acc[i][3]);
            }
        }
    }
}

// ---------------- window reverse + roll + residual + LN2 (float4, 128 thr) ----------------
__global__ __launch_bounds__(128) void res_ln2_kernel(
    const float* __restrict__ x, const half* __restrict__ proj,
    const float* __restrict__ g, const float* __restrict__ b,
    half* __restrict__ x2, half* __restrict__ h2)
{
    int t = blockIdx.x;
    int bb = t / (HDIM * WDIM);
    int rc = t - bb * (HDIM * WDIM);
    int r = rc / WDIM, c = rc - r * WDIM;
    int rs = (r - SHIFT + HDIM) % HDIM;
    int cs = (c - SHIFT + WDIM) % WDIM;
    int w   = bb * 64 + (rs / MWIN) * 8 + (cs / MWIN);
    int tok = (rs % MWIN) * MWIN + (cs % MWIN);
    const half2* ps = (const half2*)(proj + ((size_t)w * NTOKW + tok) * CH);
    const float4* xs = (const float4*)(x + (size_t)t * CH);
    int tid = threadIdx.x;
    float4 xv = xs[tid];
    float2 p01 = __half22float2(ps[tid * 2]);
    float2 p23 = __half22float2(ps[tid * 2 + 1]);
    float v0 = xv.x + p01.x, v1 = xv.y + p01.y;
    float v2 = xv.z + p23.x, v3 = xv.w + p23.y;
    half2* x2p = (half2*)(x2 + (size_t)t * CH);
    x2p[tid * 2]     = __floats2half2_rn(v0, v1);
    x2p[tid * 2 + 1] = __floats2half2_rn(v2, v3);
    float s  = v0 + v1 + v2 + v3;
    float sq = v0*v0 + v1*v1 + v2*v2 + v3*v3;
    block_reduce_128(s, sq);
    float mu  = s * (1.0f / CH);
    float var = sq * (1.0f / CH) - mu * mu;
    float inv = rsqrtf(var + 1e-5f);
    float4 gg = ((const float4*)g)[tid];
    float4 bb4 = ((const float4*)b)[tid];
    half2* h2p = (half2*)(h2 + (size_t)t * CH);
    h2p[tid * 2]     = __floats2half2_rn((v0 - mu) * inv * gg.x + bb4.x,
                                         (v1 - mu) * inv * gg.y + bb4.y);
    h2p[tid * 2 + 1] = __floats2half2_rn((v2 - mu) * inv * gg.z + bb4.z,
                                         (v3 - mu) * inv * gg.w + bb4.w);
}

// ---------------- launcher ----------------
extern "C" void kernel_launch(void* const* d_in, const int* in_sizes, int n_in,
                              void* d_out, int out_size)
{
    const float* x          = (const float*)d_in[0];
    const float* w_qkv      = (const float*)d_in[3];
    const float* b_qkv      = (const float*)d_in[4];
    const float* w_proj     = (const float*)d_in[5];
    const float* b_proj     = (const float*)d_in[6];
    const float* bias_table = (const float*)d_in[7];
    const float* g1         = (const float*)d_in[8];
    const float* be1        = (const float*)d_in[9];
    const float* g2         = (const float*)d_in[10];
    const float* be2        = (const float*)d_in[11];
    const float* w1         = (const float*)d_in[12];
    const float* b1         = (const float*)d_in[13];
    const float* w2         = (const float*)d_in[14];
    const float* b2         = (const float*)d_in[15];
    float* out = (float*)d_out;

    half *p_xw, *p_qkv, *p_att, *p_proj, *p_x2h, *p_h2, *p_ffn;
    half *p_wqkv, *p_wproj, *p_w1, *p_w2;
    cudaGetSymbolAddress((void**)&p_xw,   g_xw);
    cudaGetSymbolAddress((void**)&p_qkv,  g_qkv);
    cudaGetSymbolAddress((void**)&p_att,  g_att);
    cudaGetSymbolAddress((void**)&p_proj, g_proj);
    cudaGetSymbolAddress((void**)&p_x2h,  g_x2h);
    cudaGetSymbolAddress((void**)&p_h2,   g_h2);
    cudaGetSymbolAddress((void**)&p_ffn,  g_ffn);
    cudaGetSymbolAddress((void**)&p_wqkv,  g_wqkv);
    cudaGetSymbolAddress((void**)&p_wproj, g_wproj);
    cudaGetSymbolAddress((void**)&p_w1,    g_w1);
    cudaGetSymbolAddress((void**)&p_w2,    g_w2);

    cudaFuncSetAttribute(hmma_gemm<1>, cudaFuncAttributeMaxDynamicSharedMemorySize, GSMEM);
    cudaFuncSetAttribute(hmma_gemm<2>, cudaFuncAttributeMaxDynamicSharedMemorySize, GSMEM);
    cudaFuncSetAttribute(hmma_gemm<3>, cudaFuncAttributeMaxDynamicSharedMemorySize, GSMEM);

    // weight prep (tiled transpose to fp16)
    prep_w<<<dim3((3*CH)/32, CH/32), 256>>>(w_qkv, p_wqkv, CH, 3*CH);
    prep_w<<<dim3(CH/32,     CH/32), 256>>>(w_proj, p_wproj, CH, CH);
    prep_w<<<dim3(CFF/32,    CH/32), 256>>>(w1, p_w1, CH, CFF);
    prep_w<<<dim3(CH/32,    CFF/32), 256>>>(w2, p_w2, CFF, CH);

    // 1. LN1 + shift + window partition -> fp16
    ln1_window_kernel<<<NTOK, 128>>>(x, g1, be1, p_xw);

    // 2. QKV GEMM -> fp16 (bias only)
    hmma_gemm<3><<<dim3((3*CH)/128, NTOK/128), 256, GSMEM>>>(
        p_xw, p_wqkv, b_qkv, nullptr, nullptr, p_qkv, CH, 3*CH);

    // 3. windowed attention -> fp16
    attn_kernel<<<NWIN * NHEAD, 128>>>(p_qkv, bias_table, p_att);

    // 4. proj GEMM -> fp16
    hmma_gemm<3><<<dim3(CH/128, NTOK/128), 256, GSMEM>>>(
        p_att, p_wproj, b_proj, nullptr, nullptr, p_proj, CH, CH);

    // 5. window reverse + roll + residual + LN2 (x2 stored fp16)
    res_ln2_kernel<<<NTOK, 128>>>(x, p_proj, g2, be2, p_x2h, p_h2);

    // 6. FFN1 + fast GELU -> fp16
    hmma_gemm<1><<<dim3(CFF/128, NTOK/128), 256, GSMEM>>>(
        p_h2, p_w1, b1, nullptr, nullptr, p_ffn, CH, CFF);

    // 7. FFN2 + residual(fp16) -> fp32 out
    hmma_gemm<2><<<dim3(CH/128, NTOK/128), 256, GSMEM>>>(
        p_ffn, p_w2, b2, p_x2h, out, nullptr, CFF, CH);
}

// round 15
// speedup vs baseline: 1.2418x; 1.0282x over previous
#include <cuda_runtime.h>
#include <cuda_fp16.h>
#include <math.h>
#include <stdint.h>

// ---------------- problem constants ----------------
#define BATCH 16
#define HDIM  56
#define WDIM  56
#define CH    512
#define CFF   2048
#define NHEAD 16
#define DH    32
#define MWIN  7
#define NTOKW 49
#define SHIFT 3
#define NTOK  (BATCH*HDIM*WDIM)                  // 50176
#define NWIN  (BATCH*(HDIM/MWIN)*(WDIM/MWIN))    // 1024

// ---------------- device scratch (allocation-free) ----------------
__device__ half  g_xw  [(size_t)NTOK*CH];
__device__ half  g_qkv [(size_t)NTOK*3*CH];
__device__ half  g_att [(size_t)NTOK*CH];
__device__ half  g_proj[(size_t)NTOK*CH];
__device__ half  g_x2h [(size_t)NTOK*CH];
__device__ half  g_h2  [(size_t)NTOK*CH];
__device__ half  g_ffn [(size_t)NTOK*CFF];
// weights transposed to [N,K] fp16
__device__ half g_wqkv [(size_t)CH*3*CH];
__device__ half g_wproj[(size_t)CH*CH];
__device__ half g_w1   [(size_t)CH*CFF];
__device__ half g_w2   [(size_t)CFF*CH];

// ---------------- PTX helpers ----------------
__device__ __forceinline__ uint32_t smem_u32(const void* p){
    uint32_t a;
    asm("{ .reg .u64 t; cvta.to.shared.u64 t, %1; cvt.u32.u64 %0, t; }" : "=r"(a) : "l"(p));
    return a;
}
#define CP_ASYNC16(dst, src) \
    asm volatile("cp.async.cg.shared.global [%0], [%1], 16;" :: "r"(dst), "l"(src))
#define CP_COMMIT() asm volatile("cp.async.commit_group;" ::: "memory")
#define CP_WAIT(N)  asm volatile("cp.async.wait_group %0;" :: "n"(N) : "memory")

#define LDSM_X4(r, a) \
    asm volatile("ldmatrix.sync.aligned.m8n8.x4.shared.b16 {%0,%1,%2,%3}, [%4];" \
        : "=r"((r)[0]), "=r"((r)[1]), "=r"((r)[2]), "=r"((r)[3]) : "r"(a))

#define MMA_F16(d, a, b0, b1) \
    asm volatile("mma.sync.aligned.m16n8k16.row.col.f32.f16.f16.f32 " \
        "{%0,%1,%2,%3}, {%4,%5,%6,%7}, {%8,%9}, {%0,%1,%2,%3};" \
        : "+f"((d)[0]), "+f"((d)[1]), "+f"((d)[2]), "+f"((d)[3]) \
        : "r"((a)[0]), "r"((a)[1]), "r"((a)[2]), "r"((a)[3]), "r"(b0), "r"(b1))

// fast GELU: tanh form with HW tanh.approx (MUFU)
__device__ __forceinline__ float gelu_fast(float x){
    float u = 0.7978845608028654f * fmaf(0.044715f * x, x * x, x);
    float t;
    asm("tanh.approx.f32 %0, %1;" : "=f"(t) : "f"(u));
    return 0.5f * x * (1.0f + t);
}

// ---------------- fp16 HMMA GEMM, 5-stage ring, paired-stage sync ----------------
// C[M,N] = A @ B^T + bias ; A: [M,K] fp16, B: [N,K] fp16, fp32 accumulate.
// CTA tile 128x128, BK=32, 256 threads, rows padded to 80B (conflict-free
// ldmatrix: bank-quad (5r+c)%8 is a permutation over 8 rows).
// 5 stages x 20KB = 100KB -> 2 CTAs/SM. Two k-blocks per barrier.
// fp16 outputs (EPI 1/3) use an smem-staged coalesced epilogue
// (272B-padded rows: STS conflict-free, stores 256B/row fully coalesced).
// EPI=1: GELU -> fp16. EPI=2: +res(fp16) -> fp32. EPI=3: fp16.
#define TILEB  10240
#define STAGEB 20480
#define GSMEM  (5*STAGEB)
#define EPIROW 272

template<int EPI>
__global__ __launch_bounds__(256, 2) void hmma_gemm(
    const half* __restrict__ Ag, const half* __restrict__ Bg,
    const float* __restrict__ bias, const half* __restrict__ res,
    float* __restrict__ Cf, half* __restrict__ Ch,
    int K, int Nc)
{
    extern __shared__ char smem[];
    const int tid = threadIdx.x;
    const int lane = tid & 31, wid = tid >> 5;
    const int wm = wid & 1, wn = wid >> 1;          // warp tile: 64 x 32

    const half* Ab = Ag + (size_t)blockIdx.y * 128 * K;
    const half* Bb = Bg + (size_t)blockIdx.x * 128 * K;

    const uint32_t sb = smem_u32(smem);
    const int NK = K >> 5;

    float acc[4][4][4];
    #pragma unroll
    for (int a = 0; a < 4; a++)
        #pragma unroll
        for (int b = 0; b < 4; b++)
            #pragma unroll
            for (int c = 0; c < 4; c++) acc[a][b][c] = 0.f;

    const int lr0 = tid >> 2;          // 0..63
    const int lc  = tid & 3;           // 16B chunk 0..3
    auto load_stage = [&](int kb, int s) {
        uint32_t st = sb + (uint32_t)s * STAGEB;
        #pragma unroll
        for (int i = 0; i < 4; i++) {
            const int t = i >> 1;
            int r = (i & 1) * 64 + lr0;
            const half* src = (t ? Bb : Ab) + (size_t)r * K + kb * 32 + lc * 8;
            uint32_t dst = st + (uint32_t)(t * TILEB + r * 80 + lc * 16);
            CP_ASYNC16(dst, src);
        }
        CP_COMMIT();
    };

    auto compute_stage = [&](int s) {
        uint32_t st = sb + (uint32_t)s * STAGEB;
        #pragma unroll
        for (int kk = 0; kk < 2; kk++) {
            const int ch = kk * 2 + (lane >> 4);
            uint32_t bh[2][4];
            #pragma unroll
            for (int np = 0; np < 2; np++) {
                int row = wn * 32 + np * 16 + (lane & 15);
                uint32_t off = (uint32_t)(row * 80 + ch * 16);
                LDSM_X4(bh[np], st + 1u * TILEB + off);
            }
            #pragma unroll
            for (int mt = 0; mt < 4; mt++) {
                int row = wm * 64 + mt * 16 + (lane & 15);
                uint32_t off = (uint32_t)(row * 80 + ch * 16);
                uint32_t ah[4];
                LDSM_X4(ah, st + off);
                #pragma unroll
                for (int nt = 0; nt < 4; nt++) {
                    int np = nt >> 1, se = nt & 1;
                    MMA_F16(acc[mt][nt], ah, bh[np][se], bh[np][se + 2]);
                }
            }
        }
    };

    // prologue: fill 3 stages
    load_stage(0, 0);
    load_stage(1, 1);
    load_stage(2, 2);

    // paired-stage mainloop: 2 k-blocks per barrier, 5-slot ring
    for (int kb = 0; kb < NK; kb += 2) {
        if (kb + 2 < NK) { CP_WAIT(1); }
        else             { CP_WAIT(0); }
        __syncthreads();
        if (kb + 3 < NK) load_stage(kb + 3, (kb + 3) % 5);
        if (kb + 4 < NK) load_stage(kb + 4, (kb + 4) % 5);
        compute_stage(kb % 5);
        compute_stage((kb + 1) % 5);
    }

    // --- epilogue ---
    if (EPI == 1 || EPI == 3) {
        // smem-staged coalesced fp16 output
        __syncthreads();   // pipeline smem now reusable
        #pragma unroll
        for (int mt = 0; mt < 4; mt++) {
            #pragma unroll
            for (int nt = 0; nt < 4; nt++) {
                int cl = wn * 32 + nt * 8 + (lane & 3) * 2;
                float b0 = bias[blockIdx.x * 128 + cl];
                float b1 = bias[blockIdx.x * 128 + cl + 1];
                #pragma unroll
                for (int h = 0; h < 2; h++) {
                    int rl = wm * 64 + mt * 16 + (lane >> 2) + h * 8;
                    float v0 = acc[mt][nt][h * 2]     + b0;
                    float v1 = acc[mt][nt][h * 2 + 1] + b1;
                    if (EPI == 1) { v0 = gelu_fast(v0); v1 = gelu_fast(v1); }
                    *(half2*)(smem + rl * EPIROW + cl * 2) = __floats2half2_rn(v0, v1);
                }
            }
        }
        __syncthreads();
        // coalesced copy: 128 rows x 256B, 16 threads x uint4 per row
        size_t gbase = (size_t)blockIdx.y * 128 * Nc + blockIdx.x * 128;
        #pragma unroll
        for (int it = 0; it < 8; it++) {
            int idx = it * 256 + tid;
            int row = idx >> 4, c16 = idx & 15;
            uint4 v = *(uint4*)(smem + row * EPIROW + c16 * 16);
            *(uint4*)(Ch + gbase + (size_t)row * Nc + c16 * 8) = v;
        }
    } else {
        // direct fp32 path (float2 per 4-lane group = full sectors)
        int row0 = blockIdx.y * 128 + wm * 64;
        int col0 = blockIdx.x * 128 + wn * 32;
        #pragma unroll
        for (int mt = 0; mt < 4; mt++) {
            #pragma unroll
            for (int nt = 0; nt < 4; nt++) {
                int c = col0 + nt * 8 + (lane & 3) * 2;
                float b0 = bias[c], b1 = bias[c + 1];
                #pragma unroll
                for (int h = 0; h < 2; h++) {
                    int r = row0 + mt * 16 + (lane >> 2) + h * 8;
                    float v0 = acc[mt][nt][h * 2]     + b0;
                    float v1 = acc[mt][nt][h * 2 + 1] + b1;
                    size_t o = (size_t)r * Nc + c;
                    if (EPI == 2) {
                        float2 rv = __half22float2(*(const half2*)(res + o));
                        v0 += rv.x; v1 += rv.y;
                    }
                    *(float2*)(Cf + o) = make_float2(v0, v1);
                }
            }
        }
    }
}

// ---------------- weight prep: [K,N] fp32 -> [N,K] fp16 (tiled transpose) ----------------
__global__ __launch_bounds__(256) void prep_w(
    const float* __restrict__ W, half* __restrict__ Wh, int K, int N)
{
    __shared__ float tile[32][33];
    int nb = blockIdx.x * 32, kb = blockIdx.y * 32;
    int tx = threadIdx.x & 31, ty = threadIdx.x >> 5;  // 32 x 8
    #pragma unroll
    for (int j = 0; j < 32; j += 8)
        tile[ty + j][tx] = W[(size_t)(kb + ty + j) * N + nb + tx];
    __syncthreads();
    #pragma unroll
    for (int j = 0; j < 32; j += 8)
        Wh[(size_t)(nb + ty + j) * K + kb + tx] = __float2half_rn(tile[tx][ty + j]);
}

// ---------------- block reduction (128 threads, 4 warps) ----------------
__device__ __forceinline__ void block_reduce_128(float& s, float& sq) {
    __shared__ float sh[8];
    int lane = threadIdx.x & 31, wid = threadIdx.x >> 5;
    #pragma unroll
    for (int o = 16; o > 0; o >>= 1) {
        s  += __shfl_down_sync(0xffffffffu, s,  o);
        sq += __shfl_down_sync(0xffffffffu, sq, o);
    }
    if (lane == 0) { sh[wid] = s; sh[wid + 4] = sq; }
    __syncthreads();
    if (threadIdx.x == 0) {
        float S = 0.f, SQ = 0.f;
        #pragma unroll
        for (int i = 0; i < 4; i++) { S += sh[i]; SQ += sh[i + 4]; }
        sh[0] = S; sh[4] = SQ;
    }
    __syncthreads();
    s = sh[0]; sq = sh[4];
}

// ---------------- LN1 + shift + window partition -> fp16 (float4, 128 thr) ----------------
__global__ __launch_bounds__(128) void ln1_window_kernel(
    const float* __restrict__ x, const float* __restrict__ g, const float* __restrict__ b,
    half* __restrict__ out)
{
    int t = blockIdx.x;
    int w = t / NTOKW, tok = t - w * NTOKW;
    int bb = w >> 6, wrem = w & 63;
    int wi = wrem >> 3, wj = wrem & 7;
    int ti = tok / MWIN, tj = tok - ti * MWIN;
    int r = (wi * MWIN + ti + SHIFT) % HDIM;
    int c = (wj * MWIN + tj + SHIFT) % WDIM;
    const float4* src = (const float4*)(x + ((size_t)bb * (HDIM * WDIM) + r * WDIM + c) * CH);
    int tid = threadIdx.x;
    float4 v = src[tid];
    float s  = v.x + v.y + v.z + v.w;
    float sq = v.x*v.x + v.y*v.y + v.z*v.z + v.w*v.w;
    block_reduce_128(s, sq);
    float mu  = s * (1.0f / CH);
    float var = sq * (1.0f / CH) - mu * mu;
    float inv = rsqrtf(var + 1e-5f);
    float4 gg = ((const float4*)g)[tid];
    float4 bb4 = ((const float4*)b)[tid];
    half2 h01 = __floats2half2_rn((v.x - mu) * inv * gg.x + bb4.x,
                                  (v.y - mu) * inv * gg.y + bb4.y);
    half2 h23 = __floats2half2_rn((v.z - mu) * inv * gg.z + bb4.z,
                                  (v.w - mu) * inv * gg.w + bb4.w);
    half2* dst = (half2*)(out + (size_t)t * CH);
    dst[tid * 2]     = h01;
    dst[tid * 2 + 1] = h23;
}

// ---------------- windowed attention: register-tiled, fp16 half2 smem ----------------
__global__ __launch_bounds__(128) void attn_kernel(
    const half* __restrict__ qkv, const float* __restrict__ bias_table,
    half* __restrict__ out)
{
    int win  = blockIdx.x >> 4;
    int head = blockIdx.x & 15;
    __shared__ half2 qh[52][17], kh[52][17], vh[52][17];
    __shared__ float sc[52][57];
    __shared__ float sbias[(2*MWIN-1)*(2*MWIN-1)];   // 169
    int tid = threadIdx.x;
    const float scale = 0.17677669529663687f;
    size_t base = (size_t)win * NTOKW * (3 * CH) + head * DH;

    for (int i = tid; i < (2*MWIN-1)*(2*MWIN-1); i += 128)
        sbias[i] = bias_table[i * NHEAD + head];

    for (int i = tid; i < NTOKW * 16; i += 128) {
        int n = i >> 4, c = i & 15;
        size_t rb = base + (size_t)n * (3 * CH) + c * 2;
        qh[n][c] = *(const half2*)(qkv + rb);
        kh[n][c] = *(const half2*)(qkv + rb + CH);
        vh[n][c] = *(const half2*)(qkv + rb + 2 * CH);
    }
    __syncthreads();

    if (tid < 91) {
        int tr = tid / 7, tc = tid - tr * 7;
        int n0 = tr * 4, m0 = tc * 7;
        float acc[4][7];
        #pragma unroll
        for (int i = 0; i < 4; i++)
            #pragma unroll
            for (int j = 0; j < 7; j++) acc[i][j] = 0.f;
        #pragma unroll 4
        for (int dp = 0; dp < 16; dp++) {
            float2 qr[4], kr[7];
            #pragma unroll
            for (int i = 0; i < 4; i++) qr[i] = __half22float2(qh[n0 + i][dp]);
            #pragma unroll
            for (int j = 0; j < 7; j++) kr[j] = __half22float2(kh[m0 + j][dp]);
            #pragma unroll
            for (int i = 0; i < 4; i++)
                #pragma unroll
                for (int j = 0; j < 7; j++) {
                    acc[i][j] = fmaf(qr[i].x, kr[j].x, acc[i][j]);
                    acc[i][j] = fmaf(qr[i].y, kr[j].y, acc[i][j]);
                }
        }
        #pragma unroll
        for (int i = 0; i < 4; i++) {
            int n = n0 + i;
            int nn = n < NTOKW ? n : NTOKW - 1;
            int nr = nn / MWIN, ncm = nn - nr * MWIN;
            #pragma unroll
            for (int j = 0; j < 7; j++) {
                int m = m0 + j;
                int mr = m / MWIN, mc = m - mr * MWIN;
                int dr = nr - mr + (MWIN - 1), dc = ncm - mc + (MWIN - 1);
                sc[n][m] = acc[i][j] * scale + sbias[dr * (2 * MWIN - 1) + dc];
            }
        }
    }
    __syncthreads();

    if (tid < NTOKW) {
        float* row = sc[tid];
        float mx = -1e30f;
        #pragma unroll 7
        for (int m = 0; m < NTOKW; m++) mx = fmaxf(mx, row[m]);
        float sum = 0.f;
        #pragma unroll 7
        for (int m = 0; m < NTOKW; m++) { float e = __expf(row[m] - mx); row[m] = e; sum += e; }
        float inv = 1.0f / sum;
        #pragma unroll 7
        for (int m = 0; m < NTOKW; m++) row[m] *= inv;
    }
    __syncthreads();

    if (tid < 104) {
        int tr = tid >> 3, dc = tid & 7;
        int n0 = tr * 4, d0 = dc * 2;
        float acc[4][4];
        #pragma unroll
        for (int i = 0; i < 4; i++)
            #pragma unroll
            for (int k = 0; k < 4; k++) acc[i][k] = 0.f;
        #pragma unroll 7
        for (int m = 0; m < NTOKW; m++) {
            float2 v0 = __half22float2(vh[m][d0]);
            float2 v1 = __half22float2(vh[m][d0 + 1]);
            float pp[4];
            #pragma unroll
            for (int i = 0; i < 4; i++) pp[i] = sc[n0 + i][m];
            #pragma unroll
            for (int i = 0; i < 4; i++) {
                acc[i][0] = fmaf(pp[i], v0.x, acc[i][0]);
                acc[i][1] = fmaf(pp[i], v0.y, acc[i][1]);
                acc[i][2] = fmaf(pp[i], v1.x, acc[i][2]);
                acc[i][3] = fmaf(pp[i], v1.y, acc[i][3]);
            }
        }
        #pragma unroll
        for (int i = 0; i < 4; i++) {
            int n = n0 + i;
            if (n < NTOKW) {
                size_t o = ((size_t)win * NTOKW + n) * CH + head * DH + d0 * 2;
                *(half2*)(out + o)     = __floats2half2_rn(acc[i][0], acc[i][1]);
                *(half2*)(out + o + 2) = __floats2half2_rn(acc[i][2], acc[i][3]);
            }
        }
    }
}

// ---------------- window reverse + roll + residual + LN2 (float4, 128 thr) ----------------
__global__ __launch_bounds__(128) void res_ln2_kernel(
    const float* __restrict__ x, const half* __restrict__ proj,
    const float* __restrict__ g, const float* __restrict__ b,
    half* __restrict__ x2, half* __restrict__ h2)
{
    int t = blockIdx.x;
    int bb = t / (HDIM * WDIM);
    int rc = t - bb * (HDIM * WDIM);
    int r = rc / WDIM, c = rc - r * WDIM;
    int rs = (r - SHIFT + HDIM) % HDIM;
    int cs = (c - SHIFT + WDIM) % WDIM;
    int w   = bb * 64 + (rs / MWIN) * 8 + (cs / MWIN);
    int tok = (rs % MWIN) * MWIN + (cs % MWIN);
    const half2* ps = (const half2*)(proj + ((size_t)w * NTOKW + tok) * CH);
    const float4* xs = (const float4*)(x + (size_t)t * CH);
    int tid = threadIdx.x;
    float4 xv = xs[tid];
    float2 p01 = __half22float2(ps[tid * 2]);
    float2 p23 = __half22float2(ps[tid * 2 + 1]);
    float v0 = xv.x + p01.x, v1 = xv.y + p01.y;
    float v2 = xv.z + p23.x, v3 = xv.w + p23.y;
    half2* x2p = (half2*)(x2 + (size_t)t * CH);
    x2p[tid * 2]     = __floats2half2_rn(v0, v1);
    x2p[tid * 2 + 1] = __floats2half2_rn(v2, v3);
    float s  = v0 + v1 + v2 + v3;
    float sq = v0*v0 + v1*v1 + v2*v2 + v3*v3;
    block_reduce_128(s, sq);
    float mu  = s * (1.0f / CH);
    float var = sq * (1.0f / CH) - mu * mu;
    float inv = rsqrtf(var + 1e-5f);
    float4 gg = ((const float4*)g)[tid];
    float4 bb4 = ((const float4*)b)[tid];
    half2* h2p = (half2*)(h2 + (size_t)t * CH);
    h2p[tid * 2]     = __floats2half2_rn((v0 - mu) * inv * gg.x + bb4.x,
                                         (v1 - mu) * inv * gg.y + bb4.y);
    h2p[tid * 2 + 1] = __floats2half2_rn((v2 - mu) * inv * gg.z + bb4.z,
                                         (v3 - mu) * inv * gg.w + bb4.w);
}

// ---------------- launcher ----------------
extern "C" void kernel_launch(void* const* d_in, const int* in_sizes, int n_in,
                              void* d_out, int out_size)
{
    const float* x          = (const float*)d_in[0];
    const float* w_qkv      = (const float*)d_in[3];
    const float* b_qkv      = (const float*)d_in[4];
    const float* w_proj     = (const float*)d_in[5];
    const float* b_proj     = (const float*)d_in[6];
    const float* bias_table = (const float*)d_in[7];
    const float* g1         = (const float*)d_in[8];
    const float* be1        = (const float*)d_in[9];
    const float* g2         = (const float*)d_in[10];
    const float* be2        = (const float*)d_in[11];
    const float* w1         = (const float*)d_in[12];
    const float* b1         = (const float*)d_in[13];
    const float* w2         = (const float*)d_in[14];
    const float* b2         = (const float*)d_in[15];
    float* out = (float*)d_out;

    half *p_xw, *p_qkv, *p_att, *p_proj, *p_x2h, *p_h2, *p_ffn;
    half *p_wqkv, *p_wproj, *p_w1, *p_w2;
    cudaGetSymbolAddress((void**)&p_xw,   g_xw);
    cudaGetSymbolAddress((void**)&p_qkv,  g_qkv);
    cudaGetSymbolAddress((void**)&p_att,  g_att);
    cudaGetSymbolAddress((void**)&p_proj, g_proj);
    cudaGetSymbolAddress((void**)&p_x2h,  g_x2h);
    cudaGetSymbolAddress((void**)&p_h2,   g_h2);
    cudaGetSymbolAddress((void**)&p_ffn,  g_ffn);
    cudaGetSymbolAddress((void**)&p_wqkv,  g_wqkv);
    cudaGetSymbolAddress((void**)&p_wproj, g_wproj);
    cudaGetSymbolAddress((void**)&p_w1,    g_w1);
    cudaGetSymbolAddress((void**)&p_w2,    g_w2);

    cudaFuncSetAttribute(hmma_gemm<1>, cudaFuncAttributeMaxDynamicSharedMemorySize, GSMEM);
    cudaFuncSetAttribute(hmma_gemm<2>, cudaFuncAttributeMaxDynamicSharedMemorySize, GSMEM);
    cudaFuncSetAttribute(hmma_gemm<3>, cudaFuncAttributeMaxDynamicSharedMemorySize, GSMEM);

    // weight prep (tiled transpose to fp16)
    prep_w<<<dim3((3*CH)/32, CH/32), 256>>>(w_qkv, p_wqkv, CH, 3*CH);
    prep_w<<<dim3(CH/32,     CH/32), 256>>>(w_proj, p_wproj, CH, CH);
    prep_w<<<dim3(CFF/32,    CH/32), 256>>>(w1, p_w1, CH, CFF);
    prep_w<<<dim3(CH/32,    CFF/32), 256>>>(w2, p_w2, CFF, CH);

    // 1. LN1 + shift + window partition -> fp16
    ln1_window_kernel<<<NTOK, 128>>>(x, g1, be1, p_xw);

    // 2. QKV GEMM -> fp16 (bias only)
    hmma_gemm<3><<<dim3((3*CH)/128, NTOK/128), 256, GSMEM>>>(
        p_xw, p_wqkv, b_qkv, nullptr, nullptr, p_qkv, CH, 3*CH);

    // 3. windowed attention -> fp16
    attn_kernel<<<NWIN * NHEAD, 128>>>(p_qkv, bias_table, p_att);

    // 4. proj GEMM -> fp16
    hmma_gemm<3><<<dim3(CH/128, NTOK/128), 256, GSMEM>>>(
        p_att, p_wproj, b_proj, nullptr, nullptr, p_proj, CH, CH);

    // 5. window reverse + roll + residual + LN2 (x2 stored fp16)
    res_ln2_kernel<<<NTOK, 128>>>(x, p_proj, g2, be2, p_x2h, p_h2);

    // 6. FFN1 + fast GELU -> fp16
    hmma_gemm<1><<<dim3(CFF/128, NTOK/128), 256, GSMEM>>>(
        p_h2, p_w1, b1, nullptr, nullptr, p_ffn, CH, CFF);

    // 7. FFN2 + residual(fp16) -> fp32 out
    hmma_gemm<2><<<dim3(CH/128, NTOK/128), 256, GSMEM>>>(
        p_ffn, p_w2, b2, p_x2h, out, nullptr, CFF, CH);
}

// round 16
// speedup vs baseline: 1.2677x; 1.0208x over previous
#include <cuda_runtime.h>
#include <cuda_fp16.h>
#include <math.h>
#include <stdint.h>

// ---------------- problem constants ----------------
#define BATCH 16
#define HDIM  56
#define WDIM  56
#define CH    512
#define CFF   2048
#define NHEAD 16
#define DH    32
#define MWIN  7
#define NTOKW 49
#define SHIFT 3
#define NTOK  (BATCH*HDIM*WDIM)                  // 50176
#define NWIN  (BATCH*(HDIM/MWIN)*(WDIM/MWIN))    // 1024

// ---------------- device scratch (allocation-free) ----------------
__device__ half  g_xw  [(size_t)NTOK*CH];
__device__ half  g_qkv [(size_t)NTOK*3*CH];
__device__ half  g_att [(size_t)NTOK*CH];
__device__ half  g_proj[(size_t)NTOK*CH];
__device__ half  g_x2h [(size_t)NTOK*CH];
__device__ half  g_h2  [(size_t)NTOK*CH];
__device__ half  g_ffn [(size_t)NTOK*CFF];
// weights transposed to [N,K] fp16
__device__ half g_wqkv [(size_t)CH*3*CH];
__device__ half g_wproj[(size_t)CH*CH];
__device__ half g_w1   [(size_t)CH*CFF];
__device__ half g_w2   [(size_t)CFF*CH];

// ---------------- PTX helpers ----------------
__device__ __forceinline__ uint32_t smem_u32(const void* p){
    uint32_t a;
    asm("{ .reg .u64 t; cvta.to.shared.u64 t, %1; cvt.u32.u64 %0, t; }" : "=r"(a) : "l"(p));
    return a;
}
#define CP_ASYNC16(dst, src) \
    asm volatile("cp.async.cg.shared.global [%0], [%1], 16;" :: "r"(dst), "l"(src))
#define CP_COMMIT() asm volatile("cp.async.commit_group;" ::: "memory")
#define CP_WAIT(N)  asm volatile("cp.async.wait_group %0;" :: "n"(N) : "memory")

#define LDSM_X4(r, a) \
    asm volatile("ldmatrix.sync.aligned.m8n8.x4.shared.b16 {%0,%1,%2,%3}, [%4];" \
        : "=r"((r)[0]), "=r"((r)[1]), "=r"((r)[2]), "=r"((r)[3]) : "r"(a))

#define MMA_F16(d, a, b0, b1) \
    asm volatile("mma.sync.aligned.m16n8k16.row.col.f32.f16.f16.f32 " \
        "{%0,%1,%2,%3}, {%4,%5,%6,%7}, {%8,%9}, {%0,%1,%2,%3};" \
        : "+f"((d)[0]), "+f"((d)[1]), "+f"((d)[2]), "+f"((d)[3]) \
        : "r"((a)[0]), "r"((a)[1]), "r"((a)[2]), "r"((a)[3]), "r"(b0), "r"(b1))

// fast GELU: tanh form with HW tanh.approx (MUFU)
__device__ __forceinline__ float gelu_fast(float x){
    float u = 0.7978845608028654f * fmaf(0.044715f * x, x * x, x);
    float t;
    asm("tanh.approx.f32 %0, %1;" : "=f"(t) : "f"(u));
    return 0.5f * x * (1.0f + t);
}

// ---------------- fp16 HMMA GEMM: 4 warps x 64x64 tiles, 3-stage ring ----------------
// C[M,N] = A @ B^T + bias ; A: [M,K] fp16, B: [N,K] fp16, fp32 accumulate.
// CTA tile 128x128, 128 threads (4 warps, 2x2 of 64x64). BK=32, rows padded
// to 80B (conflict-free ldmatrix: bank-quad (5r+c)%8 is a permutation).
// 3 stages x 20KB = 60KB -> 3 CTAs/SM (12 warps). MMA:ldsm ratio 4 (vs 2.67).
// fp16 outputs (EPI 1/3): smem-staged coalesced epilogue (272B rows).
// EPI=1: GELU -> fp16. EPI=2: +res(fp16) -> fp32. EPI=3: fp16.
#define TILEB  10240
#define STAGEB 20480
#define GSMEM  (3*STAGEB)
#define EPIROW 272

template<int EPI>
__global__ __launch_bounds__(128, 3) void hmma_gemm(
    const half* __restrict__ Ag, const half* __restrict__ Bg,
    const float* __restrict__ bias, const half* __restrict__ res,
    float* __restrict__ Cf, half* __restrict__ Ch,
    int K, int Nc)
{
    extern __shared__ char smem[];
    const int tid = threadIdx.x;
    const int lane = tid & 31, wid = tid >> 5;
    const int wm = wid & 1, wn = wid >> 1;          // 2x2 warps, tile 64 x 64

    const half* Ab = Ag + (size_t)blockIdx.y * 128 * K;
    const half* Bb = Bg + (size_t)blockIdx.x * 128 * K;

    const uint32_t sb = smem_u32(smem);
    const int NK = K >> 5;

    float acc[4][8][4];
    #pragma unroll
    for (int a = 0; a < 4; a++)
        #pragma unroll
        for (int b = 0; b < 8; b++)
            #pragma unroll
            for (int c = 0; c < 4; c++) acc[a][b][c] = 0.f;

    const int lr0 = tid >> 2;          // 0..31
    const int lc  = tid & 3;           // 16B chunk 0..3
    // 128 threads load 128 rows A + 128 rows B per stage: 4 rows-of-32 each
    auto load_stage = [&](int kb, int s) {
        uint32_t st = sb + (uint32_t)s * STAGEB;
        #pragma unroll
        for (int i = 0; i < 8; i++) {
            const int t = i >> 2;              // 0=A, 1=B
            int r = (i & 3) * 32 + lr0;
            const half* src = (t ? Bb : Ab) + (size_t)r * K + kb * 32 + lc * 8;
            uint32_t dst = st + (uint32_t)(t * TILEB + r * 80 + lc * 16);
            CP_ASYNC16(dst, src);
        }
        CP_COMMIT();
    };

    auto compute_stage = [&](int s) {
        uint32_t st = sb + (uint32_t)s * STAGEB;
        #pragma unroll
        for (int kk = 0; kk < 2; kk++) {
            const int ch = kk * 2 + (lane >> 4);
            uint32_t bh[4][4];
            #pragma unroll
            for (int np = 0; np < 4; np++) {
                int row = wn * 64 + np * 16 + (lane & 15);
                uint32_t off = (uint32_t)(row * 80 + ch * 16);
                LDSM_X4(bh[np], st + 1u * TILEB + off);
            }
            #pragma unroll
            for (int mt = 0; mt < 4; mt++) {
                int row = wm * 64 + mt * 16 + (lane & 15);
                uint32_t off = (uint32_t)(row * 80 + ch * 16);
                uint32_t ah[4];
                LDSM_X4(ah, st + off);
                #pragma unroll
                for (int nt = 0; nt < 8; nt++) {
                    int np = nt >> 1, se = nt & 1;
                    MMA_F16(acc[mt][nt], ah, bh[np][se], bh[np][se + 2]);
                }
            }
        }
    };

    // prologue: fill 2 stages
    load_stage(0, 0);
    if (NK > 1) load_stage(1, 1);

    // 3-slot ring, one k-block per barrier (128-thread barrier is cheap)
    int s_cur = 0, s_next = 2;
    for (int kb = 0; kb < NK; kb++) {
        if (kb + 1 < NK) { CP_WAIT(1); }
        else             { CP_WAIT(0); }
        __syncthreads();
        if (kb + 2 < NK) {
            load_stage(kb + 2, s_next);
            s_next = s_next == 2 ? 0 : s_next + 1;
        }
        compute_stage(s_cur);
        s_cur = s_cur == 2 ? 0 : s_cur + 1;
    }

    // --- epilogue ---
    if (EPI == 1 || EPI == 3) {
        __syncthreads();
        #pragma unroll
        for (int mt = 0; mt < 4; mt++) {
            #pragma unroll
            for (int nt = 0; nt < 8; nt++) {
                int cl = wn * 64 + nt * 8 + (lane & 3) * 2;
                float b0 = bias[blockIdx.x * 128 + cl];
                float b1 = bias[blockIdx.x * 128 + cl + 1];
                #pragma unroll
                for (int h = 0; h < 2; h++) {
                    int rl = wm * 64 + mt * 16 + (lane >> 2) + h * 8;
                    float v0 = acc[mt][nt][h * 2]     + b0;
                    float v1 = acc[mt][nt][h * 2 + 1] + b1;
                    if (EPI == 1) { v0 = gelu_fast(v0); v1 = gelu_fast(v1); }
                    *(half2*)(smem + rl * EPIROW + cl * 2) = __floats2half2_rn(v0, v1);
                }
            }
        }
        __syncthreads();
        size_t gbase = (size_t)blockIdx.y * 128 * Nc + blockIdx.x * 128;
        #pragma unroll
        for (int it = 0; it < 16; it++) {
            int idx = it * 128 + tid;
            int row = idx >> 4, c16 = idx & 15;
            uint4 v = *(uint4*)(smem + row * EPIROW + c16 * 16);
            *(uint4*)(Ch + gbase + (size_t)row * Nc + c16 * 8) = v;
        }
    } else {
        int row0 = blockIdx.y * 128 + wm * 64;
        int col0 = blockIdx.x * 128 + wn * 64;
        #pragma unroll
        for (int mt = 0; mt < 4; mt++) {
            #pragma unroll
            for (int nt = 0; nt < 8; nt++) {
                int c = col0 + nt * 8 + (lane & 3) * 2;
                float b0 = bias[c], b1 = bias[c + 1];
                #pragma unroll
                for (int h = 0; h < 2; h++) {
                    int r = row0 + mt * 16 + (lane >> 2) + h * 8;
                    float v0 = acc[mt][nt][h * 2]     + b0;
                    float v1 = acc[mt][nt][h * 2 + 1] + b1;
                    size_t o = (size_t)r * Nc + c;
                    if (EPI == 2) {
                        float2 rv = __half22float2(*(const half2*)(res + o));
                        v0 += rv.x; v1 += rv.y;
                    }
                    *(float2*)(Cf + o) = make_float2(v0, v1);
                }
            }
        }
    }
}

// ---------------- weight prep: [K,N] fp32 -> [N,K] fp16 (tiled transpose) ----------------
__global__ __launch_bounds__(256) void prep_w(
    const float* __restrict__ W, half* __restrict__ Wh, int K, int N)
{
    __shared__ float tile[32][33];
    int nb = blockIdx.x * 32, kb = blockIdx.y * 32;
    int tx = threadIdx.x & 31, ty = threadIdx.x >> 5;  // 32 x 8
    #pragma unroll
    for (int j = 0; j < 32; j += 8)
        tile[ty + j][tx] = W[(size_t)(kb + ty + j) * N + nb + tx];
    __syncthreads();
    #pragma unroll
    for (int j = 0; j < 32; j += 8)
        Wh[(size_t)(nb + ty + j) * K + kb + tx] = __float2half_rn(tile[tx][ty + j]);
}

// ---------------- block reduction (128 threads, 4 warps) ----------------
__device__ __forceinline__ void block_reduce_128(float& s, float& sq) {
    __shared__ float sh[8];
    int lane = threadIdx.x & 31, wid = threadIdx.x >> 5;
    #pragma unroll
    for (int o = 16; o > 0; o >>= 1) {
        s  += __shfl_down_sync(0xffffffffu, s,  o);
        sq += __shfl_down_sync(0xffffffffu, sq, o);
    }
    if (lane == 0) { sh[wid] = s; sh[wid + 4] = sq; }
    __syncthreads();
    if (threadIdx.x == 0) {
        float S = 0.f, SQ = 0.f;
        #pragma unroll
        for (int i = 0; i < 4; i++) { S += sh[i]; SQ += sh[i + 4]; }
        sh[0] = S; sh[4] = SQ;
    }
    __syncthreads();
    s = sh[0]; sq = sh[4];
}

// ---------------- LN1 + shift + window partition -> fp16 (float4, 128 thr) ----------------
__global__ __launch_bounds__(128) void ln1_window_kernel(
    const float* __restrict__ x, const float* __restrict__ g, const float* __restrict__ b,
    half* __restrict__ out)
{
    int t = blockIdx.x;
    int w = t / NTOKW, tok = t - w * NTOKW;
    int bb = w >> 6, wrem = w & 63;
    int wi = wrem >> 3, wj = wrem & 7;
    int ti = tok / MWIN, tj = tok - ti * MWIN;
    int r = (wi * MWIN + ti + SHIFT) % HDIM;
    int c = (wj * MWIN + tj + SHIFT) % WDIM;
    const float4* src = (const float4*)(x + ((size_t)bb * (HDIM * WDIM) + r * WDIM + c) * CH);
    int tid = threadIdx.x;
    float4 v = src[tid];
    float s  = v.x + v.y + v.z + v.w;
    float sq = v.x*v.x + v.y*v.y + v.z*v.z + v.w*v.w;
    block_reduce_128(s, sq);
    float mu  = s * (1.0f / CH);
    float var = sq * (1.0f / CH) - mu * mu;
    float inv = rsqrtf(var + 1e-5f);
    float4 gg = ((const float4*)g)[tid];
    float4 bb4 = ((const float4*)b)[tid];
    half2 h01 = __floats2half2_rn((v.x - mu) * inv * gg.x + bb4.x,
                                  (v.y - mu) * inv * gg.y + bb4.y);
    half2 h23 = __floats2half2_rn((v.z - mu) * inv * gg.z + bb4.z,
                                  (v.w - mu) * inv * gg.w + bb4.w);
    half2* dst = (half2*)(out + (size_t)t * CH);
    dst[tid * 2]     = h01;
    dst[tid * 2 + 1] = h23;
}

// ---------------- windowed attention: register-tiled, fp16 half2 smem ----------------
__global__ __launch_bounds__(128) void attn_kernel(
    const half* __restrict__ qkv, const float* __restrict__ bias_table,
    half* __restrict__ out)
{
    int win  = blockIdx.x >> 4;
    int head = blockIdx.x & 15;
    __shared__ half2 qh[52][17], kh[52][17], vh[52][17];
    __shared__ float sc[52][57];
    __shared__ float sbias[(2*MWIN-1)*(2*MWIN-1)];   // 169
    int tid = threadIdx.x;
    const float scale = 0.17677669529663687f;
    size_t base = (size_t)win * NTOKW * (3 * CH) + head * DH;

    for (int i = tid; i < (2*MWIN-1)*(2*MWIN-1); i += 128)
        sbias[i] = bias_table[i * NHEAD + head];

    for (int i = tid; i < NTOKW * 16; i += 128) {
        int n = i >> 4, c = i & 15;
        size_t rb = base + (size_t)n * (3 * CH) + c * 2;
        qh[n][c] = *(const half2*)(qkv + rb);
        kh[n][c] = *(const half2*)(qkv + rb + CH);
        vh[n][c] = *(const half2*)(qkv + rb + 2 * CH);
    }
    __syncthreads();

    if (tid < 91) {
        int tr = tid / 7, tc = tid - tr * 7;
        int n0 = tr * 4, m0 = tc * 7;
        float acc[4][7];
        #pragma unroll
        for (int i = 0; i < 4; i++)
            #pragma unroll
            for (int j = 0; j < 7; j++) acc[i][j] = 0.f;
        #pragma unroll 4
        for (int dp = 0; dp < 16; dp++) {
            float2 qr[4], kr[7];
            #pragma unroll
            for (int i = 0; i < 4; i++) qr[i] = __half22float2(qh[n0 + i][dp]);
            #pragma unroll
            for (int j = 0; j < 7; j++) kr[j] = __half22float2(kh[m0 + j][dp]);
            #pragma unroll
            for (int i = 0; i < 4; i++)
                #pragma unroll
                for (int j = 0; j < 7; j++) {
                    acc[i][j] = fmaf(qr[i].x, kr[j].x, acc[i][j]);
                    acc[i][j] = fmaf(qr[i].y, kr[j].y, acc[i][j]);
                }
        }
        #pragma unroll
        for (int i = 0; i < 4; i++) {
            int n = n0 + i;
            int nn = n < NTOKW ? n : NTOKW - 1;
            int nr = nn / MWIN, ncm = nn - nr * MWIN;
            #pragma unroll
            for (int j = 0; j < 7; j++) {
                int m = m0 + j;
                int mr = m / MWIN, mc = m - mr * MWIN;
                int dr = nr - mr + (MWIN - 1), dc = ncm - mc + (MWIN - 1);
                sc[n][m] = acc[i][j] * scale + sbias[dr * (2 * MWIN - 1) + dc];
            }
        }
    }
    __syncthreads();

    if (tid < NTOKW) {
        float* row = sc[tid];
        float mx = -1e30f;
        #pragma unroll 7
        for (int m = 0; m < NTOKW; m++) mx = fmaxf(mx, row[m]);
        float sum = 0.f;
        #pragma unroll 7
        for (int m = 0; m < NTOKW; m++) { float e = __expf(row[m] - mx); row[m] = e; sum += e; }
        float inv = 1.0f / sum;
        #pragma unroll 7
        for (int m = 0; m < NTOKW; m++) row[m] *= inv;
    }
    __syncthreads();

    if (tid < 104) {
        int tr = tid >> 3, dc = tid & 7;
        int n0 = tr * 4, d0 = dc * 2;
        float acc[4][4];
        #pragma unroll
        for (int i = 0; i < 4; i++)
            #pragma unroll
            for (int k = 0; k < 4; k++) acc[i][k] = 0.f;
        #pragma unroll 7
        for (int m = 0; m < NTOKW; m++) {
            float2 v0 = __half22float2(vh[m][d0]);
            float2 v1 = __half22float2(vh[m][d0 + 1]);
            float pp[4];
            #pragma unroll
            for (int i = 0; i < 4; i++) pp[i] = sc[n0 + i][m];
            #pragma unroll
            for (int i = 0; i < 4; i++) {
                acc[i][0] = fmaf(pp[i], v0.x, acc[i][0]);
                acc[i][1] = fmaf(pp[i], v0.y, acc[i][1]);
                acc[i][2] = fmaf(pp[i], v1.x, acc[i][2]);
                acc[i][3] = fmaf(pp[i], v1.y, acc[i][3]);
            }
        }
        #pragma unroll
        for (int i = 0; i < 4; i++) {
            int n = n0 + i;
            if (n < NTOKW) {
                size_t o = ((size_t)win * NTOKW + n) * CH + head * DH + d0 * 2;
                *(half2*)(out + o)     = __floats2half2_rn(acc[i][0], acc[i][1]);
                *(half2*)(out + o + 2) = __floats2half2_rn(acc[i][2], acc[i][3]);
            }
        }
    }
}

// ---------------- window reverse + roll + residual + LN2 (float4, 128 thr) ----------------
__global__ __launch_bounds__(128) void res_ln2_kernel(
    const float* __restrict__ x, const half* __restrict__ proj,
    const float* __restrict__ g, const float* __restrict__ b,
    half* __restrict__ x2, half* __restrict__ h2)
{
    int t = blockIdx.x;
    int bb = t / (HDIM * WDIM);
    int rc = t - bb * (HDIM * WDIM);
    int r = rc / WDIM, c = rc - r * WDIM;
    int rs = (r - SHIFT + HDIM) % HDIM;
    int cs = (c - SHIFT + WDIM) % WDIM;
    int w   = bb * 64 + (rs / MWIN) * 8 + (cs / MWIN);
    int tok = (rs % MWIN) * MWIN + (cs % MWIN);
    const half2* ps = (const half2*)(proj + ((size_t)w * NTOKW + tok) * CH);
    const float4* xs = (const float4*)(x + (size_t)t * CH);
    int tid = threadIdx.x;
    float4 xv = xs[tid];
    float2 p01 = __half22float2(ps[tid * 2]);
    float2 p23 = __half22float2(ps[tid * 2 + 1]);
    float v0 = xv.x + p01.x, v1 = xv.y + p01.y;
    float v2 = xv.z + p23.x, v3 = xv.w + p23.y;
    half2* x2p = (half2*)(x2 + (size_t)t * CH);
    x2p[tid * 2]     = __floats2half2_rn(v0, v1);
    x2p[tid * 2 + 1] = __floats2half2_rn(v2, v3);
    float s  = v0 + v1 + v2 + v3;
    float sq = v0*v0 + v1*v1 + v2*v2 + v3*v3;
    block_reduce_128(s, sq);
    float mu  = s * (1.0f / CH);
    float var = sq * (1.0f / CH) - mu * mu;
    float inv = rsqrtf(var + 1e-5f);
    float4 gg = ((const float4*)g)[tid];
    float4 bb4 = ((const float4*)b)[tid];
    half2* h2p = (half2*)(h2 + (size_t)t * CH);
    h2p[tid * 2]     = __floats2half2_rn((v0 - mu) * inv * gg.x + bb4.x,
                                         (v1 - mu) * inv * gg.y + bb4.y);
    h2p[tid * 2 + 1] = __floats2half2_rn((v2 - mu) * inv * gg.z + bb4.z,
                                         (v3 - mu) * inv * gg.w + bb4.w);
}

// ---------------- launcher ----------------
extern "C" void kernel_launch(void* const* d_in, const int* in_sizes, int n_in,
                              void* d_out, int out_size)
{
    const float* x          = (const float*)d_in[0];
    const float* w_qkv      = (const float*)d_in[3];
    const float* b_qkv      = (const float*)d_in[4];
    const float* w_proj     = (const float*)d_in[5];
    const float* b_proj     = (const float*)d_in[6];
    const float* bias_table = (const float*)d_in[7];
    const float* g1         = (const float*)d_in[8];
    const float* be1        = (const float*)d_in[9];
    const float* g2         = (const float*)d_in[10];
    const float* be2        = (const float*)d_in[11];
    const float* w1         = (const float*)d_in[12];
    const float* b1         = (const float*)d_in[13];
    const float* w2         = (const float*)d_in[14];
    const float* b2         = (const float*)d_in[15];
    float* out = (float*)d_out;

    half *p_xw, *p_qkv, *p_att, *p_proj, *p_x2h, *p_h2, *p_ffn;
    half *p_wqkv, *p_wproj, *p_w1, *p_w2;
    cudaGetSymbolAddress((void**)&p_xw,   g_xw);
    cudaGetSymbolAddress((void**)&p_qkv,  g_qkv);
    cudaGetSymbolAddress((void**)&p_att,  g_att);
    cudaGetSymbolAddress((void**)&p_proj, g_proj);
    cudaGetSymbolAddress((void**)&p_x2h,  g_x2h);
    cudaGetSymbolAddress((void**)&p_h2,   g_h2);
    cudaGetSymbolAddress((void**)&p_ffn,  g_ffn);
    cudaGetSymbolAddress((void**)&p_wqkv,  g_wqkv);
    cudaGetSymbolAddress((void**)&p_wproj, g_wproj);
    cudaGetSymbolAddress((void**)&p_w1,    g_w1);
    cudaGetSymbolAddress((void**)&p_w2,    g_w2);

    cudaFuncSetAttribute(hmma_gemm<1>, cudaFuncAttributeMaxDynamicSharedMemorySize, GSMEM);
    cudaFuncSetAttribute(hmma_gemm<2>, cudaFuncAttributeMaxDynamicSharedMemorySize, GSMEM);
    cudaFuncSetAttribute(hmma_gemm<3>, cudaFuncAttributeMaxDynamicSharedMemorySize, GSMEM);

    // weight prep (tiled transpose to fp16)
    prep_w<<<dim3((3*CH)/32, CH/32), 256>>>(w_qkv, p_wqkv, CH, 3*CH);
    prep_w<<<dim3(CH/32,     CH/32), 256>>>(w_proj, p_wproj, CH, CH);
    prep_w<<<dim3(CFF/32,    CH/32), 256>>>(w1, p_w1, CH, CFF);
    prep_w<<<dim3(CH/32,    CFF/32), 256>>>(w2, p_w2, CFF, CH);

    // 1. LN1 + shift + window partition -> fp16
    ln1_window_kernel<<<NTOK, 128>>>(x, g1, be1, p_xw);

    // 2. QKV GEMM -> fp16 (bias only)
    hmma_gemm<3><<<dim3((3*CH)/128, NTOK/128), 128, GSMEM>>>(
        p_xw, p_wqkv, b_qkv, nullptr, nullptr, p_qkv, CH, 3*CH);

    // 3. windowed attention -> fp16
    attn_kernel<<<NWIN * NHEAD, 128>>>(p_qkv, bias_table, p_att);

    // 4. proj GEMM -> fp16
    hmma_gemm<3><<<dim3(CH/128, NTOK/128), 128, GSMEM>>>(
        p_att, p_wproj, b_proj, nullptr, nullptr, p_proj, CH, CH);

    // 5. window reverse + roll + residual + LN2 (x2 stored fp16)
    res_ln2_kernel<<<NTOK, 128>>>(x, p_proj, g2, be2, p_x2h, p_h2);

    // 6. FFN1 + fast GELU -> fp16
    hmma_gemm<1><<<dim3(CFF/128, NTOK/128), 128, GSMEM>>>(
        p_h2, p_w1, b1, nullptr, nullptr, p_ffn, CH, CFF);

    // 7. FFN2 + residual(fp16) -> fp32 out
    hmma_gemm<2><<<dim3(CH/128, NTOK/128), 128, GSMEM>>>(
        p_ffn, p_w2, b2, p_x2h, out, nullptr, CFF, CH);
}

// round 17
// speedup vs baseline: 1.2795x; 1.0093x over previous
#include <cuda_runtime.h>
#include <cuda_fp16.h>
#include <math.h>
#include <stdint.h>

// ---------------- problem constants ----------------
#define BATCH 16
#define HDIM  56
#define WDIM  56
#define CH    512
#define CFF   2048
#define NHEAD 16
#define DH    32
#define MWIN  7
#define NTOKW 49
#define SHIFT 3
#define NTOK  (BATCH*HDIM*WDIM)                  // 50176
#define NWIN  (BATCH*(HDIM/MWIN)*(WDIM/MWIN))    // 1024

// ---------------- device scratch (allocation-free) ----------------
__device__ half  g_xw  [(size_t)NTOK*CH];
__device__ half  g_qkv [(size_t)NTOK*3*CH];
__device__ half  g_att [(size_t)NTOK*CH];
__device__ half  g_proj[(size_t)NTOK*CH];
__device__ half  g_x2h [(size_t)NTOK*CH];
__device__ half  g_h2  [(size_t)NTOK*CH];
__device__ half  g_ffn [(size_t)NTOK*CFF];
// weights transposed to [N,K] fp16
__device__ half g_wqkv [(size_t)CH*3*CH];
__device__ half g_wproj[(size_t)CH*CH];
__device__ half g_w1   [(size_t)CH*CFF];
__device__ half g_w2   [(size_t)CFF*CH];

// ---------------- PTX helpers ----------------
__device__ __forceinline__ uint32_t smem_u32(const void* p){
    uint32_t a;
    asm("{ .reg .u64 t; cvta.to.shared.u64 t, %1; cvt.u32.u64 %0, t; }" : "=r"(a) : "l"(p));
    return a;
}
__device__ __forceinline__ uint32_t h2u(half2 h){ return *(uint32_t*)&h; }
#define CP_ASYNC16(dst, src) \
    asm volatile("cp.async.cg.shared.global [%0], [%1], 16;" :: "r"(dst), "l"(src))
#define CP_COMMIT() asm volatile("cp.async.commit_group;" ::: "memory")
#define CP_WAIT(N)  asm volatile("cp.async.wait_group %0;" :: "n"(N) : "memory")

#define LDSM_X4(r, a) \
    asm volatile("ldmatrix.sync.aligned.m8n8.x4.shared.b16 {%0,%1,%2,%3}, [%4];" \
        : "=r"((r)[0]), "=r"((r)[1]), "=r"((r)[2]), "=r"((r)[3]) : "r"(a))

#define MMA_F16(d, a, b0, b1) \
    asm volatile("mma.sync.aligned.m16n8k16.row.col.f32.f16.f16.f32 " \
        "{%0,%1,%2,%3}, {%4,%5,%6,%7}, {%8,%9}, {%0,%1,%2,%3};" \
        : "+f"((d)[0]), "+f"((d)[1]), "+f"((d)[2]), "+f"((d)[3]) \
        : "r"((a)[0]), "r"((a)[1]), "r"((a)[2]), "r"((a)[3]), "r"(b0), "r"(b1))

// fast GELU: tanh form with HW tanh.approx (MUFU)
__device__ __forceinline__ float gelu_fast(float x){
    float u = 0.7978845608028654f * fmaf(0.044715f * x, x * x, x);
    float t;
    asm("tanh.approx.f32 %0, %1;" : "=f"(t) : "f"(u));
    return 0.5f * x * (1.0f + t);
}

// ---------------- fp16 HMMA GEMM: 4 warps x 64x64 tiles, 3-stage ring ----------------
#define TILEB  10240
#define STAGEB 20480
#define GSMEM  (3*STAGEB)
#define EPIROW 272

template<int EPI>
__global__ __launch_bounds__(128, 3) void hmma_gemm(
    const half* __restrict__ Ag, const half* __restrict__ Bg,
    const float* __restrict__ bias, const half* __restrict__ res,
    float* __restrict__ Cf, half* __restrict__ Ch,
    int K, int Nc)
{
    extern __shared__ char smem[];
    const int tid = threadIdx.x;
    const int lane = tid & 31, wid = tid >> 5;
    const int wm = wid & 1, wn = wid >> 1;

    const half* Ab = Ag + (size_t)blockIdx.y * 128 * K;
    const half* Bb = Bg + (size_t)blockIdx.x * 128 * K;

    const uint32_t sb = smem_u32(smem);
    const int NK = K >> 5;

    float acc[4][8][4];
    #pragma unroll
    for (int a = 0; a < 4; a++)
        #pragma unroll
        for (int b = 0; b < 8; b++)
            #pragma unroll
            for (int c = 0; c < 4; c++) acc[a][b][c] = 0.f;

    const int lr0 = tid >> 2;
    const int lc  = tid & 3;
    auto load_stage = [&](int kb, int s) {
        uint32_t st = sb + (uint32_t)s * STAGEB;
        #pragma unroll
        for (int i = 0; i < 8; i++) {
            const int t = i >> 2;
            int r = (i & 3) * 32 + lr0;
            const half* src = (t ? Bb : Ab) + (size_t)r * K + kb * 32 + lc * 8;
            uint32_t dst = st + (uint32_t)(t * TILEB + r * 80 + lc * 16);
            CP_ASYNC16(dst, src);
        }
        CP_COMMIT();
    };

    auto compute_stage = [&](int s) {
        uint32_t st = sb + (uint32_t)s * STAGEB;
        #pragma unroll
        for (int kk = 0; kk < 2; kk++) {
            const int ch = kk * 2 + (lane >> 4);
            uint32_t bh[4][4];
            #pragma unroll
            for (int np = 0; np < 4; np++) {
                int row = wn * 64 + np * 16 + (lane & 15);
                uint32_t off = (uint32_t)(row * 80 + ch * 16);
                LDSM_X4(bh[np], st + 1u * TILEB + off);
            }
            #pragma unroll
            for (int mt = 0; mt < 4; mt++) {
                int row = wm * 64 + mt * 16 + (lane & 15);
                uint32_t off = (uint32_t)(row * 80 + ch * 16);
                uint32_t ah[4];
                LDSM_X4(ah, st + off);
                #pragma unroll
                for (int nt = 0; nt < 8; nt++) {
                    int np = nt >> 1, se = nt & 1;
                    MMA_F16(acc[mt][nt], ah, bh[np][se], bh[np][se + 2]);
                }
            }
        }
    };

    load_stage(0, 0);
    if (NK > 1) load_stage(1, 1);

    int s_cur = 0, s_next = 2;
    for (int kb = 0; kb < NK; kb++) {
        if (kb + 1 < NK) { CP_WAIT(1); }
        else             { CP_WAIT(0); }
        __syncthreads();
        if (kb + 2 < NK) {
            load_stage(kb + 2, s_next);
            s_next = s_next == 2 ? 0 : s_next + 1;
        }
        compute_stage(s_cur);
        s_cur = s_cur == 2 ? 0 : s_cur + 1;
    }

    if (EPI == 1 || EPI == 3) {
        __syncthreads();
        #pragma unroll
        for (int mt = 0; mt < 4; mt++) {
            #pragma unroll
            for (int nt = 0; nt < 8; nt++) {
                int cl = wn * 64 + nt * 8 + (lane & 3) * 2;
                float b0 = bias[blockIdx.x * 128 + cl];
                float b1 = bias[blockIdx.x * 128 + cl + 1];
                #pragma unroll
                for (int h = 0; h < 2; h++) {
                    int rl = wm * 64 + mt * 16 + (lane >> 2) + h * 8;
                    float v0 = acc[mt][nt][h * 2]     + b0;
                    float v1 = acc[mt][nt][h * 2 + 1] + b1;
                    if (EPI == 1) { v0 = gelu_fast(v0); v1 = gelu_fast(v1); }
                    *(half2*)(smem + rl * EPIROW + cl * 2) = __floats2half2_rn(v0, v1);
                }
            }
        }
        __syncthreads();
        size_t gbase = (size_t)blockIdx.y * 128 * Nc + blockIdx.x * 128;
        #pragma unroll
        for (int it = 0; it < 16; it++) {
            int idx = it * 128 + tid;
            int row = idx >> 4, c16 = idx & 15;
            uint4 v = *(uint4*)(smem + row * EPIROW + c16 * 16);
            *(uint4*)(Ch + gbase + (size_t)row * Nc + c16 * 8) = v;
        }
    } else {
        int row0 = blockIdx.y * 128 + wm * 64;
        int col0 = blockIdx.x * 128 + wn * 64;
        #pragma unroll
        for (int mt = 0; mt < 4; mt++) {
            #pragma unroll
            for (int nt = 0; nt < 8; nt++) {
                int c = col0 + nt * 8 + (lane & 3) * 2;
                float b0 = bias[c], b1 = bias[c + 1];
                #pragma unroll
                for (int h = 0; h < 2; h++) {
                    int r = row0 + mt * 16 + (lane >> 2) + h * 8;
                    float v0 = acc[mt][nt][h * 2]     + b0;
                    float v1 = acc[mt][nt][h * 2 + 1] + b1;
                    size_t o = (size_t)r * Nc + c;
                    if (EPI == 2) {
                        float2 rv = __half22float2(*(const half2*)(res + o));
                        v0 += rv.x; v1 += rv.y;
                    }
                    *(float2*)(Cf + o) = make_float2(v0, v1);
                }
            }
        }
    }
}

// ---------------- weight prep: [K,N] fp32 -> [N,K] fp16 (tiled transpose) ----------------
__global__ __launch_bounds__(256) void prep_w(
    const float* __restrict__ W, half* __restrict__ Wh, int K, int N)
{
    __shared__ float tile[32][33];
    int nb = blockIdx.x * 32, kb = blockIdx.y * 32;
    int tx = threadIdx.x & 31, ty = threadIdx.x >> 5;
    #pragma unroll
    for (int j = 0; j < 32; j += 8)
        tile[ty + j][tx] = W[(size_t)(kb + ty + j) * N + nb + tx];
    __syncthreads();
    #pragma unroll
    for (int j = 0; j < 32; j += 8)
        Wh[(size_t)(nb + ty + j) * K + kb + tx] = __float2half_rn(tile[tx][ty + j]);
}

// ---------------- LN1 + shift + window partition: warp-per-token ----------------
// 256 threads = 8 warps = 8 tokens/block; shfl-only reduction, no barriers.
__global__ __launch_bounds__(256) void ln1_window_kernel(
    const float* __restrict__ x, const float* __restrict__ g, const float* __restrict__ b,
    half* __restrict__ out)
{
    int lane = threadIdx.x & 31;
    int t = blockIdx.x * 8 + (threadIdx.x >> 5);
    int w = t / NTOKW, tok = t - w * NTOKW;
    int bb = w >> 6, wrem = w & 63;
    int wi = wrem >> 3, wj = wrem & 7;
    int ti = tok / MWIN, tj = tok - ti * MWIN;
    int r = (wi * MWIN + ti + SHIFT) % HDIM;
    int c = (wj * MWIN + tj + SHIFT) % WDIM;
    const float4* src = (const float4*)(x + ((size_t)bb * (HDIM * WDIM) + r * WDIM + c) * CH);
    float4 v[4];
    float s = 0.f, sq = 0.f;
    #pragma unroll
    for (int i = 0; i < 4; i++) {
        v[i] = src[lane + 32 * i];
        s  += v[i].x + v[i].y + v[i].z + v[i].w;
        sq += v[i].x*v[i].x + v[i].y*v[i].y + v[i].z*v[i].z + v[i].w*v[i].w;
    }
    #pragma unroll
    for (int o = 16; o > 0; o >>= 1) {
        s  += __shfl_xor_sync(0xffffffffu, s,  o);
        sq += __shfl_xor_sync(0xffffffffu, sq, o);
    }
    float mu  = s * (1.0f / CH);
    float var = sq * (1.0f / CH) - mu * mu;
    float inv = rsqrtf(var + 1e-5f);
    half* dst = out + (size_t)t * CH;
    #pragma unroll
    for (int i = 0; i < 4; i++) {
        int idx = lane + 32 * i;
        float4 gg = ((const float4*)g)[idx];
        float4 bb4 = ((const float4*)b)[idx];
        half2 h01 = __floats2half2_rn((v[i].x - mu) * inv * gg.x + bb4.x,
                                      (v[i].y - mu) * inv * gg.y + bb4.y);
        half2 h23 = __floats2half2_rn((v[i].z - mu) * inv * gg.z + bb4.z,
                                      (v[i].w - mu) * inv * gg.w + bb4.w);
        *(uint2*)(dst + idx * 4) = make_uint2(h2u(h01), h2u(h23));
    }
}

// ---------------- windowed attention: register-tiled, fp16 half2 smem ----------------
__global__ __launch_bounds__(128) void attn_kernel(
    const half* __restrict__ qkv, const float* __restrict__ bias_table,
    half* __restrict__ out)
{
    int win  = blockIdx.x >> 4;
    int head = blockIdx.x & 15;
    __shared__ half2 qh[52][17], kh[52][17], vh[52][17];
    __shared__ float sc[52][57];
    __shared__ float sbias[(2*MWIN-1)*(2*MWIN-1)];
    int tid = threadIdx.x;
    const float scale = 0.17677669529663687f;
    size_t base = (size_t)win * NTOKW * (3 * CH) + head * DH;

    for (int i = tid; i < (2*MWIN-1)*(2*MWIN-1); i += 128)
        sbias[i] = bias_table[i * NHEAD + head];

    for (int i = tid; i < NTOKW * 16; i += 128) {
        int n = i >> 4, c = i & 15;
        size_t rb = base + (size_t)n * (3 * CH) + c * 2;
        qh[n][c] = *(const half2*)(qkv + rb);
        kh[n][c] = *(const half2*)(qkv + rb + CH);
        vh[n][c] = *(const half2*)(qkv + rb + 2 * CH);
    }
    __syncthreads();

    if (tid < 91) {
        int tr = tid / 7, tc = tid - tr * 7;
        int n0 = tr * 4, m0 = tc * 7;
        float acc[4][7];
        #pragma unroll
        for (int i = 0; i < 4; i++)
            #pragma unroll
            for (int j = 0; j < 7; j++) acc[i][j] = 0.f;
        #pragma unroll 4
        for (int dp = 0; dp < 16; dp++) {
            float2 qr[4], kr[7];
            #pragma unroll
            for (int i = 0; i < 4; i++) qr[i] = __half22float2(qh[n0 + i][dp]);
            #pragma unroll
            for (int j = 0; j < 7; j++) kr[j] = __half22float2(kh[m0 + j][dp]);
            #pragma unroll
            for (int i = 0; i < 4; i++)
                #pragma unroll
                for (int j = 0; j < 7; j++) {
                    acc[i][j] = fmaf(qr[i].x, kr[j].x, acc[i][j]);
                    acc[i][j] = fmaf(qr[i].y, kr[j].y, acc[i][j]);
                }
        }
        #pragma unroll
        for (int i = 0; i < 4; i++) {
            int n = n0 + i;
            int nn = n < NTOKW ? n : NTOKW - 1;
            int nr = nn / MWIN, ncm = nn - nr * MWIN;
            #pragma unroll
            for (int j = 0; j < 7; j++) {
                int m = m0 + j;
                int mr = m / MWIN, mc = m - mr * MWIN;
                int dr = nr - mr + (MWIN - 1), dc = ncm - mc + (MWIN - 1);
                sc[n][m] = acc[i][j] * scale + sbias[dr * (2 * MWIN - 1) + dc];
            }
        }
    }
    __syncthreads();

    if (tid < NTOKW) {
        float* row = sc[tid];
        float mx = -1e30f;
        #pragma unroll 7
        for (int m = 0; m < NTOKW; m++) mx = fmaxf(mx, row[m]);
        float sum = 0.f;
        #pragma unroll 7
        for (int m = 0; m < NTOKW; m++) { float e = __expf(row[m] - mx); row[m] = e; sum += e; }
        float inv = 1.0f / sum;
        #pragma unroll 7
        for (int m = 0; m < NTOKW; m++) row[m] *= inv;
    }
    __syncthreads();

    if (tid < 104) {
        int tr = tid >> 3, dc = tid & 7;
        int n0 = tr * 4, d0 = dc * 2;
        float acc[4][4];
        #pragma unroll
        for (int i = 0; i < 4; i++)
            #pragma unroll
            for (int k = 0; k < 4; k++) acc[i][k] = 0.f;
        #pragma unroll 7
        for (int m = 0; m < NTOKW; m++) {
            float2 v0 = __half22float2(vh[m][d0]);
            float2 v1 = __half22float2(vh[m][d0 + 1]);
            float pp[4];
            #pragma unroll
            for (int i = 0; i < 4; i++) pp[i] = sc[n0 + i][m];
            #pragma unroll
            for (int i = 0; i < 4; i++) {
                acc[i][0] = fmaf(pp[i], v0.x, acc[i][0]);
                acc[i][1] = fmaf(pp[i], v0.y, acc[i][1]);
                acc[i][2] = fmaf(pp[i], v1.x, acc[i][2]);
                acc[i][3] = fmaf(pp[i], v1.y, acc[i][3]);
            }
        }
        #pragma unroll
        for (int i = 0; i < 4; i++) {
            int n = n0 + i;
            if (n < NTOKW) {
                size_t o = ((size_t)win * NTOKW + n) * CH + head * DH + d0 * 2;
                *(half2*)(out + o)     = __floats2half2_rn(acc[i][0], acc[i][1]);
                *(half2*)(out + o + 2) = __floats2half2_rn(acc[i][2], acc[i][3]);
            }
        }
    }
}

// ---------------- window reverse + roll + residual + LN2: warp-per-token ----------------
__global__ __launch_bounds__(256) void res_ln2_kernel(
    const float* __restrict__ x, const half* __restrict__ proj,
    const float* __restrict__ g, const float* __restrict__ b,
    half* __restrict__ x2, half* __restrict__ h2)
{
    int lane = threadIdx.x & 31;
    int t = blockIdx.x * 8 + (threadIdx.x >> 5);
    int bb = t / (HDIM * WDIM);
    int rc = t - bb * (HDIM * WDIM);
    int r = rc / WDIM, c = rc - r * WDIM;
    int rs = (r - SHIFT + HDIM) % HDIM;
    int cs = (c - SHIFT + WDIM) % WDIM;
    int w   = bb * 64 + (rs / MWIN) * 8 + (cs / MWIN);
    int tok = (rs % MWIN) * MWIN + (cs % MWIN);
    const half* ps = proj + ((size_t)w * NTOKW + tok) * CH;
    const float4* xs = (const float4*)(x + (size_t)t * CH);
    float4 v[4];
    float s = 0.f, sq = 0.f;
    half* x2p = x2 + (size_t)t * CH;
    #pragma unroll
    for (int i = 0; i < 4; i++) {
        int idx = lane + 32 * i;
        float4 xv = xs[idx];
        uint2 pr = *(const uint2*)(ps + idx * 4);
        float2 p01 = __half22float2(*(half2*)&pr.x);
        float2 p23 = __half22float2(*(half2*)&pr.y);
        v[i].x = xv.x + p01.x; v[i].y = xv.y + p01.y;
        v[i].z = xv.z + p23.x; v[i].w = xv.w + p23.y;
        *(uint2*)(x2p + idx * 4) = make_uint2(
            h2u(__floats2half2_rn(v[i].x, v[i].y)),
            h2u(__floats2half2_rn(v[i].z, v[i].w)));
        s  += v[i].x + v[i].y + v[i].z + v[i].w;
        sq += v[i].x*v[i].x + v[i].y*v[i].y + v[i].z*v[i].z + v[i].w*v[i].w;
    }
    #pragma unroll
    for (int o = 16; o > 0; o >>= 1) {
        s  += __shfl_xor_sync(0xffffffffu, s,  o);
        sq += __shfl_xor_sync(0xffffffffu, sq, o);
    }
    float mu  = s * (1.0f / CH);
    float var = sq * (1.0f / CH) - mu * mu;
    float inv = rsqrtf(var + 1e-5f);
    half* h2p = h2 + (size_t)t * CH;
    #pragma unroll
    for (int i = 0; i < 4; i++) {
        int idx = lane + 32 * i;
        float4 gg = ((const float4*)g)[idx];
        float4 bb4 = ((const float4*)b)[idx];
        *(uint2*)(h2p + idx * 4) = make_uint2(
            h2u(__floats2half2_rn((v[i].x - mu) * inv * gg.x + bb4.x,
                                  (v[i].y - mu) * inv * gg.y + bb4.y)),
            h2u(__floats2half2_rn((v[i].z - mu) * inv * gg.z + bb4.z,
                                  (v[i].w - mu) * inv * gg.w + bb4.w)));
    }
}

// ---------------- launcher ----------------
extern "C" void kernel_launch(void* const* d_in, const int* in_sizes, int n_in,
                              void* d_out, int out_size)
{
    const float* x          = (const float*)d_in[0];
    const float* w_qkv      = (const float*)d_in[3];
    const float* b_qkv      = (const float*)d_in[4];
    const float* w_proj     = (const float*)d_in[5];
    const float* b_proj     = (const float*)d_in[6];
    const float* bias_table = (const float*)d_in[7];
    const float* g1         = (const float*)d_in[8];
    const float* be1        = (const float*)d_in[9];
    const float* g2         = (const float*)d_in[10];
    const float* be2        = (const float*)d_in[11];
    const float* w1         = (const float*)d_in[12];
    const float* b1         = (const float*)d_in[13];
    const float* w2         = (const float*)d_in[14];
    const float* b2         = (const float*)d_in[15];
    float* out = (float*)d_out;

    half *p_xw, *p_qkv, *p_att, *p_proj, *p_x2h, *p_h2, *p_ffn;
    half *p_wqkv, *p_wproj, *p_w1, *p_w2;
    cudaGetSymbolAddress((void**)&p_xw,   g_xw);
    cudaGetSymbolAddress((void**)&p_qkv,  g_qkv);
    cudaGetSymbolAddress((void**)&p_att,  g_att);
    cudaGetSymbolAddress((void**)&p_proj, g_proj);
    cudaGetSymbolAddress((void**)&p_x2h,  g_x2h);
    cudaGetSymbolAddress((void**)&p_h2,   g_h2);
    cudaGetSymbolAddress((void**)&p_ffn,  g_ffn);
    cudaGetSymbolAddress((void**)&p_wqkv,  g_wqkv);
    cudaGetSymbolAddress((void**)&p_wproj, g_wproj);
    cudaGetSymbolAddress((void**)&p_w1,    g_w1);
    cudaGetSymbolAddress((void**)&p_w2,    g_w2);

    cudaFuncSetAttribute(hmma_gemm<1>, cudaFuncAttributeMaxDynamicSharedMemorySize, GSMEM);
    cudaFuncSetAttribute(hmma_gemm<2>, cudaFuncAttributeMaxDynamicSharedMemorySize, GSMEM);
    cudaFuncSetAttribute(hmma_gemm<3>, cudaFuncAttributeMaxDynamicSharedMemorySize, GSMEM);

    // weight prep (tiled transpose to fp16)
    prep_w<<<dim3((3*CH)/32, CH/32), 256>>>(w_qkv, p_wqkv, CH, 3*CH);
    prep_w<<<dim3(CH/32,     CH/32), 256>>>(w_proj, p_wproj, CH, CH);
    prep_w<<<dim3(CFF/32,    CH/32), 256>>>(w1, p_w1, CH, CFF);
    prep_w<<<dim3(CH/32,    CFF/32), 256>>>(w2, p_w2, CFF, CH);

    // 1. LN1 + shift + window partition -> fp16 (warp-per-token)
    ln1_window_kernel<<<NTOK/8, 256>>>(x, g1, be1, p_xw);

    // 2. QKV GEMM -> fp16 (bias only)
    hmma_gemm<3><<<dim3((3*CH)/128, NTOK/128), 128, GSMEM>>>(
        p_xw, p_wqkv, b_qkv, nullptr, nullptr, p_qkv, CH, 3*CH);

    // 3. windowed attention -> fp16
    attn_kernel<<<NWIN * NHEAD, 128>>>(p_qkv, bias_table, p_att);

    // 4. proj GEMM -> fp16
    hmma_gemm<3><<<dim3(CH/128, NTOK/128), 128, GSMEM>>>(
        p_att, p_wproj, b_proj, nullptr, nullptr, p_proj, CH, CH);

    // 5. window reverse + roll + residual + LN2 (warp-per-token)
    res_ln2_kernel<<<NTOK/8, 256>>>(x, p_proj, g2, be2, p_x2h, p_h2);

    // 6. FFN1 + fast GELU -> fp16
    hmma_gemm<1><<<dim3(CFF/128, NTOK/128), 128, GSMEM>>>(
        p_h2, p_w1, b1, nullptr, nullptr, p_ffn, CH, CFF);

    // 7. FFN2 + residual(fp16) -> fp32 out
    hmma_gemm<2><<<dim3(CH/128, NTOK/128), 128, GSMEM>>>(
        p_ffn, p_w2, b2, p_x2h, out, nullptr, CFF, CH);
}